// round 9
// baseline (speedup 1.0000x reference)
#include <cuda_runtime.h>
#include <cuda_bf16.h>
#include <math.h>
#include <stdint.h>

// ---------------------------------------------------------------------------
// Shapes: x (T=4096, B=2, E=1024); H=16 heads, dk=dv=64; window 512 (513 rel pos)
// QKV rows = t*B + b (8192), cols = h*192 + c  (c<64 q, 64..127 k, 128..191 v)
// QE layout: [r = (t*2+b)*16+h][j], row stride 640 (cols 513..639 are pad)
// ---------------------------------------------------------------------------
#define NROWS 8192
#define EMB   1024
#define QKV_N 3072
#define FFN_I 4096
#define NJ    513
#define NJP   640

// fp32 scratch offsets (floats)
#define OFF_OUT1   16777216ull
#define OFF_QKV    33554432ull
#define OFF_QE     92274688ull   // 131072*640 = 83886080 -> ends 176160768
#define SCRATCH_FLOATS 176160768ull

__device__ float g_scratch[SCRATCH_FLOATS];

// split-bf16 buffers
__device__ __nv_bfloat16 g_act_hi[8388608];
__device__ __nv_bfloat16 g_act_lo[8388608];
__device__ __nv_bfloat16 g_act2_hi[33554432];   // fc1 out; reused as Qsplit earlier
__device__ __nv_bfloat16 g_act2_lo[33554432];
__device__ __nv_bfloat16 g_w_hi[4194304];
__device__ __nv_bfloat16 g_w_lo[4194304];
__device__ __nv_bfloat16 g_pet_hi[40960];       // pe^T padded [640][64]
__device__ __nv_bfloat16 g_pet_lo[40960];

__device__ __forceinline__ uint32_t smem_u32(const void* p) {
    uint32_t a;
    asm("{ .reg .u64 t; cvta.to.shared.u64 t, %1; cvt.u32.u64 %0, t; }" : "=r"(a) : "l"(p));
    return a;
}

__device__ __forceinline__ void split1(float v, __nv_bfloat16& h, __nv_bfloat16& l) {
    h = __float2bfloat16(v);
    l = __float2bfloat16(v - __bfloat162float(h));
}

// ---------------------------------------------------------------------------
// split fp32 -> (hi, lo) bf16   (weights)
// ---------------------------------------------------------------------------
__global__ __launch_bounds__(256) void split_kernel(
    const float* __restrict__ X, __nv_bfloat16* __restrict__ Hi,
    __nv_bfloat16* __restrict__ Lo)
{
    int i4 = blockIdx.x * 256 + threadIdx.x;
    float4 v = ((const float4*)X)[i4];
    __nv_bfloat162 hi0, hi1, lo0, lo1;
    split1(v.x, hi0.x, lo0.x);
    split1(v.y, hi0.y, lo0.y);
    split1(v.z, hi1.x, lo1.x);
    split1(v.w, hi1.y, lo1.y);
    ((__nv_bfloat162*)Hi)[i4 * 2]     = hi0;
    ((__nv_bfloat162*)Hi)[i4 * 2 + 1] = hi1;
    ((__nv_bfloat162*)Lo)[i4 * 2]     = lo0;
    ((__nv_bfloat162*)Lo)[i4 * 2 + 1] = lo1;
}

// ---------------------------------------------------------------------------
// pe^T split: out[j][k] = split(pe[k*513 + j]), j<513 else 0.  640*64 elems.
// ---------------------------------------------------------------------------
__global__ __launch_bounds__(256) void pe_split_t_kernel(
    const float* __restrict__ pe, __nv_bfloat16* __restrict__ Hi,
    __nv_bfloat16* __restrict__ Lo)
{
    int idx = blockIdx.x * 256 + threadIdx.x;   // 40960
    int k = idx & 63;
    int j = idx >> 6;
    float v = (j < NJ) ? pe[(size_t)k * NJ + j] : 0.f;
    __nv_bfloat16 h, l;
    split1(v, h, l);
    Hi[idx] = h;
    Lo[idx] = l;
}

// ---------------------------------------------------------------------------
// LayerNorm fused with split
// ---------------------------------------------------------------------------
__global__ __launch_bounds__(256) void ln_split_kernel(
    const float* __restrict__ X, const float* __restrict__ G,
    const float* __restrict__ Bt, __nv_bfloat16* __restrict__ Hi,
    __nv_bfloat16* __restrict__ Lo)
{
    __shared__ float ssum[8], ssq[8], smv[2];
    int row = blockIdx.x;
    int tid = threadIdx.x;
    const float4* xr = (const float4*)(X + (size_t)row * EMB);
    float4 v = xr[tid];
    float s = v.x + v.y + v.z + v.w;
    float q = v.x*v.x + v.y*v.y + v.z*v.z + v.w*v.w;
#pragma unroll
    for (int o = 16; o > 0; o >>= 1) {
        s += __shfl_xor_sync(0xffffffffu, s, o);
        q += __shfl_xor_sync(0xffffffffu, q, o);
    }
    if ((tid & 31) == 0) { ssum[tid >> 5] = s; ssq[tid >> 5] = q; }
    __syncthreads();
    if (tid == 0) {
        float S = 0.f, Q = 0.f;
#pragma unroll
        for (int i = 0; i < 8; i++) { S += ssum[i]; Q += ssq[i]; }
        float mean = S * (1.f / EMB);
        float var  = Q * (1.f / EMB) - mean * mean;
        smv[0] = mean;
        smv[1] = rsqrtf(var + 1e-5f);
    }
    __syncthreads();
    float mean = smv[0], inv = smv[1];
    float4 g = ((const float4*)G)[tid];
    float4 b = ((const float4*)Bt)[tid];
    float o0 = (v.x - mean) * inv * g.x + b.x;
    float o1 = (v.y - mean) * inv * g.y + b.y;
    float o2 = (v.z - mean) * inv * g.z + b.z;
    float o3 = (v.w - mean) * inv * g.w + b.w;
    __nv_bfloat162 hi0, hi1, lo0, lo1;
    split1(o0, hi0.x, lo0.x);
    split1(o1, hi0.y, lo0.y);
    split1(o2, hi1.x, lo1.x);
    split1(o3, hi1.y, lo1.y);
    size_t i4 = (size_t)row * 256 + tid;
    ((__nv_bfloat162*)Hi)[i4 * 2]     = hi0;
    ((__nv_bfloat162*)Hi)[i4 * 2 + 1] = hi1;
    ((__nv_bfloat162*)Lo)[i4 * 2]     = lo0;
    ((__nv_bfloat162*)Lo)[i4 * 2 + 1] = lo1;
}

// ---------------------------------------------------------------------------
// mma.sync bf16 split GEMM NT: C = (Ah+Al)(Bh+Bl)^T (+bias)(relu)(+Res)
// CTA 128x128, BK=32, 8 warps, cp.async 3-stage pipeline, ONE barrier/iter.
// SPLITO: write (hi,lo) bf16 instead of fp32.
// QOUT: also write q-columns (c%192<64) as split bf16 [row*16+h][64] (QKV only)
// ---------------------------------------------------------------------------
#define STAGE_BYTES 32768
#define MMA_SMEM    98304

__device__ __forceinline__ void cp16(uint32_t dst, const void* src) {
    asm volatile("cp.async.cg.shared.global [%0], [%1], 16;" :: "r"(dst), "l"(src));
}
__device__ __forceinline__ void ldm4(uint32_t* r, uint32_t addr) {
    asm volatile("ldmatrix.sync.aligned.m8n8.x4.shared.b16 {%0,%1,%2,%3}, [%4];"
                 : "=r"(r[0]), "=r"(r[1]), "=r"(r[2]), "=r"(r[3]) : "r"(addr));
}
__device__ __forceinline__ void mma16816(float* c, const uint32_t* a,
                                         uint32_t b0, uint32_t b1) {
    asm volatile(
        "mma.sync.aligned.m16n8k16.row.col.f32.bf16.bf16.f32 "
        "{%0,%1,%2,%3}, {%4,%5,%6,%7}, {%8,%9}, {%0,%1,%2,%3};"
        : "+f"(c[0]), "+f"(c[1]), "+f"(c[2]), "+f"(c[3])
        : "r"(a[0]), "r"(a[1]), "r"(a[2]), "r"(a[3]), "r"(b0), "r"(b1));
}

template<bool BIAS, bool RELU, bool RES, bool SPLITO, bool QOUT>
__global__ __launch_bounds__(256, 2) void mma_gemm(
    const __nv_bfloat16* __restrict__ Ah, const __nv_bfloat16* __restrict__ Al,
    const __nv_bfloat16* __restrict__ Bh, const __nv_bfloat16* __restrict__ Bl,
    const float* __restrict__ bias, const float* __restrict__ Res,
    float* __restrict__ C, __nv_bfloat16* __restrict__ OHi,
    __nv_bfloat16* __restrict__ OLo, int M, int N, int K)
{
    extern __shared__ char smem[];
    const uint32_t sbase = smem_u32(smem);
    const int tid = threadIdx.x;
    const int wid = tid >> 5, lane = tid & 31;
    const int bm = blockIdx.y * 128, bn = blockIdx.x * 128;
    const int m0w = (wid >> 2) * 64, n0w = (wid & 3) * 32;

    const int r0 = tid >> 2,         c0 = tid & 3;
    const int r1 = (tid + 256) >> 2, c1 = (tid + 256) & 3;
    const uint32_t so0 = (uint32_t)(r0 * 64 + ((c0 ^ ((r0 >> 1) & 3)) * 16));
    const uint32_t so1 = (uint32_t)(r1 * 64 + ((c1 ^ ((r1 >> 1) & 3)) * 16));
    const size_t offA0 = (size_t)(bm + r0) * K + c0 * 8;
    const size_t offA1 = (size_t)(bm + r1) * K + c1 * 8;
    const size_t offB0 = (size_t)(bn + r0) * K + c0 * 8;
    const size_t offB1 = (size_t)(bn + r1) * K + c1 * 8;

    float acc[4][4][4];
#pragma unroll
    for (int a = 0; a < 4; a++)
#pragma unroll
        for (int n = 0; n < 4; n++)
#pragma unroll
            for (int q = 0; q < 4; q++) acc[a][n][q] = 0.f;

    const int nt = K >> 5;
    const int rowA_base = m0w + (lane & 15);
    const int rowB_base = n0w + (lane & 15);
    const int chsel = lane >> 4;

#define LOAD_STAGE(s, k0)                                                     \
    do {                                                                      \
        uint32_t d = sbase + (s) * STAGE_BYTES;                               \
        cp16(d + so0,          Ah + offA0 + (k0));                            \
        cp16(d + so1,          Ah + offA1 + (k0));                            \
        cp16(d + 8192  + so0,  Al + offA0 + (k0));                            \
        cp16(d + 8192  + so1,  Al + offA1 + (k0));                            \
        cp16(d + 16384 + so0,  Bh + offB0 + (k0));                            \
        cp16(d + 16384 + so1,  Bh + offB1 + (k0));                            \
        cp16(d + 24576 + so0,  Bl + offB0 + (k0));                            \
        cp16(d + 24576 + so1,  Bl + offB1 + (k0));                            \
    } while (0)

    // 3-stage pipeline: preload 0,1
    LOAD_STAGE(0, 0);
    asm volatile("cp.async.commit_group;");
    if (nt > 1) LOAD_STAGE(1, 32);
    asm volatile("cp.async.commit_group;");

    int stage = 0;
    for (int i = 0; i < nt; i++) {
        asm volatile("cp.async.wait_group 1;");
        __syncthreads();   // stage i ready; stage (i+2)%3 (= i-1's buffer) free
        int nx = i + 2;
        if (nx < nt) {
            int ns = stage + 2; if (ns >= 3) ns -= 3;
            LOAD_STAGE(ns, nx << 5);
        }
        asm volatile("cp.async.commit_group;");

        uint32_t base = sbase + stage * STAGE_BYTES;
#pragma unroll
        for (int ks = 0; ks < 2; ks++) {
            const int chunk = ks * 2 + chsel;
            uint32_t bh[2][4], bl[2][4];
#pragma unroll
            for (int p = 0; p < 2; p++) {
                int row = rowB_base + p * 16;
                uint32_t ad = base + 16384 + (uint32_t)(row * 64 + ((chunk ^ ((row >> 1) & 3)) * 16));
                ldm4(bh[p], ad);
                ldm4(bl[p], ad + 8192);
            }
#pragma unroll
            for (int a = 0; a < 4; a++) {
                uint32_t ah[4], al[4];
                int row = rowA_base + a * 16;
                uint32_t ad = base + (uint32_t)(row * 64 + ((chunk ^ ((row >> 1) & 3)) * 16));
                ldm4(ah, ad);
                ldm4(al, ad + 8192);
#pragma unroll
                for (int n = 0; n < 4; n++) {
                    int p = n >> 1, q = n & 1;
                    mma16816(acc[a][n], ah, bh[p][q], bh[p][q + 2]);
                    mma16816(acc[a][n], ah, bl[p][q], bl[p][q + 2]);
                    mma16816(acc[a][n], al, bh[p][q], bh[p][q + 2]);
                }
            }
        }
        if (++stage == 3) stage = 0;
    }
#undef LOAD_STAGE

    const int g = lane >> 2, t = lane & 3;
#pragma unroll
    for (int a = 0; a < 4; a++) {
#pragma unroll
        for (int n = 0; n < 4; n++) {
            int row0 = bm + m0w + a * 16 + g;
            int col  = bn + n0w + n * 8 + 2 * t;
            float v0 = acc[a][n][0], v1 = acc[a][n][1];
            float v2 = acc[a][n][2], v3 = acc[a][n][3];
            if (BIAS) {
                float b0 = bias[col], b1 = bias[col + 1];
                v0 += b0; v1 += b1; v2 += b0; v3 += b1;
            }
            if (RELU) {
                v0 = fmaxf(v0, 0.f); v1 = fmaxf(v1, 0.f);
                v2 = fmaxf(v2, 0.f); v3 = fmaxf(v3, 0.f);
            }
            if (RES) {
                const float2 q0 = *(const float2*)(Res + (size_t)row0 * N + col);
                const float2 q1 = *(const float2*)(Res + (size_t)(row0 + 8) * N + col);
                v0 += q0.x; v1 += q0.y; v2 += q1.x; v3 += q1.y;
            }
            if (SPLITO) {
                __nv_bfloat162 h0, h1, l0, l1;
                split1(v0, h0.x, l0.x); split1(v1, h0.y, l0.y);
                split1(v2, h1.x, l1.x); split1(v3, h1.y, l1.y);
                *(__nv_bfloat162*)(OHi + (size_t)row0 * N + col)       = h0;
                *(__nv_bfloat162*)(OLo + (size_t)row0 * N + col)       = l0;
                *(__nv_bfloat162*)(OHi + (size_t)(row0 + 8) * N + col) = h1;
                *(__nv_bfloat162*)(OLo + (size_t)(row0 + 8) * N + col) = l1;
            } else {
                float2 o0; o0.x = v0; o0.y = v1;
                float2 o1; o1.x = v2; o1.y = v3;
                *(float2*)(C + (size_t)row0 * N + col)       = o0;
                *(float2*)(C + (size_t)(row0 + 8) * N + col) = o1;
            }
            if (QOUT) {
                int hh = col / 192;
                int cc = col - hh * 192;
                if (cc < 64) {
                    size_t q0o = ((size_t)row0 * 16 + hh) * 64 + cc;
                    size_t q1o = ((size_t)(row0 + 8) * 16 + hh) * 64 + cc;
                    __nv_bfloat162 h0, h1, l0, l1;
                    split1(v0, h0.x, l0.x); split1(v1, h0.y, l0.y);
                    split1(v2, h1.x, l1.x); split1(v3, h1.y, l1.y);
                    *(__nv_bfloat162*)(OHi + q0o) = h0;
                    *(__nv_bfloat162*)(OLo + q0o) = l0;
                    *(__nv_bfloat162*)(OHi + q1o) = h1;
                    *(__nv_bfloat162*)(OLo + q1o) = l1;
                }
            }
        }
    }
}

// ---------------------------------------------------------------------------
// Sliding-window attention (QE row stride NJP)
// ---------------------------------------------------------------------------
#define ATT_SMEM 52224
__global__ __launch_bounds__(256) void attn_kernel(
    const float* __restrict__ QKVm, const float* __restrict__ QE,
    __nv_bfloat16* __restrict__ OHi, __nv_bfloat16* __restrict__ OLo)
{
    extern __shared__ float sm[];
    float* QsT = sm;              // [k][si]  stride 68
    float* KT  = sm + 4352;       // [k][kk]  stride 68 ; reused as P[si][kk]
    float* Vs  = sm + 8704;       // [kk][d]  stride 68

    const int s0 = blockIdx.x * 64;
    const int g  = blockIdx.y;
    const int bh = blockIdx.z;
    const int b = bh >> 4, h = bh & 15;
    const int tid = threadIdx.x;
    const int tx = tid & 15, ty = tid >> 4;
    const int tbase = g * 512 + s0;
    const int base_key = tbase - 512;

    const int li = tid >> 2;
    const int kb = (tid & 3) << 4;

    {
        int t = tbase + li;
        const float* qp = QKVm + (size_t)(t * 2 + b) * QKV_N + h * 192 + kb;
#pragma unroll
        for (int q = 0; q < 4; q++) {
            float4 v = *(const float4*)(qp + q * 4);
            QsT[(kb + q * 4 + 0) * 68 + li] = v.x;
            QsT[(kb + q * 4 + 1) * 68 + li] = v.y;
            QsT[(kb + q * 4 + 2) * 68 + li] = v.z;
            QsT[(kb + q * 4 + 3) * 68 + li] = v.w;
        }
    }

    float O[4][4];
    float mrow[4], lrow[4];
#pragma unroll
    for (int r = 0; r < 4; r++) {
        mrow[r] = -1e30f; lrow[r] = 0.f;
#pragma unroll
        for (int c = 0; c < 4; c++) O[r][c] = 0.f;
    }
    size_t qe_base[4];
#pragma unroll
    for (int r = 0; r < 4; r++) {
        int t = tbase + ty * 4 + r;
        qe_base[r] = ((size_t)(t * 2 + b) * 16 + h) * NJP;
    }

    for (int kt = 0; kt < 9; kt++) {
        __syncthreads();
        {
            int kk = li;
            int u = base_key + kt * 64 + kk;
            if (u >= 0) {
                const float* kp = QKVm + (size_t)(u * 2 + b) * QKV_N + h * 192 + 64 + kb;
#pragma unroll
                for (int q = 0; q < 4; q++) {
                    float4 k4 = *(const float4*)(kp + q * 4);
                    int kc = kb + q * 4;
                    KT[(kc + 0) * 68 + kk] = k4.x;
                    KT[(kc + 1) * 68 + kk] = k4.y;
                    KT[(kc + 2) * 68 + kk] = k4.z;
                    KT[(kc + 3) * 68 + kk] = k4.w;
                    *(float4*)&Vs[kk * 68 + kc] = *(const float4*)(kp + 64 + q * 4);
                }
            } else {
                float4 z = make_float4(0.f, 0.f, 0.f, 0.f);
#pragma unroll
                for (int q = 0; q < 4; q++) {
                    int kc = kb + q * 4;
                    KT[(kc + 0) * 68 + kk] = 0.f;
                    KT[(kc + 1) * 68 + kk] = 0.f;
                    KT[(kc + 2) * 68 + kk] = 0.f;
                    KT[(kc + 3) * 68 + kk] = 0.f;
                    *(float4*)&Vs[kk * 68 + kc] = z;
                }
            }
        }
        __syncthreads();

        float acc[4][4];
#pragma unroll
        for (int r = 0; r < 4; r++)
#pragma unroll
            for (int c = 0; c < 4; c++) acc[r][c] = 0.f;
#pragma unroll 8
        for (int k = 0; k < 64; k++) {
            float4 qv = *(const float4*)&QsT[k * 68 + ty * 4];
            float4 kv = *(const float4*)&KT[k * 68 + tx * 4];
            float qa[4] = {qv.x, qv.y, qv.z, qv.w};
            float ka[4] = {kv.x, kv.y, kv.z, kv.w};
#pragma unroll
            for (int r = 0; r < 4; r++)
#pragma unroll
                for (int c = 0; c < 4; c++)
                    acc[r][c] += qa[r] * ka[c];
        }

#pragma unroll
        for (int r = 0; r < 4; r++) {
            int si = ty * 4 + r;
#pragma unroll
            for (int c = 0; c < 4; c++) {
                int kk = tx * 4 + c;
                int j = kt * 64 + kk - si;
                int u = base_key + kt * 64 + kk;
                if (j >= 0 && j <= 512 && u >= 0)
                    acc[r][c] = (acc[r][c] + QE[qe_base[r] + j]) * 0.125f;
                else
                    acc[r][c] = -1e30f;
            }
        }
        float mnew[4], corr[4];
#pragma unroll
        for (int r = 0; r < 4; r++) {
            float tm = fmaxf(fmaxf(acc[r][0], acc[r][1]), fmaxf(acc[r][2], acc[r][3]));
#pragma unroll
            for (int o = 1; o < 16; o <<= 1)
                tm = fmaxf(tm, __shfl_xor_sync(0xffffffffu, tm, o));
            mnew[r] = fmaxf(mrow[r], tm);
            corr[r] = __expf(mrow[r] - mnew[r]);
            float rs = 0.f;
#pragma unroll
            for (int c = 0; c < 4; c++) {
                float p = (acc[r][c] > -5e29f) ? __expf(acc[r][c] - mnew[r]) : 0.f;
                acc[r][c] = p;
                rs += p;
            }
#pragma unroll
            for (int o = 1; o < 16; o <<= 1)
                rs += __shfl_xor_sync(0xffffffffu, rs, o);
            lrow[r] = lrow[r] * corr[r] + rs;
            mrow[r] = mnew[r];
#pragma unroll
            for (int c = 0; c < 4; c++) O[r][c] *= corr[r];
        }

        __syncthreads();
#pragma unroll
        for (int r = 0; r < 4; r++) {
            float4 pv; pv.x = acc[r][0]; pv.y = acc[r][1];
            pv.z = acc[r][2]; pv.w = acc[r][3];
            *(float4*)&KT[(ty * 4 + r) * 68 + tx * 4] = pv;
        }
        __syncthreads();

#pragma unroll 8
        for (int kk = 0; kk < 64; kk++) {
            float pa[4];
#pragma unroll
            for (int r = 0; r < 4; r++) pa[r] = KT[(ty * 4 + r) * 68 + kk];
            float4 vv = *(const float4*)&Vs[kk * 68 + tx * 4];
            float va[4] = {vv.x, vv.y, vv.z, vv.w};
#pragma unroll
            for (int r = 0; r < 4; r++)
#pragma unroll
                for (int c = 0; c < 4; c++)
                    O[r][c] += pa[r] * va[c];
        }
    }

#pragma unroll
    for (int r = 0; r < 4; r++) {
        int t = tbase + ty * 4 + r;
        float inv = 1.f / lrow[r];
        size_t base = (size_t)(t * 2 + b) * 1024 + h * 64 + tx * 4;
        __nv_bfloat162 h0, h1, l0, l1;
        split1(O[r][0] * inv, h0.x, l0.x);
        split1(O[r][1] * inv, h0.y, l0.y);
        split1(O[r][2] * inv, h1.x, l1.x);
        split1(O[r][3] * inv, h1.y, l1.y);
        *(__nv_bfloat162*)(OHi + base)     = h0;
        *(__nv_bfloat162*)(OHi + base + 2) = h1;
        *(__nv_bfloat162*)(OLo + base)     = l0;
        *(__nv_bfloat162*)(OLo + base + 2) = l1;
    }
}

// ---------------------------------------------------------------------------
// nxt output copy
// ---------------------------------------------------------------------------
__global__ __launch_bounds__(256) void nxt_kernel(
    const float* __restrict__ QKVm, float* __restrict__ NXT)
{
    int idx = blockIdx.x * 256 + threadIdx.x;
    int c  = idx & 127;
    int bh = (idx >> 7) & 31;
    int s  = idx >> 12;
    int b = bh >> 4, h = bh & 15;
    int t = 3584 + s;
    NXT[idx] = QKVm[(size_t)(t * 2 + b) * QKV_N + h * 192 + 64 + c];
}

// ---------------------------------------------------------------------------
extern "C" void kernel_launch(void* const* d_in, const int* in_sizes, int n_in,
                              void* d_out, int out_size)
{
    const float* x      = (const float*)d_in[0];
    const float* ln1_g  = (const float*)d_in[1];
    const float* ln1_b  = (const float*)d_in[2];
    const float* qkv_w  = (const float*)d_in[3];
    const float* qkv_b  = (const float*)d_in[4];
    const float* pos_emb= (const float*)d_in[5];
    const float* out_w  = (const float*)d_in[6];
    const float* ln2_g  = (const float*)d_in[7];
    const float* ln2_b  = (const float*)d_in[8];
    const float* fc1_w  = (const float*)d_in[9];
    const float* fc1_b  = (const float*)d_in[10];
    const float* fc2_w  = (const float*)d_in[11];
    const float* fc2_b  = (const float*)d_in[12];
    float* out = (float*)d_out;

    float* scratch = 0;
    cudaGetSymbolAddress((void**)&scratch, g_scratch);
    __nv_bfloat16 *Ahi, *Alo, *A2hi, *A2lo, *Whi, *Wlo, *PThi, *PTlo;
    cudaGetSymbolAddress((void**)&Ahi, g_act_hi);
    cudaGetSymbolAddress((void**)&Alo, g_act_lo);
    cudaGetSymbolAddress((void**)&A2hi, g_act2_hi);
    cudaGetSymbolAddress((void**)&A2lo, g_act2_lo);
    cudaGetSymbolAddress((void**)&Whi, g_w_hi);
    cudaGetSymbolAddress((void**)&Wlo, g_w_lo);
    cudaGetSymbolAddress((void**)&PThi, g_pet_hi);
    cudaGetSymbolAddress((void**)&PTlo, g_pet_lo);

    float* OUT1 = scratch + OFF_OUT1;
    float* QKVm = scratch + OFF_QKV;
    float* QE   = scratch + OFF_QE;

    cudaFuncSetAttribute(mma_gemm<true, false, false, false, true>,  cudaFuncAttributeMaxDynamicSharedMemorySize, MMA_SMEM);
    cudaFuncSetAttribute(mma_gemm<false, false, false, false, false>,cudaFuncAttributeMaxDynamicSharedMemorySize, MMA_SMEM);
    cudaFuncSetAttribute(mma_gemm<false, false, true, false, false>, cudaFuncAttributeMaxDynamicSharedMemorySize, MMA_SMEM);
    cudaFuncSetAttribute(mma_gemm<true, true, false, true, false>,   cudaFuncAttributeMaxDynamicSharedMemorySize, MMA_SMEM);
    cudaFuncSetAttribute(mma_gemm<true, false, true, false, false>,  cudaFuncAttributeMaxDynamicSharedMemorySize, MMA_SMEM);
    cudaFuncSetAttribute(attn_kernel, cudaFuncAttributeMaxDynamicSharedMemorySize, ATT_SMEM);

    // 0. pe^T split (tiny, independent)
    pe_split_t_kernel<<<160, 256>>>(pos_emb, PThi, PTlo);
    // 1. LN1 + split -> act
    ln_split_kernel<<<NROWS, 256>>>(x, ln1_g, ln1_b, Ahi, Alo);
    // 2. QKV = H @ qkv_w^T + qkv_b (fp32), also emit Qsplit -> A2 buffers
    split_kernel<<<(QKV_N * EMB) / 1024, 256>>>(qkv_w, Whi, Wlo);
    mma_gemm<true, false, false, false, true><<<dim3(QKV_N / 128, NROWS / 128), 256, MMA_SMEM>>>(
        Ahi, Alo, Whi, Wlo, qkv_b, 0, QKVm, A2hi, A2lo, NROWS, QKV_N, EMB);
    // 3. QE = Qsplit @ peT^T  (M=131072, N=640, K=64)
    mma_gemm<false, false, false, false, false><<<dim3(NJP / 128, 131072 / 128), 256, MMA_SMEM>>>(
        A2hi, A2lo, PThi, PTlo, 0, 0, QE, 0, 0, 131072, NJP, 64);
    // 4. attention -> act (split out)
    attn_kernel<<<dim3(8, 8, 32), 256, ATT_SMEM>>>(QKVm, QE, Ahi, Alo);
    // 5. OUT1 = AV @ out_w^T + x
    split_kernel<<<(EMB * EMB) / 1024, 256>>>(out_w, Whi, Wlo);
    mma_gemm<false, false, true, false, false><<<dim3(EMB / 128, NROWS / 128), 256, MMA_SMEM>>>(
        Ahi, Alo, Whi, Wlo, 0, x, OUT1, 0, 0, NROWS, EMB, EMB);
    // 6. LN2 + split -> act
    ln_split_kernel<<<NROWS, 256>>>(OUT1, ln2_g, ln2_b, Ahi, Alo);
    // 7. act2 = split(relu(H2 @ fc1_w^T + fc1_b))
    split_kernel<<<(FFN_I * EMB) / 1024, 256>>>(fc1_w, Whi, Wlo);
    mma_gemm<true, true, false, true, false><<<dim3(FFN_I / 128, NROWS / 128), 256, MMA_SMEM>>>(
        Ahi, Alo, Whi, Wlo, fc1_b, 0, 0, A2hi, A2lo, NROWS, FFN_I, EMB);
    // 8. out = FF1 @ fc2_w^T + fc2_b + OUT1
    split_kernel<<<(EMB * FFN_I) / 1024, 256>>>(fc2_w, Whi, Wlo);
    mma_gemm<true, false, true, false, false><<<dim3(EMB / 128, NROWS / 128), 256, MMA_SMEM>>>(
        A2hi, A2lo, Whi, Wlo, fc2_b, OUT1, out, 0, 0, NROWS, EMB, FFN_I);
    // 9. nxt slice
    nxt_kernel<<<2097152 / 256, 256>>>(QKVm, out + 8388608);
}

// round 10
// speedup vs baseline: 1.0146x; 1.0146x over previous
#include <cuda_runtime.h>
#include <cuda_bf16.h>
#include <math.h>
#include <stdint.h>

// ---------------------------------------------------------------------------
// Shapes: x (T=4096, B=2, E=1024); H=16 heads, dk=dv=64; window 512 (513 rel pos)
// QKV rows = t*B + b (8192), cols = h*192 + c  (c<64 q, 64..127 k, 128..191 v)
// QE layout: bf16 [r = (t*2+b)*16+h][j], row stride 640 (cols 513..639 pad)
// ---------------------------------------------------------------------------
#define NROWS 8192
#define EMB   1024
#define QKV_N 3072
#define FFN_I 4096
#define NJ    513
#define NJP   640

// fp32 scratch offsets (floats)
#define OFF_OUT1   16777216ull
#define OFF_QKV    33554432ull
#define OFF_QE     92274688ull   // used as bf16[131072*640] (fits in fp32 span)
#define SCRATCH_FLOATS 176160768ull

__device__ float g_scratch[SCRATCH_FLOATS];

// split-bf16 buffers
__device__ __nv_bfloat16 g_act_hi[8388608];
__device__ __nv_bfloat16 g_act_lo[8388608];
__device__ __nv_bfloat16 g_act2_hi[33554432];   // fc1 out; reused as Qsplit earlier
__device__ __nv_bfloat16 g_act2_lo[33554432];
__device__ __nv_bfloat16 g_w_hi[4194304];
__device__ __nv_bfloat16 g_w_lo[4194304];
__device__ __nv_bfloat16 g_pet_hi[40960];       // pe^T padded [640][64]
__device__ __nv_bfloat16 g_pet_lo[40960];

__device__ __forceinline__ uint32_t smem_u32(const void* p) {
    uint32_t a;
    asm("{ .reg .u64 t; cvta.to.shared.u64 t, %1; cvt.u32.u64 %0, t; }" : "=r"(a) : "l"(p));
    return a;
}

__device__ __forceinline__ void split1(float v, __nv_bfloat16& h, __nv_bfloat16& l) {
    h = __float2bfloat16(v);
    l = __float2bfloat16(v - __bfloat162float(h));
}

// ---------------------------------------------------------------------------
// split fp32 -> (hi, lo) bf16   (weights)
// ---------------------------------------------------------------------------
__global__ __launch_bounds__(256) void split_kernel(
    const float* __restrict__ X, __nv_bfloat16* __restrict__ Hi,
    __nv_bfloat16* __restrict__ Lo)
{
    int i4 = blockIdx.x * 256 + threadIdx.x;
    float4 v = ((const float4*)X)[i4];
    __nv_bfloat162 hi0, hi1, lo0, lo1;
    split1(v.x, hi0.x, lo0.x);
    split1(v.y, hi0.y, lo0.y);
    split1(v.z, hi1.x, lo1.x);
    split1(v.w, hi1.y, lo1.y);
    ((__nv_bfloat162*)Hi)[i4 * 2]     = hi0;
    ((__nv_bfloat162*)Hi)[i4 * 2 + 1] = hi1;
    ((__nv_bfloat162*)Lo)[i4 * 2]     = lo0;
    ((__nv_bfloat162*)Lo)[i4 * 2 + 1] = lo1;
}

// ---------------------------------------------------------------------------
// pe^T split: out[j][k] = split(pe[k*513 + j]), j<513 else 0.  640*64 elems.
// ---------------------------------------------------------------------------
__global__ __launch_bounds__(256) void pe_split_t_kernel(
    const float* __restrict__ pe, __nv_bfloat16* __restrict__ Hi,
    __nv_bfloat16* __restrict__ Lo)
{
    int idx = blockIdx.x * 256 + threadIdx.x;   // 40960
    int k = idx & 63;
    int j = idx >> 6;
    float v = (j < NJ) ? pe[(size_t)k * NJ + j] : 0.f;
    __nv_bfloat16 h, l;
    split1(v, h, l);
    Hi[idx] = h;
    Lo[idx] = l;
}

// ---------------------------------------------------------------------------
// LayerNorm fused with split
// ---------------------------------------------------------------------------
__global__ __launch_bounds__(256) void ln_split_kernel(
    const float* __restrict__ X, const float* __restrict__ G,
    const float* __restrict__ Bt, __nv_bfloat16* __restrict__ Hi,
    __nv_bfloat16* __restrict__ Lo)
{
    __shared__ float ssum[8], ssq[8], smv[2];
    int row = blockIdx.x;
    int tid = threadIdx.x;
    const float4* xr = (const float4*)(X + (size_t)row * EMB);
    float4 v = xr[tid];
    float s = v.x + v.y + v.z + v.w;
    float q = v.x*v.x + v.y*v.y + v.z*v.z + v.w*v.w;
#pragma unroll
    for (int o = 16; o > 0; o >>= 1) {
        s += __shfl_xor_sync(0xffffffffu, s, o);
        q += __shfl_xor_sync(0xffffffffu, q, o);
    }
    if ((tid & 31) == 0) { ssum[tid >> 5] = s; ssq[tid >> 5] = q; }
    __syncthreads();
    if (tid == 0) {
        float S = 0.f, Q = 0.f;
#pragma unroll
        for (int i = 0; i < 8; i++) { S += ssum[i]; Q += ssq[i]; }
        float mean = S * (1.f / EMB);
        float var  = Q * (1.f / EMB) - mean * mean;
        smv[0] = mean;
        smv[1] = rsqrtf(var + 1e-5f);
    }
    __syncthreads();
    float mean = smv[0], inv = smv[1];
    float4 g = ((const float4*)G)[tid];
    float4 b = ((const float4*)Bt)[tid];
    float o0 = (v.x - mean) * inv * g.x + b.x;
    float o1 = (v.y - mean) * inv * g.y + b.y;
    float o2 = (v.z - mean) * inv * g.z + b.z;
    float o3 = (v.w - mean) * inv * g.w + b.w;
    __nv_bfloat162 hi0, hi1, lo0, lo1;
    split1(o0, hi0.x, lo0.x);
    split1(o1, hi0.y, lo0.y);
    split1(o2, hi1.x, lo1.x);
    split1(o3, hi1.y, lo1.y);
    size_t i4 = (size_t)row * 256 + tid;
    ((__nv_bfloat162*)Hi)[i4 * 2]     = hi0;
    ((__nv_bfloat162*)Hi)[i4 * 2 + 1] = hi1;
    ((__nv_bfloat162*)Lo)[i4 * 2]     = lo0;
    ((__nv_bfloat162*)Lo)[i4 * 2 + 1] = lo1;
}

// ---------------------------------------------------------------------------
// mma.sync bf16 split GEMM NT: C = (Ah+Al)(Bh+Bl)^T (+bias)(relu)(+Res)
// CTA 128x128, BK=32, 8 warps. 3-stage cp.async pipeline, ONE barrier/iter,
// loads issued AFTER compute (LSU ordering: LDSM first, cp.async behind).
// SPLITO: write (hi,lo) bf16. HALFO: write single bf16 (no lo).
// QOUT: also write q-columns (c%192<64) as split bf16 [row*16+h][64] (QKV only)
// ---------------------------------------------------------------------------
#define STAGE_BYTES 32768
#define MMA_SMEM    98304

__device__ __forceinline__ void cp16(uint32_t dst, const void* src) {
    asm volatile("cp.async.cg.shared.global [%0], [%1], 16;" :: "r"(dst), "l"(src));
}
__device__ __forceinline__ void ldm4(uint32_t* r, uint32_t addr) {
    asm volatile("ldmatrix.sync.aligned.m8n8.x4.shared.b16 {%0,%1,%2,%3}, [%4];"
                 : "=r"(r[0]), "=r"(r[1]), "=r"(r[2]), "=r"(r[3]) : "r"(addr));
}
__device__ __forceinline__ void mma16816(float* c, const uint32_t* a,
                                         uint32_t b0, uint32_t b1) {
    asm volatile(
        "mma.sync.aligned.m16n8k16.row.col.f32.bf16.bf16.f32 "
        "{%0,%1,%2,%3}, {%4,%5,%6,%7}, {%8,%9}, {%0,%1,%2,%3};"
        : "+f"(c[0]), "+f"(c[1]), "+f"(c[2]), "+f"(c[3])
        : "r"(a[0]), "r"(a[1]), "r"(a[2]), "r"(a[3]), "r"(b0), "r"(b1));
}

template<bool BIAS, bool RELU, bool RES, bool SPLITO, bool QOUT, bool HALFO>
__global__ __launch_bounds__(256, 2) void mma_gemm(
    const __nv_bfloat16* __restrict__ Ah, const __nv_bfloat16* __restrict__ Al,
    const __nv_bfloat16* __restrict__ Bh, const __nv_bfloat16* __restrict__ Bl,
    const float* __restrict__ bias, const float* __restrict__ Res,
    float* __restrict__ C, __nv_bfloat16* __restrict__ OHi,
    __nv_bfloat16* __restrict__ OLo, int M, int N, int K)
{
    extern __shared__ char smem[];
    const uint32_t sbase = smem_u32(smem);
    const int tid = threadIdx.x;
    const int wid = tid >> 5, lane = tid & 31;
    const int bm = blockIdx.y * 128, bn = blockIdx.x * 128;
    const int m0w = (wid >> 2) * 64, n0w = (wid & 3) * 32;

    const int r0 = tid >> 2,         c0 = tid & 3;
    const int r1 = (tid + 256) >> 2, c1 = (tid + 256) & 3;
    const uint32_t so0 = (uint32_t)(r0 * 64 + ((c0 ^ ((r0 >> 1) & 3)) * 16));
    const uint32_t so1 = (uint32_t)(r1 * 64 + ((c1 ^ ((r1 >> 1) & 3)) * 16));
    const size_t offA0 = (size_t)(bm + r0) * K + c0 * 8;
    const size_t offA1 = (size_t)(bm + r1) * K + c1 * 8;
    const size_t offB0 = (size_t)(bn + r0) * K + c0 * 8;
    const size_t offB1 = (size_t)(bn + r1) * K + c1 * 8;

    float acc[4][4][4];
#pragma unroll
    for (int a = 0; a < 4; a++)
#pragma unroll
        for (int n = 0; n < 4; n++)
#pragma unroll
            for (int q = 0; q < 4; q++) acc[a][n][q] = 0.f;

    const int nt = K >> 5;
    const int rowA_base = m0w + (lane & 15);
    const int rowB_base = n0w + (lane & 15);
    const int chsel = lane >> 4;

#define LOAD_STAGE(s, k0)                                                     \
    do {                                                                      \
        uint32_t d = sbase + (s) * STAGE_BYTES;                               \
        cp16(d + so0,          Ah + offA0 + (k0));                            \
        cp16(d + so1,          Ah + offA1 + (k0));                            \
        cp16(d + 8192  + so0,  Al + offA0 + (k0));                            \
        cp16(d + 8192  + so1,  Al + offA1 + (k0));                            \
        cp16(d + 16384 + so0,  Bh + offB0 + (k0));                            \
        cp16(d + 16384 + so1,  Bh + offB1 + (k0));                            \
        cp16(d + 24576 + so0,  Bl + offB0 + (k0));                            \
        cp16(d + 24576 + so1,  Bl + offB1 + (k0));                            \
    } while (0)

    // 3-stage pipeline: preload 0,1
    LOAD_STAGE(0, 0);
    asm volatile("cp.async.commit_group;");
    if (nt > 1) LOAD_STAGE(1, 32);
    asm volatile("cp.async.commit_group;");

    int stage = 0;
    for (int i = 0; i < nt; i++) {
        asm volatile("cp.async.wait_group 1;");
        __syncthreads();   // stage i ready; all threads done with iter i-1 reads

        uint32_t base = sbase + stage * STAGE_BYTES;
#pragma unroll
        for (int ks = 0; ks < 2; ks++) {
            const int chunk = ks * 2 + chsel;
            uint32_t bh[2][4], bl[2][4];
#pragma unroll
            for (int p = 0; p < 2; p++) {
                int row = rowB_base + p * 16;
                uint32_t ad = base + 16384 + (uint32_t)(row * 64 + ((chunk ^ ((row >> 1) & 3)) * 16));
                ldm4(bh[p], ad);
                ldm4(bl[p], ad + 8192);
            }
#pragma unroll
            for (int a = 0; a < 4; a++) {
                uint32_t ah[4], al[4];
                int row = rowA_base + a * 16;
                uint32_t ad = base + (uint32_t)(row * 64 + ((chunk ^ ((row >> 1) & 3)) * 16));
                ldm4(ah, ad);
                ldm4(al, ad + 8192);
#pragma unroll
                for (int n = 0; n < 4; n++) {
                    int p = n >> 1, q = n & 1;
                    mma16816(acc[a][n], ah, bh[p][q], bh[p][q + 2]);
                    mma16816(acc[a][n], ah, bl[p][q], bl[p][q + 2]);
                    mma16816(acc[a][n], al, bh[p][q], bh[p][q + 2]);
                }
            }
        }
        // loads AFTER compute: target = buffer read at iter i-1 (barrier-safe)
        int nx = i + 2;
        if (nx < nt) {
            int ns = stage + 2; if (ns >= 3) ns -= 3;
            LOAD_STAGE(ns, nx << 5);
        }
        asm volatile("cp.async.commit_group;");
        if (++stage == 3) stage = 0;
    }
#undef LOAD_STAGE

    const int g = lane >> 2, t = lane & 3;
#pragma unroll
    for (int a = 0; a < 4; a++) {
#pragma unroll
        for (int n = 0; n < 4; n++) {
            int row0 = bm + m0w + a * 16 + g;
            int col  = bn + n0w + n * 8 + 2 * t;
            float v0 = acc[a][n][0], v1 = acc[a][n][1];
            float v2 = acc[a][n][2], v3 = acc[a][n][3];
            if (BIAS) {
                float b0 = bias[col], b1 = bias[col + 1];
                v0 += b0; v1 += b1; v2 += b0; v3 += b1;
            }
            if (RELU) {
                v0 = fmaxf(v0, 0.f); v1 = fmaxf(v1, 0.f);
                v2 = fmaxf(v2, 0.f); v3 = fmaxf(v3, 0.f);
            }
            if (RES) {
                const float2 q0 = *(const float2*)(Res + (size_t)row0 * N + col);
                const float2 q1 = *(const float2*)(Res + (size_t)(row0 + 8) * N + col);
                v0 += q0.x; v1 += q0.y; v2 += q1.x; v3 += q1.y;
            }
            if (SPLITO) {
                __nv_bfloat162 h0, h1, l0, l1;
                split1(v0, h0.x, l0.x); split1(v1, h0.y, l0.y);
                split1(v2, h1.x, l1.x); split1(v3, h1.y, l1.y);
                *(__nv_bfloat162*)(OHi + (size_t)row0 * N + col)       = h0;
                *(__nv_bfloat162*)(OLo + (size_t)row0 * N + col)       = l0;
                *(__nv_bfloat162*)(OHi + (size_t)(row0 + 8) * N + col) = h1;
                *(__nv_bfloat162*)(OLo + (size_t)(row0 + 8) * N + col) = l1;
            } else if (HALFO) {
                __nv_bfloat162 h0, h1;
                h0.x = __float2bfloat16(v0); h0.y = __float2bfloat16(v1);
                h1.x = __float2bfloat16(v2); h1.y = __float2bfloat16(v3);
                *(__nv_bfloat162*)(OHi + (size_t)row0 * N + col)       = h0;
                *(__nv_bfloat162*)(OHi + (size_t)(row0 + 8) * N + col) = h1;
            } else {
                float2 o0; o0.x = v0; o0.y = v1;
                float2 o1; o1.x = v2; o1.y = v3;
                *(float2*)(C + (size_t)row0 * N + col)       = o0;
                *(float2*)(C + (size_t)(row0 + 8) * N + col) = o1;
            }
            if (QOUT) {
                int hh = col / 192;
                int cc = col - hh * 192;
                if (cc < 64) {
                    size_t q0o = ((size_t)row0 * 16 + hh) * 64 + cc;
                    size_t q1o = ((size_t)(row0 + 8) * 16 + hh) * 64 + cc;
                    __nv_bfloat162 h0, h1, l0, l1;
                    split1(v0, h0.x, l0.x); split1(v1, h0.y, l0.y);
                    split1(v2, h1.x, l1.x); split1(v3, h1.y, l1.y);
                    *(__nv_bfloat162*)(OHi + q0o) = h0;
                    *(__nv_bfloat162*)(OLo + q0o) = l0;
                    *(__nv_bfloat162*)(OHi + q1o) = h1;
                    *(__nv_bfloat162*)(OLo + q1o) = l1;
                }
            }
        }
    }
}

// ---------------------------------------------------------------------------
// Sliding-window attention (QE is bf16, row stride NJP)
// ---------------------------------------------------------------------------
#define ATT_SMEM 52224
__global__ __launch_bounds__(256) void attn_kernel(
    const float* __restrict__ QKVm, const __nv_bfloat16* __restrict__ QEb,
    __nv_bfloat16* __restrict__ OHi, __nv_bfloat16* __restrict__ OLo)
{
    extern __shared__ float sm[];
    float* QsT = sm;              // [k][si]  stride 68
    float* KT  = sm + 4352;       // [k][kk]  stride 68 ; reused as P[si][kk]
    float* Vs  = sm + 8704;       // [kk][d]  stride 68

    const int s0 = blockIdx.x * 64;
    const int g  = blockIdx.y;
    const int bh = blockIdx.z;
    const int b = bh >> 4, h = bh & 15;
    const int tid = threadIdx.x;
    const int tx = tid & 15, ty = tid >> 4;
    const int tbase = g * 512 + s0;
    const int base_key = tbase - 512;

    const int li = tid >> 2;
    const int kb = (tid & 3) << 4;

    {
        int t = tbase + li;
        const float* qp = QKVm + (size_t)(t * 2 + b) * QKV_N + h * 192 + kb;
#pragma unroll
        for (int q = 0; q < 4; q++) {
            float4 v = *(const float4*)(qp + q * 4);
            QsT[(kb + q * 4 + 0) * 68 + li] = v.x;
            QsT[(kb + q * 4 + 1) * 68 + li] = v.y;
            QsT[(kb + q * 4 + 2) * 68 + li] = v.z;
            QsT[(kb + q * 4 + 3) * 68 + li] = v.w;
        }
    }

    float O[4][4];
    float mrow[4], lrow[4];
#pragma unroll
    for (int r = 0; r < 4; r++) {
        mrow[r] = -1e30f; lrow[r] = 0.f;
#pragma unroll
        for (int c = 0; c < 4; c++) O[r][c] = 0.f;
    }
    size_t qe_base[4];
#pragma unroll
    for (int r = 0; r < 4; r++) {
        int t = tbase + ty * 4 + r;
        qe_base[r] = ((size_t)(t * 2 + b) * 16 + h) * NJP;
    }

    for (int kt = 0; kt < 9; kt++) {
        __syncthreads();
        {
            int kk = li;
            int u = base_key + kt * 64 + kk;
            if (u >= 0) {
                const float* kp = QKVm + (size_t)(u * 2 + b) * QKV_N + h * 192 + 64 + kb;
#pragma unroll
                for (int q = 0; q < 4; q++) {
                    float4 k4 = *(const float4*)(kp + q * 4);
                    int kc = kb + q * 4;
                    KT[(kc + 0) * 68 + kk] = k4.x;
                    KT[(kc + 1) * 68 + kk] = k4.y;
                    KT[(kc + 2) * 68 + kk] = k4.z;
                    KT[(kc + 3) * 68 + kk] = k4.w;
                    *(float4*)&Vs[kk * 68 + kc] = *(const float4*)(kp + 64 + q * 4);
                }
            } else {
                float4 z = make_float4(0.f, 0.f, 0.f, 0.f);
#pragma unroll
                for (int q = 0; q < 4; q++) {
                    int kc = kb + q * 4;
                    KT[(kc + 0) * 68 + kk] = 0.f;
                    KT[(kc + 1) * 68 + kk] = 0.f;
                    KT[(kc + 2) * 68 + kk] = 0.f;
                    KT[(kc + 3) * 68 + kk] = 0.f;
                    *(float4*)&Vs[kk * 68 + kc] = z;
                }
            }
        }
        __syncthreads();

        float acc[4][4];
#pragma unroll
        for (int r = 0; r < 4; r++)
#pragma unroll
            for (int c = 0; c < 4; c++) acc[r][c] = 0.f;
#pragma unroll 8
        for (int k = 0; k < 64; k++) {
            float4 qv = *(const float4*)&QsT[k * 68 + ty * 4];
            float4 kv = *(const float4*)&KT[k * 68 + tx * 4];
            float qa[4] = {qv.x, qv.y, qv.z, qv.w};
            float ka[4] = {kv.x, kv.y, kv.z, kv.w};
#pragma unroll
            for (int r = 0; r < 4; r++)
#pragma unroll
                for (int c = 0; c < 4; c++)
                    acc[r][c] += qa[r] * ka[c];
        }

#pragma unroll
        for (int r = 0; r < 4; r++) {
            int si = ty * 4 + r;
#pragma unroll
            for (int c = 0; c < 4; c++) {
                int kk = tx * 4 + c;
                int j = kt * 64 + kk - si;
                int u = base_key + kt * 64 + kk;
                if (j >= 0 && j <= 512 && u >= 0)
                    acc[r][c] = (acc[r][c] + __bfloat162float(QEb[qe_base[r] + j])) * 0.125f;
                else
                    acc[r][c] = -1e30f;
            }
        }
        float mnew[4], corr[4];
#pragma unroll
        for (int r = 0; r < 4; r++) {
            float tm = fmaxf(fmaxf(acc[r][0], acc[r][1]), fmaxf(acc[r][2], acc[r][3]));
#pragma unroll
            for (int o = 1; o < 16; o <<= 1)
                tm = fmaxf(tm, __shfl_xor_sync(0xffffffffu, tm, o));
            mnew[r] = fmaxf(mrow[r], tm);
            corr[r] = __expf(mrow[r] - mnew[r]);
            float rs = 0.f;
#pragma unroll
            for (int c = 0; c < 4; c++) {
                float p = (acc[r][c] > -5e29f) ? __expf(acc[r][c] - mnew[r]) : 0.f;
                acc[r][c] = p;
                rs += p;
            }
#pragma unroll
            for (int o = 1; o < 16; o <<= 1)
                rs += __shfl_xor_sync(0xffffffffu, rs, o);
            lrow[r] = lrow[r] * corr[r] + rs;
            mrow[r] = mnew[r];
#pragma unroll
            for (int c = 0; c < 4; c++) O[r][c] *= corr[r];
        }

        __syncthreads();
#pragma unroll
        for (int r = 0; r < 4; r++) {
            float4 pv; pv.x = acc[r][0]; pv.y = acc[r][1];
            pv.z = acc[r][2]; pv.w = acc[r][3];
            *(float4*)&KT[(ty * 4 + r) * 68 + tx * 4] = pv;
        }
        __syncthreads();

#pragma unroll 8
        for (int kk = 0; kk < 64; kk++) {
            float pa[4];
#pragma unroll
            for (int r = 0; r < 4; r++) pa[r] = KT[(ty * 4 + r) * 68 + kk];
            float4 vv = *(const float4*)&Vs[kk * 68 + tx * 4];
            float va[4] = {vv.x, vv.y, vv.z, vv.w};
#pragma unroll
            for (int r = 0; r < 4; r++)
#pragma unroll
                for (int c = 0; c < 4; c++)
                    O[r][c] += pa[r] * va[c];
        }
    }

#pragma unroll
    for (int r = 0; r < 4; r++) {
        int t = tbase + ty * 4 + r;
        float inv = 1.f / lrow[r];
        size_t base = (size_t)(t * 2 + b) * 1024 + h * 64 + tx * 4;
        __nv_bfloat162 h0, h1, l0, l1;
        split1(O[r][0] * inv, h0.x, l0.x);
        split1(O[r][1] * inv, h0.y, l0.y);
        split1(O[r][2] * inv, h1.x, l1.x);
        split1(O[r][3] * inv, h1.y, l1.y);
        *(__nv_bfloat162*)(OHi + base)     = h0;
        *(__nv_bfloat162*)(OHi + base + 2) = h1;
        *(__nv_bfloat162*)(OLo + base)     = l0;
        *(__nv_bfloat162*)(OLo + base + 2) = l1;
    }
}

// ---------------------------------------------------------------------------
// nxt output copy
// ---------------------------------------------------------------------------
__global__ __launch_bounds__(256) void nxt_kernel(
    const float* __restrict__ QKVm, float* __restrict__ NXT)
{
    int idx = blockIdx.x * 256 + threadIdx.x;
    int c  = idx & 127;
    int bh = (idx >> 7) & 31;
    int s  = idx >> 12;
    int b = bh >> 4, h = bh & 15;
    int t = 3584 + s;
    NXT[idx] = QKVm[(size_t)(t * 2 + b) * QKV_N + h * 192 + 64 + c];
}

// ---------------------------------------------------------------------------
extern "C" void kernel_launch(void* const* d_in, const int* in_sizes, int n_in,
                              void* d_out, int out_size)
{
    const float* x      = (const float*)d_in[0];
    const float* ln1_g  = (const float*)d_in[1];
    const float* ln1_b  = (const float*)d_in[2];
    const float* qkv_w  = (const float*)d_in[3];
    const float* qkv_b  = (const float*)d_in[4];
    const float* pos_emb= (const float*)d_in[5];
    const float* out_w  = (const float*)d_in[6];
    const float* ln2_g  = (const float*)d_in[7];
    const float* ln2_b  = (const float*)d_in[8];
    const float* fc1_w  = (const float*)d_in[9];
    const float* fc1_b  = (const float*)d_in[10];
    const float* fc2_w  = (const float*)d_in[11];
    const float* fc2_b  = (const float*)d_in[12];
    float* out = (float*)d_out;

    float* scratch = 0;
    cudaGetSymbolAddress((void**)&scratch, g_scratch);
    __nv_bfloat16 *Ahi, *Alo, *A2hi, *A2lo, *Whi, *Wlo, *PThi, *PTlo;
    cudaGetSymbolAddress((void**)&Ahi, g_act_hi);
    cudaGetSymbolAddress((void**)&Alo, g_act_lo);
    cudaGetSymbolAddress((void**)&A2hi, g_act2_hi);
    cudaGetSymbolAddress((void**)&A2lo, g_act2_lo);
    cudaGetSymbolAddress((void**)&Whi, g_w_hi);
    cudaGetSymbolAddress((void**)&Wlo, g_w_lo);
    cudaGetSymbolAddress((void**)&PThi, g_pet_hi);
    cudaGetSymbolAddress((void**)&PTlo, g_pet_lo);

    float* OUT1 = scratch + OFF_OUT1;
    float* QKVm = scratch + OFF_QKV;
    __nv_bfloat16* QEb = (__nv_bfloat16*)(scratch + OFF_QE);

    cudaFuncSetAttribute(mma_gemm<true, false, false, false, true, false>,  cudaFuncAttributeMaxDynamicSharedMemorySize, MMA_SMEM);
    cudaFuncSetAttribute(mma_gemm<false, false, false, false, false, true>, cudaFuncAttributeMaxDynamicSharedMemorySize, MMA_SMEM);
    cudaFuncSetAttribute(mma_gemm<false, false, true, false, false, false>, cudaFuncAttributeMaxDynamicSharedMemorySize, MMA_SMEM);
    cudaFuncSetAttribute(mma_gemm<true, true, false, true, false, false>,   cudaFuncAttributeMaxDynamicSharedMemorySize, MMA_SMEM);
    cudaFuncSetAttribute(mma_gemm<true, false, true, false, false, false>,  cudaFuncAttributeMaxDynamicSharedMemorySize, MMA_SMEM);
    cudaFuncSetAttribute(attn_kernel, cudaFuncAttributeMaxDynamicSharedMemorySize, ATT_SMEM);

    // 0. pe^T split (tiny, independent)
    pe_split_t_kernel<<<160, 256>>>(pos_emb, PThi, PTlo);
    // 1. LN1 + split -> act
    ln_split_kernel<<<NROWS, 256>>>(x, ln1_g, ln1_b, Ahi, Alo);
    // 2. QKV = H @ qkv_w^T + qkv_b (fp32), also emit Qsplit -> A2 buffers
    split_kernel<<<(QKV_N * EMB) / 1024, 256>>>(qkv_w, Whi, Wlo);
    mma_gemm<true, false, false, false, true, false><<<dim3(QKV_N / 128, NROWS / 128), 256, MMA_SMEM>>>(
        Ahi, Alo, Whi, Wlo, qkv_b, 0, QKVm, A2hi, A2lo, NROWS, QKV_N, EMB);
    // 3. QE = Qsplit @ peT^T  (M=131072, N=640, K=64) -> bf16 out
    mma_gemm<false, false, false, false, false, true><<<dim3(NJP / 128, 131072 / 128), 256, MMA_SMEM>>>(
        A2hi, A2lo, PThi, PTlo, 0, 0, 0, QEb, 0, 131072, NJP, 64);
    // 4. attention -> act (split out)
    attn_kernel<<<dim3(8, 8, 32), 256, ATT_SMEM>>>(QKVm, QEb, Ahi, Alo);
    // 5. OUT1 = AV @ out_w^T + x
    split_kernel<<<(EMB * EMB) / 1024, 256>>>(out_w, Whi, Wlo);
    mma_gemm<false, false, true, false, false, false><<<dim3(EMB / 128, NROWS / 128), 256, MMA_SMEM>>>(
        Ahi, Alo, Whi, Wlo, 0, x, OUT1, 0, 0, NROWS, EMB, EMB);
    // 6. LN2 + split -> act
    ln_split_kernel<<<NROWS, 256>>>(OUT1, ln2_g, ln2_b, Ahi, Alo);
    // 7. act2 = split(relu(H2 @ fc1_w^T + fc1_b))
    split_kernel<<<(FFN_I * EMB) / 1024, 256>>>(fc1_w, Whi, Wlo);
    mma_gemm<true, true, false, true, false, false><<<dim3(FFN_I / 128, NROWS / 128), 256, MMA_SMEM>>>(
        Ahi, Alo, Whi, Wlo, fc1_b, 0, 0, A2hi, A2lo, NROWS, FFN_I, EMB);
    // 8. out = FF1 @ fc2_w^T + fc2_b + OUT1
    split_kernel<<<(EMB * FFN_I) / 1024, 256>>>(fc2_w, Whi, Wlo);
    mma_gemm<true, false, true, false, false, false><<<dim3(EMB / 128, NROWS / 128), 256, MMA_SMEM>>>(
        A2hi, A2lo, Whi, Wlo, fc2_b, OUT1, out, 0, 0, NROWS, EMB, FFN_I);
    // 9. nxt slice
    nxt_kernel<<<2097152 / 256, 256>>>(QKVm, out + 8388608);
}

// round 11
// speedup vs baseline: 1.1446x; 1.1281x over previous
#include <cuda_runtime.h>
#include <cuda_bf16.h>
#include <math.h>
#include <stdint.h>

// ---------------------------------------------------------------------------
// Shapes: x (T=4096, B=2, E=1024); H=16 heads, dk=dv=64; window 512 (513 rel pos)
// QKV rows = t*B + b (8192), cols = h*192 + c  (c<64 q, 64..127 k, 128..191 v)
// QE: bf16 [r = (t*2+b)*16+h][j], row stride 640 (cols 513..639 pad)
// Ksplit/Vsplit: bf16 head-major [(b*16+h)][t][64]
// ---------------------------------------------------------------------------
#define NROWS 8192
#define EMB   1024
#define QKV_N 3072
#define FFN_I 4096
#define NJ    513
#define NJP   640

#define OFF_OUT1   16777216ull
#define OFF_QKV    33554432ull
#define OFF_QE     92274688ull
#define SCRATCH_FLOATS 176160768ull

__device__ float g_scratch[SCRATCH_FLOATS];

__device__ __nv_bfloat16 g_act_hi[8388608];
__device__ __nv_bfloat16 g_act_lo[8388608];
__device__ __nv_bfloat16 g_act2_hi[33554432];   // fc1 out; Qsplit earlier
__device__ __nv_bfloat16 g_act2_lo[33554432];
__device__ __nv_bfloat16 g_w_hi[4194304];
__device__ __nv_bfloat16 g_w_lo[4194304];
__device__ __nv_bfloat16 g_pet_hi[40960];
__device__ __nv_bfloat16 g_pet_lo[40960];
__device__ __nv_bfloat16 g_k_hi[8388608];
__device__ __nv_bfloat16 g_k_lo[8388608];
__device__ __nv_bfloat16 g_v_hi[8388608];
__device__ __nv_bfloat16 g_v_lo[8388608];

__device__ __forceinline__ uint32_t smem_u32(const void* p) {
    uint32_t a;
    asm("{ .reg .u64 t; cvta.to.shared.u64 t, %1; cvt.u32.u64 %0, t; }" : "=r"(a) : "l"(p));
    return a;
}
__device__ __forceinline__ void split1(float v, __nv_bfloat16& h, __nv_bfloat16& l) {
    h = __float2bfloat16(v);
    l = __float2bfloat16(v - __bfloat162float(h));
}

// ---------------------------------------------------------------------------
__global__ __launch_bounds__(256) void split_kernel(
    const float* __restrict__ X, __nv_bfloat16* __restrict__ Hi,
    __nv_bfloat16* __restrict__ Lo)
{
    int i4 = blockIdx.x * 256 + threadIdx.x;
    float4 v = ((const float4*)X)[i4];
    __nv_bfloat162 hi0, hi1, lo0, lo1;
    split1(v.x, hi0.x, lo0.x);
    split1(v.y, hi0.y, lo0.y);
    split1(v.z, hi1.x, lo1.x);
    split1(v.w, hi1.y, lo1.y);
    ((__nv_bfloat162*)Hi)[i4 * 2]     = hi0;
    ((__nv_bfloat162*)Hi)[i4 * 2 + 1] = hi1;
    ((__nv_bfloat162*)Lo)[i4 * 2]     = lo0;
    ((__nv_bfloat162*)Lo)[i4 * 2 + 1] = lo1;
}

__global__ __launch_bounds__(256) void pe_split_t_kernel(
    const float* __restrict__ pe, __nv_bfloat16* __restrict__ Hi,
    __nv_bfloat16* __restrict__ Lo)
{
    int idx = blockIdx.x * 256 + threadIdx.x;
    int k = idx & 63;
    int j = idx >> 6;
    float v = (j < NJ) ? pe[(size_t)k * NJ + j] : 0.f;
    __nv_bfloat16 h, l;
    split1(v, h, l);
    Hi[idx] = h;
    Lo[idx] = l;
}

__global__ __launch_bounds__(256) void ln_split_kernel(
    const float* __restrict__ X, const float* __restrict__ G,
    const float* __restrict__ Bt, __nv_bfloat16* __restrict__ Hi,
    __nv_bfloat16* __restrict__ Lo)
{
    __shared__ float ssum[8], ssq[8], smv[2];
    int row = blockIdx.x;
    int tid = threadIdx.x;
    const float4* xr = (const float4*)(X + (size_t)row * EMB);
    float4 v = xr[tid];
    float s = v.x + v.y + v.z + v.w;
    float q = v.x*v.x + v.y*v.y + v.z*v.z + v.w*v.w;
#pragma unroll
    for (int o = 16; o > 0; o >>= 1) {
        s += __shfl_xor_sync(0xffffffffu, s, o);
        q += __shfl_xor_sync(0xffffffffu, q, o);
    }
    if ((tid & 31) == 0) { ssum[tid >> 5] = s; ssq[tid >> 5] = q; }
    __syncthreads();
    if (tid == 0) {
        float S = 0.f, Q = 0.f;
#pragma unroll
        for (int i = 0; i < 8; i++) { S += ssum[i]; Q += ssq[i]; }
        float mean = S * (1.f / EMB);
        float var  = Q * (1.f / EMB) - mean * mean;
        smv[0] = mean;
        smv[1] = rsqrtf(var + 1e-5f);
    }
    __syncthreads();
    float mean = smv[0], inv = smv[1];
    float4 g = ((const float4*)G)[tid];
    float4 b = ((const float4*)Bt)[tid];
    float o0 = (v.x - mean) * inv * g.x + b.x;
    float o1 = (v.y - mean) * inv * g.y + b.y;
    float o2 = (v.z - mean) * inv * g.z + b.z;
    float o3 = (v.w - mean) * inv * g.w + b.w;
    __nv_bfloat162 hi0, hi1, lo0, lo1;
    split1(o0, hi0.x, lo0.x);
    split1(o1, hi0.y, lo0.y);
    split1(o2, hi1.x, lo1.x);
    split1(o3, hi1.y, lo1.y);
    size_t i4 = (size_t)row * 256 + tid;
    ((__nv_bfloat162*)Hi)[i4 * 2]     = hi0;
    ((__nv_bfloat162*)Hi)[i4 * 2 + 1] = hi1;
    ((__nv_bfloat162*)Lo)[i4 * 2]     = lo0;
    ((__nv_bfloat162*)Lo)[i4 * 2 + 1] = lo1;
}

// ---------------------------------------------------------------------------
// mma.sync split GEMM (r10 mainloop). QOUT: route Q/K/V split outputs.
// ---------------------------------------------------------------------------
#define STAGE_BYTES 32768
#define MMA_SMEM    98304

__device__ __forceinline__ void cp16(uint32_t dst, const void* src) {
    asm volatile("cp.async.cg.shared.global [%0], [%1], 16;" :: "r"(dst), "l"(src));
}
__device__ __forceinline__ void ldm4(uint32_t* r, uint32_t addr) {
    asm volatile("ldmatrix.sync.aligned.m8n8.x4.shared.b16 {%0,%1,%2,%3}, [%4];"
                 : "=r"(r[0]), "=r"(r[1]), "=r"(r[2]), "=r"(r[3]) : "r"(addr));
}
__device__ __forceinline__ void mma16816(float* c, const uint32_t* a,
                                         uint32_t b0, uint32_t b1) {
    asm volatile(
        "mma.sync.aligned.m16n8k16.row.col.f32.bf16.bf16.f32 "
        "{%0,%1,%2,%3}, {%4,%5,%6,%7}, {%8,%9}, {%0,%1,%2,%3};"
        : "+f"(c[0]), "+f"(c[1]), "+f"(c[2]), "+f"(c[3])
        : "r"(a[0]), "r"(a[1]), "r"(a[2]), "r"(a[3]), "r"(b0), "r"(b1));
}

template<bool BIAS, bool RELU, bool RES, bool SPLITO, bool QOUT, bool HALFO>
__global__ __launch_bounds__(256, 2) void mma_gemm(
    const __nv_bfloat16* __restrict__ Ah, const __nv_bfloat16* __restrict__ Al,
    const __nv_bfloat16* __restrict__ Bh, const __nv_bfloat16* __restrict__ Bl,
    const float* __restrict__ bias, const float* __restrict__ Res,
    float* __restrict__ C, __nv_bfloat16* __restrict__ OHi,
    __nv_bfloat16* __restrict__ OLo, int M, int N, int K)
{
    extern __shared__ char smem[];
    const uint32_t sbase = smem_u32(smem);
    const int tid = threadIdx.x;
    const int wid = tid >> 5, lane = tid & 31;
    const int bm = blockIdx.y * 128, bn = blockIdx.x * 128;
    const int m0w = (wid >> 2) * 64, n0w = (wid & 3) * 32;

    const int r0 = tid >> 2,         c0 = tid & 3;
    const int r1 = (tid + 256) >> 2, c1 = (tid + 256) & 3;
    const uint32_t so0 = (uint32_t)(r0 * 64 + ((c0 ^ ((r0 >> 1) & 3)) * 16));
    const uint32_t so1 = (uint32_t)(r1 * 64 + ((c1 ^ ((r1 >> 1) & 3)) * 16));
    const size_t offA0 = (size_t)(bm + r0) * K + c0 * 8;
    const size_t offA1 = (size_t)(bm + r1) * K + c1 * 8;
    const size_t offB0 = (size_t)(bn + r0) * K + c0 * 8;
    const size_t offB1 = (size_t)(bn + r1) * K + c1 * 8;

    float acc[4][4][4];
#pragma unroll
    for (int a = 0; a < 4; a++)
#pragma unroll
        for (int n = 0; n < 4; n++)
#pragma unroll
            for (int q = 0; q < 4; q++) acc[a][n][q] = 0.f;

    const int nt = K >> 5;
    const int rowA_base = m0w + (lane & 15);
    const int rowB_base = n0w + (lane & 15);
    const int chsel = lane >> 4;

#define LOAD_STAGE(s, k0)                                                     \
    do {                                                                      \
        uint32_t d = sbase + (s) * STAGE_BYTES;                               \
        cp16(d + so0,          Ah + offA0 + (k0));                            \
        cp16(d + so1,          Ah + offA1 + (k0));                            \
        cp16(d + 8192  + so0,  Al + offA0 + (k0));                            \
        cp16(d + 8192  + so1,  Al + offA1 + (k0));                            \
        cp16(d + 16384 + so0,  Bh + offB0 + (k0));                            \
        cp16(d + 16384 + so1,  Bh + offB1 + (k0));                            \
        cp16(d + 24576 + so0,  Bl + offB0 + (k0));                            \
        cp16(d + 24576 + so1,  Bl + offB1 + (k0));                            \
    } while (0)

    LOAD_STAGE(0, 0);
    asm volatile("cp.async.commit_group;");
    if (nt > 1) LOAD_STAGE(1, 32);
    asm volatile("cp.async.commit_group;");

    int stage = 0;
    for (int i = 0; i < nt; i++) {
        asm volatile("cp.async.wait_group 1;");
        __syncthreads();

        uint32_t base = sbase + stage * STAGE_BYTES;
#pragma unroll
        for (int ks = 0; ks < 2; ks++) {
            const int chunk = ks * 2 + chsel;
            uint32_t bh[2][4], bl[2][4];
#pragma unroll
            for (int p = 0; p < 2; p++) {
                int row = rowB_base + p * 16;
                uint32_t ad = base + 16384 + (uint32_t)(row * 64 + ((chunk ^ ((row >> 1) & 3)) * 16));
                ldm4(bh[p], ad);
                ldm4(bl[p], ad + 8192);
            }
#pragma unroll
            for (int a = 0; a < 4; a++) {
                uint32_t ah[4], al[4];
                int row = rowA_base + a * 16;
                uint32_t ad = base + (uint32_t)(row * 64 + ((chunk ^ ((row >> 1) & 3)) * 16));
                ldm4(ah, ad);
                ldm4(al, ad + 8192);
#pragma unroll
                for (int n = 0; n < 4; n++) {
                    int p = n >> 1, q = n & 1;
                    mma16816(acc[a][n], ah, bh[p][q], bh[p][q + 2]);
                    mma16816(acc[a][n], ah, bl[p][q], bl[p][q + 2]);
                    mma16816(acc[a][n], al, bh[p][q], bh[p][q + 2]);
                }
            }
        }
        int nx = i + 2;
        if (nx < nt) {
            int ns = stage + 2; if (ns >= 3) ns -= 3;
            LOAD_STAGE(ns, nx << 5);
        }
        asm volatile("cp.async.commit_group;");
        if (++stage == 3) stage = 0;
    }
#undef LOAD_STAGE

    const int g = lane >> 2, t = lane & 3;
#pragma unroll
    for (int a = 0; a < 4; a++) {
#pragma unroll
        for (int n = 0; n < 4; n++) {
            int row0 = bm + m0w + a * 16 + g;
            int col  = bn + n0w + n * 8 + 2 * t;
            float v0 = acc[a][n][0], v1 = acc[a][n][1];
            float v2 = acc[a][n][2], v3 = acc[a][n][3];
            if (BIAS) {
                float b0 = bias[col], b1 = bias[col + 1];
                v0 += b0; v1 += b1; v2 += b0; v3 += b1;
            }
            if (RELU) {
                v0 = fmaxf(v0, 0.f); v1 = fmaxf(v1, 0.f);
                v2 = fmaxf(v2, 0.f); v3 = fmaxf(v3, 0.f);
            }
            if (RES) {
                const float2 q0 = *(const float2*)(Res + (size_t)row0 * N + col);
                const float2 q1 = *(const float2*)(Res + (size_t)(row0 + 8) * N + col);
                v0 += q0.x; v1 += q0.y; v2 += q1.x; v3 += q1.y;
            }
            if (SPLITO) {
                __nv_bfloat162 h0, h1, l0, l1;
                split1(v0, h0.x, l0.x); split1(v1, h0.y, l0.y);
                split1(v2, h1.x, l1.x); split1(v3, h1.y, l1.y);
                *(__nv_bfloat162*)(OHi + (size_t)row0 * N + col)       = h0;
                *(__nv_bfloat162*)(OLo + (size_t)row0 * N + col)       = l0;
                *(__nv_bfloat162*)(OHi + (size_t)(row0 + 8) * N + col) = h1;
                *(__nv_bfloat162*)(OLo + (size_t)(row0 + 8) * N + col) = l1;
            } else if (HALFO) {
                __nv_bfloat162 h0, h1;
                h0.x = __float2bfloat16(v0); h0.y = __float2bfloat16(v1);
                h1.x = __float2bfloat16(v2); h1.y = __float2bfloat16(v3);
                *(__nv_bfloat162*)(OHi + (size_t)row0 * N + col)       = h0;
                *(__nv_bfloat162*)(OHi + (size_t)(row0 + 8) * N + col) = h1;
            } else {
                float2 o0; o0.x = v0; o0.y = v1;
                float2 o1; o1.x = v2; o1.y = v3;
                *(float2*)(C + (size_t)row0 * N + col)       = o0;
                *(float2*)(C + (size_t)(row0 + 8) * N + col) = o1;
            }
            if (QOUT) {
                int hh = col / 192;
                int cc = col - hh * 192;
                __nv_bfloat162 h0, h1, l0, l1;
                split1(v0, h0.x, l0.x); split1(v1, h0.y, l0.y);
                split1(v2, h1.x, l1.x); split1(v3, h1.y, l1.y);
                int b0_ = row0 & 1, t0_ = row0 >> 1;
                int t1_ = (row0 + 8) >> 1;
                if (cc < 64) {
                    size_t q0o = ((size_t)row0 * 16 + hh) * 64 + cc;
                    size_t q1o = ((size_t)(row0 + 8) * 16 + hh) * 64 + cc;
                    *(__nv_bfloat162*)(OHi + q0o) = h0; *(__nv_bfloat162*)(OLo + q0o) = l0;
                    *(__nv_bfloat162*)(OHi + q1o) = h1; *(__nv_bfloat162*)(OLo + q1o) = l1;
                } else if (cc < 128) {
                    size_t k0o = (((size_t)(b0_ * 16 + hh)) * 4096 + t0_) * 64 + (cc - 64);
                    size_t k1o = (((size_t)(b0_ * 16 + hh)) * 4096 + t1_) * 64 + (cc - 64);
                    *(__nv_bfloat162*)(g_k_hi + k0o) = h0; *(__nv_bfloat162*)(g_k_lo + k0o) = l0;
                    *(__nv_bfloat162*)(g_k_hi + k1o) = h1; *(__nv_bfloat162*)(g_k_lo + k1o) = l1;
                } else {
                    size_t v0o = (((size_t)(b0_ * 16 + hh)) * 4096 + t0_) * 64 + (cc - 128);
                    size_t v1o = (((size_t)(b0_ * 16 + hh)) * 4096 + t1_) * 64 + (cc - 128);
                    *(__nv_bfloat162*)(g_v_hi + v0o) = h0; *(__nv_bfloat162*)(g_v_lo + v0o) = l0;
                    *(__nv_bfloat162*)(g_v_hi + v1o) = h1; *(__nv_bfloat162*)(g_v_lo + v1o) = l1;
                }
            }
        }
    }
}

// ---------------------------------------------------------------------------
// HMMA sliding-window attention. 64 queries per CTA, 9 key tiles of 64.
// S and PV via m16n8k16 (GEMM-identical fragment mappings); softmax scalar
// via smem staging. All operands split bf16 (3-term products).
// ---------------------------------------------------------------------------
#define AT_QH 0
#define AT_QL 8192
#define AT_KH 16384
#define AT_KL 24576
#define AT_VH 32768
#define AT_VL 40960
#define AT_VTH 49152
#define AT_VTL 57344
#define AT_S   65536
#define AT_PH  82944
#define AT_PL  91136
#define AT_CORR 99328
#define AT_LINV 99584
#define ATT_SMEM 99840

__global__ __launch_bounds__(256, 2) void attn_kernel(
    const __nv_bfloat16* __restrict__ Qhi, const __nv_bfloat16* __restrict__ Qlo,
    const __nv_bfloat16* __restrict__ QEb,
    __nv_bfloat16* __restrict__ OHi, __nv_bfloat16* __restrict__ OLo)
{
    extern __shared__ char smem[];
    const uint32_t sbase = smem_u32(smem);
    float* Sf    = (float*)(smem + AT_S);
    float* corrS = (float*)(smem + AT_CORR);
    float* linvS = (float*)(smem + AT_LINV);

    const int s0 = blockIdx.x * 64;
    const int gg = blockIdx.y;
    const int bh = blockIdx.z;
    const int b = bh >> 4, h = bh & 15;
    const int tid = threadIdx.x;
    const int lane = tid & 31, wid = tid >> 5;
    const int tx = tid & 15, ty = tid >> 4;
    const int tbase = gg * 512 + s0;
    const int base_key = tbase - 512;
    const int bh_ = b * 16 + h;

    const int mrow0 = (wid >> 1) * 16;
    const int ncol0 = (wid & 1) * 32;
    const int lg = lane >> 2, lt = lane & 3;

    const int cr0 = tid >> 3, cc0 = tid & 7;
    const int cr1 = (tid + 256) >> 3, cc1 = (tid + 256) & 7;

#define CPT(dstoff, srcp, stride)                                                        \
    do {                                                                                 \
        cp16(sbase + (dstoff) + cr0 * 128 + ((cc0 ^ (cr0 & 7)) * 16),                    \
             (srcp) + (size_t)cr0 * (stride) + cc0 * 8);                                 \
        cp16(sbase + (dstoff) + cr1 * 128 + ((cc1 ^ (cr1 & 7)) * 16),                    \
             (srcp) + (size_t)cr1 * (stride) + cc1 * 8);                                 \
    } while (0)

    {   // preload Q + K/V(0)
        const size_t qoff = (((size_t)tbase * 2 + b) * 16 + h) * 64;
        CPT(AT_QH, Qhi + qoff, 2048);
        CPT(AT_QL, Qlo + qoff, 2048);
        int u0 = base_key; if (u0 < 0) u0 = 0;
        const size_t koff = ((size_t)bh_ * 4096 + u0) * 64;
        CPT(AT_KH, g_k_hi + koff, 64);
        CPT(AT_KL, g_k_lo + koff, 64);
        CPT(AT_VH, g_v_hi + koff, 64);
        CPT(AT_VL, g_v_lo + koff, 64);
        asm volatile("cp.async.commit_group;");
    }

    float O[4][4];
    float mrow[4], lrow[4];
#pragma unroll
    for (int r = 0; r < 4; r++) {
        mrow[r] = -1e30f; lrow[r] = 0.f;
#pragma unroll
        for (int c = 0; c < 4; c++) O[r][c] = 0.f;
    }
    size_t qe_base[4];
#pragma unroll
    for (int r = 0; r < 4; r++) {
        int t = tbase + ty * 4 + r;
        qe_base[r] = ((size_t)(t * 2 + b) * 16 + h) * NJP;
    }

    for (int kt = 0; kt < 9; kt++) {
        asm volatile("cp.async.wait_group 0;");
        __syncthreads();

        {   // transpose V[kk][d] -> VT[d][kk] (hi and lo)
            int d0 = (tid & 15) * 4, kk0 = (tid >> 4) * 4;
#pragma unroll
            for (int tile = 0; tile < 2; tile++) {
                uint32_t inb = tile ? AT_VL : AT_VH;
                uint32_t outb = tile ? AT_VTL : AT_VTH;
                uint16_t m[4][4];
#pragma unroll
                for (int i = 0; i < 4; i++) {
                    int row = kk0 + i;
                    uint32_t off = inb + row * 128 + (((d0 >> 3) ^ (row & 7)) << 4) + ((d0 & 7) * 2);
                    uint2 v = *(uint2*)(smem + off);
                    uint16_t* pv = (uint16_t*)&v;
                    m[i][0] = pv[0]; m[i][1] = pv[1]; m[i][2] = pv[2]; m[i][3] = pv[3];
                }
#pragma unroll
                for (int j = 0; j < 4; j++) {
                    int rd = d0 + j;
                    uint32_t o2 = outb + rd * 128 + (((kk0 >> 3) ^ (rd & 7)) << 4) + ((kk0 & 7) * 2);
                    uint16_t o[4] = {m[0][j], m[1][j], m[2][j], m[3][j]};
                    *(uint2*)(smem + o2) = *(uint2*)o;
                }
            }
        }
        __syncthreads();

        // S = Q.K^T via HMMA
        float sacc[4][4];
#pragma unroll
        for (int n = 0; n < 4; n++)
#pragma unroll
            for (int q = 0; q < 4; q++) sacc[n][q] = 0.f;
#pragma unroll
        for (int ks = 0; ks < 4; ks++) {
            int chunk = 2 * ks + (lane >> 4);
            int rq = mrow0 + (lane & 15);
            uint32_t aq = sbase + AT_QH + rq * 128 + ((chunk ^ (rq & 7)) << 4);
            uint32_t qh[4], ql[4];
            ldm4(qh, aq); ldm4(ql, aq + 8192);
            uint32_t khf[2][4], klf[2][4];
#pragma unroll
            for (int p = 0; p < 2; p++) {
                int rk = ncol0 + p * 16 + (lane & 15);
                uint32_t ak = sbase + AT_KH + rk * 128 + ((chunk ^ (rk & 7)) << 4);
                ldm4(khf[p], ak); ldm4(klf[p], ak + 8192);
            }
#pragma unroll
            for (int n = 0; n < 4; n++) {
                int p = n >> 1, q = n & 1;
                mma16816(sacc[n], qh, khf[p][q], khf[p][q + 2]);
                mma16816(sacc[n], qh, klf[p][q], klf[p][q + 2]);
                mma16816(sacc[n], ql, khf[p][q], khf[p][q + 2]);
            }
        }
#pragma unroll
        for (int n = 0; n < 4; n++) {
            int si = mrow0 + lg, ck = ncol0 + n * 8 + lt * 2;
            float2 a0; a0.x = sacc[n][0]; a0.y = sacc[n][1];
            float2 a1; a1.x = sacc[n][2]; a1.y = sacc[n][3];
            *(float2*)&Sf[si * 68 + ck]       = a0;
            *(float2*)&Sf[(si + 8) * 68 + ck] = a1;
        }
        __syncthreads();

        // scalar softmax on smem S (r10 mapping)
        float acc[4][4];
#pragma unroll
        for (int r = 0; r < 4; r++) {
            float4 sv = *(const float4*)&Sf[(ty * 4 + r) * 68 + tx * 4];
            acc[r][0] = sv.x; acc[r][1] = sv.y; acc[r][2] = sv.z; acc[r][3] = sv.w;
        }
#pragma unroll
        for (int r = 0; r < 4; r++) {
            int si = ty * 4 + r;
#pragma unroll
            for (int c = 0; c < 4; c++) {
                int kk = tx * 4 + c;
                int j = kt * 64 + kk - si;
                int u = base_key + kt * 64 + kk;
                if (j >= 0 && j <= 512 && u >= 0)
                    acc[r][c] = (acc[r][c] + __bfloat162float(QEb[qe_base[r] + j])) * 0.125f;
                else
                    acc[r][c] = -1e30f;
            }
        }
        float corr[4];
#pragma unroll
        for (int r = 0; r < 4; r++) {
            float tm = fmaxf(fmaxf(acc[r][0], acc[r][1]), fmaxf(acc[r][2], acc[r][3]));
#pragma unroll
            for (int o = 1; o < 16; o <<= 1)
                tm = fmaxf(tm, __shfl_xor_sync(0xffffffffu, tm, o));
            float mnew = fmaxf(mrow[r], tm);
            corr[r] = __expf(mrow[r] - mnew);
            float rs = 0.f;
#pragma unroll
            for (int c = 0; c < 4; c++) {
                float p = (acc[r][c] > -5e29f) ? __expf(acc[r][c] - mnew) : 0.f;
                acc[r][c] = p;
                rs += p;
            }
#pragma unroll
            for (int o = 1; o < 16; o <<= 1)
                rs += __shfl_xor_sync(0xffffffffu, rs, o);
            lrow[r] = lrow[r] * corr[r] + rs;
            mrow[r] = mnew;
        }
        // write P split bf16 (swizzled rows) + corr
#pragma unroll
        for (int r = 0; r < 4; r++) {
            int si = ty * 4 + r;
            uint32_t poff = si * 128 + ((((tx >> 1) ^ (si & 7))) << 4) + ((tx & 1) * 8);
            uint16_t hs[4], ls[4];
#pragma unroll
            for (int c = 0; c < 4; c++) {
                __nv_bfloat16 hh_, ll_;
                split1(acc[r][c], hh_, ll_);
                hs[c] = *(uint16_t*)&hh_;
                ls[c] = *(uint16_t*)&ll_;
            }
            *(uint2*)(smem + AT_PH + poff) = *(uint2*)hs;
            *(uint2*)(smem + AT_PL + poff) = *(uint2*)ls;
        }
        if (tx == 0) {
#pragma unroll
            for (int r = 0; r < 4; r++) corrS[ty * 4 + r] = corr[r];
        }
        __syncthreads();

        // prefetch next K/V (overlaps PV)
        if (kt < 8) {
            int u0 = base_key + (kt + 1) * 64; if (u0 < 0) u0 = 0;
            const size_t koff = ((size_t)bh_ * 4096 + u0) * 64;
            CPT(AT_KH, g_k_hi + koff, 64);
            CPT(AT_KL, g_k_lo + koff, 64);
            CPT(AT_VH, g_v_hi + koff, 64);
            CPT(AT_VL, g_v_lo + koff, 64);
        }
        asm volatile("cp.async.commit_group;");

        // O = O*corr + P.V via HMMA
        float cA = corrS[mrow0 + lg], cB = corrS[mrow0 + lg + 8];
#pragma unroll
        for (int n = 0; n < 4; n++) {
            O[n][0] *= cA; O[n][1] *= cA; O[n][2] *= cB; O[n][3] *= cB;
        }
#pragma unroll
        for (int ks = 0; ks < 4; ks++) {
            int chunk = 2 * ks + (lane >> 4);
            int rp = mrow0 + (lane & 15);
            uint32_t ap = sbase + AT_PH + rp * 128 + ((chunk ^ (rp & 7)) << 4);
            uint32_t ph[4], pl[4];
            ldm4(ph, ap); ldm4(pl, ap + 8192);
            uint32_t vhf[2][4], vlf[2][4];
#pragma unroll
            for (int p = 0; p < 2; p++) {
                int rv = ncol0 + p * 16 + (lane & 15);
                uint32_t av = sbase + AT_VTH + rv * 128 + ((chunk ^ (rv & 7)) << 4);
                ldm4(vhf[p], av); ldm4(vlf[p], av + 8192);
            }
#pragma unroll
            for (int n = 0; n < 4; n++) {
                int p = n >> 1, q = n & 1;
                mma16816(O[n], ph, vhf[p][q], vhf[p][q + 2]);
                mma16816(O[n], ph, vlf[p][q], vlf[p][q + 2]);
                mma16816(O[n], pl, vhf[p][q], vhf[p][q + 2]);
            }
        }
    }
#undef CPT

    if (tx == 0) {
#pragma unroll
        for (int r = 0; r < 4; r++) linvS[ty * 4 + r] = 1.f / lrow[r];
    }
    __syncthreads();
    float li0 = linvS[mrow0 + lg], li1 = linvS[mrow0 + lg + 8];
#pragma unroll
    for (int n = 0; n < 4; n++) {
        int si = mrow0 + lg, d = ncol0 + n * 8 + lt * 2;
        int t0 = tbase + si, t1 = t0 + 8;
        size_t o0 = ((size_t)(t0 * 2 + b)) * 1024 + h * 64 + d;
        size_t o1 = ((size_t)(t1 * 2 + b)) * 1024 + h * 64 + d;
        __nv_bfloat162 h0, h1, l0, l1;
        split1(O[n][0] * li0, h0.x, l0.x);
        split1(O[n][1] * li0, h0.y, l0.y);
        split1(O[n][2] * li1, h1.x, l1.x);
        split1(O[n][3] * li1, h1.y, l1.y);
        *(__nv_bfloat162*)(OHi + o0) = h0;
        *(__nv_bfloat162*)(OLo + o0) = l0;
        *(__nv_bfloat162*)(OHi + o1) = h1;
        *(__nv_bfloat162*)(OLo + o1) = l1;
    }
}

// ---------------------------------------------------------------------------
__global__ __launch_bounds__(256) void nxt_kernel(
    const float* __restrict__ QKVm, float* __restrict__ NXT)
{
    int idx = blockIdx.x * 256 + threadIdx.x;
    int c  = idx & 127;
    int bh = (idx >> 7) & 31;
    int s  = idx >> 12;
    int b = bh >> 4, h = bh & 15;
    int t = 3584 + s;
    NXT[idx] = QKVm[(size_t)(t * 2 + b) * QKV_N + h * 192 + 64 + c];
}

// ---------------------------------------------------------------------------
extern "C" void kernel_launch(void* const* d_in, const int* in_sizes, int n_in,
                              void* d_out, int out_size)
{
    const float* x      = (const float*)d_in[0];
    const float* ln1_g  = (const float*)d_in[1];
    const float* ln1_b  = (const float*)d_in[2];
    const float* qkv_w  = (const float*)d_in[3];
    const float* qkv_b  = (const float*)d_in[4];
    const float* pos_emb= (const float*)d_in[5];
    const float* out_w  = (const float*)d_in[6];
    const float* ln2_g  = (const float*)d_in[7];
    const float* ln2_b  = (const float*)d_in[8];
    const float* fc1_w  = (const float*)d_in[9];
    const float* fc1_b  = (const float*)d_in[10];
    const float* fc2_w  = (const float*)d_in[11];
    const float* fc2_b  = (const float*)d_in[12];
    float* out = (float*)d_out;

    float* scratch = 0;
    cudaGetSymbolAddress((void**)&scratch, g_scratch);
    __nv_bfloat16 *Ahi, *Alo, *A2hi, *A2lo, *Whi, *Wlo, *PThi, *PTlo;
    cudaGetSymbolAddress((void**)&Ahi, g_act_hi);
    cudaGetSymbolAddress((void**)&Alo, g_act_lo);
    cudaGetSymbolAddress((void**)&A2hi, g_act2_hi);
    cudaGetSymbolAddress((void**)&A2lo, g_act2_lo);
    cudaGetSymbolAddress((void**)&Whi, g_w_hi);
    cudaGetSymbolAddress((void**)&Wlo, g_w_lo);
    cudaGetSymbolAddress((void**)&PThi, g_pet_hi);
    cudaGetSymbolAddress((void**)&PTlo, g_pet_lo);

    float* OUT1 = scratch + OFF_OUT1;
    float* QKVm = scratch + OFF_QKV;
    __nv_bfloat16* QEb = (__nv_bfloat16*)(scratch + OFF_QE);

    cudaFuncSetAttribute(mma_gemm<true, false, false, false, true, false>,  cudaFuncAttributeMaxDynamicSharedMemorySize, MMA_SMEM);
    cudaFuncSetAttribute(mma_gemm<false, false, false, false, false, true>, cudaFuncAttributeMaxDynamicSharedMemorySize, MMA_SMEM);
    cudaFuncSetAttribute(mma_gemm<false, false, true, false, false, false>, cudaFuncAttributeMaxDynamicSharedMemorySize, MMA_SMEM);
    cudaFuncSetAttribute(mma_gemm<true, true, false, true, false, false>,   cudaFuncAttributeMaxDynamicSharedMemorySize, MMA_SMEM);
    cudaFuncSetAttribute(mma_gemm<true, false, true, false, false, false>,  cudaFuncAttributeMaxDynamicSharedMemorySize, MMA_SMEM);
    cudaFuncSetAttribute(attn_kernel, cudaFuncAttributeMaxDynamicSharedMemorySize, ATT_SMEM);

    // 0. pe^T split
    pe_split_t_kernel<<<160, 256>>>(pos_emb, PThi, PTlo);
    // 1. LN1 + split
    ln_split_kernel<<<NROWS, 256>>>(x, ln1_g, ln1_b, Ahi, Alo);
    // 2. QKV GEMM (fp32 out) + Q/K/V split side-outputs
    split_kernel<<<(QKV_N * EMB) / 1024, 256>>>(qkv_w, Whi, Wlo);
    mma_gemm<true, false, false, false, true, false><<<dim3(QKV_N / 128, NROWS / 128), 256, MMA_SMEM>>>(
        Ahi, Alo, Whi, Wlo, qkv_b, 0, QKVm, A2hi, A2lo, NROWS, QKV_N, EMB);
    // 3. QE = Qsplit @ peT^T -> bf16
    mma_gemm<false, false, false, false, false, true><<<dim3(NJP / 128, 131072 / 128), 256, MMA_SMEM>>>(
        A2hi, A2lo, PThi, PTlo, 0, 0, 0, QEb, 0, 131072, NJP, 64);
    // 4. HMMA attention -> act split
    attn_kernel<<<dim3(8, 8, 32), 256, ATT_SMEM>>>(A2hi, A2lo, QEb, Ahi, Alo);
    // 5. OUT1 = AV @ out_w^T + x
    split_kernel<<<(EMB * EMB) / 1024, 256>>>(out_w, Whi, Wlo);
    mma_gemm<false, false, true, false, false, false><<<dim3(EMB / 128, NROWS / 128), 256, MMA_SMEM>>>(
        Ahi, Alo, Whi, Wlo, 0, x, OUT1, 0, 0, NROWS, EMB, EMB);
    // 6. LN2 + split
    ln_split_kernel<<<NROWS, 256>>>(OUT1, ln2_g, ln2_b, Ahi, Alo);
    // 7. act2 = split(relu(H2 @ fc1_w^T + fc1_b))
    split_kernel<<<(FFN_I * EMB) / 1024, 256>>>(fc1_w, Whi, Wlo);
    mma_gemm<true, true, false, true, false, false><<<dim3(FFN_I / 128, NROWS / 128), 256, MMA_SMEM>>>(
        Ahi, Alo, Whi, Wlo, fc1_b, 0, 0, A2hi, A2lo, NROWS, FFN_I, EMB);
    // 8. out = FF1 @ fc2_w^T + fc2_b + OUT1
    split_kernel<<<(EMB * FFN_I) / 1024, 256>>>(fc2_w, Whi, Wlo);
    mma_gemm<true, false, true, false, false, false><<<dim3(EMB / 128, NROWS / 128), 256, MMA_SMEM>>>(
        A2hi, A2lo, Whi, Wlo, fc2_b, OUT1, out, 0, 0, NROWS, EMB, FFN_I);
    // 9. nxt slice
    nxt_kernel<<<2097152 / 256, 256>>>(QKVm, out + 8388608);
}

// round 12
// speedup vs baseline: 1.1560x; 1.0100x over previous
#include <cuda_runtime.h>
#include <cuda_bf16.h>
#include <math.h>
#include <stdint.h>

// ---------------------------------------------------------------------------
// Shapes: x (T=4096, B=2, E=1024); H=16 heads, dk=dv=64; window 512 (513 rel pos)
// QE: bf16 [r = (t*2+b)*16+h][j], row stride 640 (cols 513..639 pad)
// Qsplit: bf16 [(t*2+b)*16+h][64];  Ksplit/Vsplit: bf16 [(b*16+h)][t][64]
// nxt (d_out+8388608): fp32 [s][b*16+h][128] = k,v of t=3584+s (written by QKV GEMM)
// ---------------------------------------------------------------------------
#define NROWS 8192
#define EMB   1024
#define QKV_N 3072
#define FFN_I 4096
#define NJ    513
#define NJP   640

#define OFF_OUT1   16777216ull
#define OFF_QE     92274688ull
#define SCRATCH_FLOATS 176160768ull

__device__ float g_scratch[SCRATCH_FLOATS];

__device__ __nv_bfloat16 g_act_hi[8388608];
__device__ __nv_bfloat16 g_act_lo[8388608];
__device__ __nv_bfloat16 g_act2_hi[33554432];   // fc1 out; Qsplit earlier
__device__ __nv_bfloat16 g_act2_lo[33554432];
__device__ __nv_bfloat16 g_w_hi[4194304];
__device__ __nv_bfloat16 g_w_lo[4194304];
__device__ __nv_bfloat16 g_pet_hi[40960];
__device__ __nv_bfloat16 g_pet_lo[40960];
__device__ __nv_bfloat16 g_k_hi[8388608];
__device__ __nv_bfloat16 g_k_lo[8388608];
__device__ __nv_bfloat16 g_v_hi[8388608];
__device__ __nv_bfloat16 g_v_lo[8388608];

__device__ __forceinline__ uint32_t smem_u32(const void* p) {
    uint32_t a;
    asm("{ .reg .u64 t; cvta.to.shared.u64 t, %1; cvt.u32.u64 %0, t; }" : "=r"(a) : "l"(p));
    return a;
}
__device__ __forceinline__ void split1(float v, __nv_bfloat16& h, __nv_bfloat16& l) {
    h = __float2bfloat16(v);
    l = __float2bfloat16(v - __bfloat162float(h));
}

// ---------------------------------------------------------------------------
__global__ __launch_bounds__(256) void split_kernel(
    const float* __restrict__ X, __nv_bfloat16* __restrict__ Hi,
    __nv_bfloat16* __restrict__ Lo)
{
    int i4 = blockIdx.x * 256 + threadIdx.x;
    float4 v = ((const float4*)X)[i4];
    __nv_bfloat162 hi0, hi1, lo0, lo1;
    split1(v.x, hi0.x, lo0.x);
    split1(v.y, hi0.y, lo0.y);
    split1(v.z, hi1.x, lo1.x);
    split1(v.w, hi1.y, lo1.y);
    ((__nv_bfloat162*)Hi)[i4 * 2]     = hi0;
    ((__nv_bfloat162*)Hi)[i4 * 2 + 1] = hi1;
    ((__nv_bfloat162*)Lo)[i4 * 2]     = lo0;
    ((__nv_bfloat162*)Lo)[i4 * 2 + 1] = lo1;
}

__global__ __launch_bounds__(256) void pe_split_t_kernel(
    const float* __restrict__ pe, __nv_bfloat16* __restrict__ Hi,
    __nv_bfloat16* __restrict__ Lo)
{
    int idx = blockIdx.x * 256 + threadIdx.x;
    int k = idx & 63;
    int j = idx >> 6;
    float v = (j < NJ) ? pe[(size_t)k * NJ + j] : 0.f;
    __nv_bfloat16 h, l;
    split1(v, h, l);
    Hi[idx] = h;
    Lo[idx] = l;
}

__global__ __launch_bounds__(256) void ln_split_kernel(
    const float* __restrict__ X, const float* __restrict__ G,
    const float* __restrict__ Bt, __nv_bfloat16* __restrict__ Hi,
    __nv_bfloat16* __restrict__ Lo)
{
    __shared__ float ssum[8], ssq[8], smv[2];
    int row = blockIdx.x;
    int tid = threadIdx.x;
    const float4* xr = (const float4*)(X + (size_t)row * EMB);
    float4 v = xr[tid];
    float s = v.x + v.y + v.z + v.w;
    float q = v.x*v.x + v.y*v.y + v.z*v.z + v.w*v.w;
#pragma unroll
    for (int o = 16; o > 0; o >>= 1) {
        s += __shfl_xor_sync(0xffffffffu, s, o);
        q += __shfl_xor_sync(0xffffffffu, q, o);
    }
    if ((tid & 31) == 0) { ssum[tid >> 5] = s; ssq[tid >> 5] = q; }
    __syncthreads();
    if (tid == 0) {
        float S = 0.f, Q = 0.f;
#pragma unroll
        for (int i = 0; i < 8; i++) { S += ssum[i]; Q += ssq[i]; }
        float mean = S * (1.f / EMB);
        float var  = Q * (1.f / EMB) - mean * mean;
        smv[0] = mean;
        smv[1] = rsqrtf(var + 1e-5f);
    }
    __syncthreads();
    float mean = smv[0], inv = smv[1];
    float4 g = ((const float4*)G)[tid];
    float4 b = ((const float4*)Bt)[tid];
    float o0 = (v.x - mean) * inv * g.x + b.x;
    float o1 = (v.y - mean) * inv * g.y + b.y;
    float o2 = (v.z - mean) * inv * g.z + b.z;
    float o3 = (v.w - mean) * inv * g.w + b.w;
    __nv_bfloat162 hi0, hi1, lo0, lo1;
    split1(o0, hi0.x, lo0.x);
    split1(o1, hi0.y, lo0.y);
    split1(o2, hi1.x, lo1.x);
    split1(o3, hi1.y, lo1.y);
    size_t i4 = (size_t)row * 256 + tid;
    ((__nv_bfloat162*)Hi)[i4 * 2]     = hi0;
    ((__nv_bfloat162*)Hi)[i4 * 2 + 1] = hi1;
    ((__nv_bfloat162*)Lo)[i4 * 2]     = lo0;
    ((__nv_bfloat162*)Lo)[i4 * 2 + 1] = lo1;
}

// ---------------------------------------------------------------------------
// mma.sync split GEMM. QOUT: route Q/K/V split side-outputs.
// NXTO: no fp32 C tile store; write nxt slice (t>=3584, kv cols) fp32 to C.
// ---------------------------------------------------------------------------
#define STAGE_BYTES 32768
#define MMA_SMEM    98304

__device__ __forceinline__ void cp16(uint32_t dst, const void* src) {
    asm volatile("cp.async.cg.shared.global [%0], [%1], 16;" :: "r"(dst), "l"(src));
}
__device__ __forceinline__ void ldm4(uint32_t* r, uint32_t addr) {
    asm volatile("ldmatrix.sync.aligned.m8n8.x4.shared.b16 {%0,%1,%2,%3}, [%4];"
                 : "=r"(r[0]), "=r"(r[1]), "=r"(r[2]), "=r"(r[3]) : "r"(addr));
}
__device__ __forceinline__ void mma16816(float* c, const uint32_t* a,
                                         uint32_t b0, uint32_t b1) {
    asm volatile(
        "mma.sync.aligned.m16n8k16.row.col.f32.bf16.bf16.f32 "
        "{%0,%1,%2,%3}, {%4,%5,%6,%7}, {%8,%9}, {%0,%1,%2,%3};"
        : "+f"(c[0]), "+f"(c[1]), "+f"(c[2]), "+f"(c[3])
        : "r"(a[0]), "r"(a[1]), "r"(a[2]), "r"(a[3]), "r"(b0), "r"(b1));
}

template<bool BIAS, bool RELU, bool RES, bool SPLITO, bool QOUT, bool HALFO, bool NXTO>
__global__ __launch_bounds__(256, 2) void mma_gemm(
    const __nv_bfloat16* __restrict__ Ah, const __nv_bfloat16* __restrict__ Al,
    const __nv_bfloat16* __restrict__ Bh, const __nv_bfloat16* __restrict__ Bl,
    const float* __restrict__ bias, const float* __restrict__ Res,
    float* __restrict__ C, __nv_bfloat16* __restrict__ OHi,
    __nv_bfloat16* __restrict__ OLo, int M, int N, int K)
{
    extern __shared__ char smem[];
    const uint32_t sbase = smem_u32(smem);
    const int tid = threadIdx.x;
    const int wid = tid >> 5, lane = tid & 31;
    const int bm = blockIdx.y * 128, bn = blockIdx.x * 128;
    const int m0w = (wid >> 2) * 64, n0w = (wid & 3) * 32;

    const int r0 = tid >> 2,         c0 = tid & 3;
    const int r1 = (tid + 256) >> 2, c1 = (tid + 256) & 3;
    const uint32_t so0 = (uint32_t)(r0 * 64 + ((c0 ^ ((r0 >> 1) & 3)) * 16));
    const uint32_t so1 = (uint32_t)(r1 * 64 + ((c1 ^ ((r1 >> 1) & 3)) * 16));
    const size_t offA0 = (size_t)(bm + r0) * K + c0 * 8;
    const size_t offA1 = (size_t)(bm + r1) * K + c1 * 8;
    const size_t offB0 = (size_t)(bn + r0) * K + c0 * 8;
    const size_t offB1 = (size_t)(bn + r1) * K + c1 * 8;

    float acc[4][4][4];
#pragma unroll
    for (int a = 0; a < 4; a++)
#pragma unroll
        for (int n = 0; n < 4; n++)
#pragma unroll
            for (int q = 0; q < 4; q++) acc[a][n][q] = 0.f;

    const int nt = K >> 5;
    const int rowA_base = m0w + (lane & 15);
    const int rowB_base = n0w + (lane & 15);
    const int chsel = lane >> 4;

#define LOAD_STAGE(s, k0)                                                     \
    do {                                                                      \
        uint32_t d = sbase + (s) * STAGE_BYTES;                               \
        cp16(d + so0,          Ah + offA0 + (k0));                            \
        cp16(d + so1,          Ah + offA1 + (k0));                            \
        cp16(d + 8192  + so0,  Al + offA0 + (k0));                            \
        cp16(d + 8192  + so1,  Al + offA1 + (k0));                            \
        cp16(d + 16384 + so0,  Bh + offB0 + (k0));                            \
        cp16(d + 16384 + so1,  Bh + offB1 + (k0));                            \
        cp16(d + 24576 + so0,  Bl + offB0 + (k0));                            \
        cp16(d + 24576 + so1,  Bl + offB1 + (k0));                            \
    } while (0)

    LOAD_STAGE(0, 0);
    asm volatile("cp.async.commit_group;");
    if (nt > 1) LOAD_STAGE(1, 32);
    asm volatile("cp.async.commit_group;");

    int stage = 0;
    for (int i = 0; i < nt; i++) {
        asm volatile("cp.async.wait_group 1;");
        __syncthreads();

        uint32_t base = sbase + stage * STAGE_BYTES;
#pragma unroll
        for (int ks = 0; ks < 2; ks++) {
            const int chunk = ks * 2 + chsel;
            uint32_t bh[2][4], bl[2][4];
#pragma unroll
            for (int p = 0; p < 2; p++) {
                int row = rowB_base + p * 16;
                uint32_t ad = base + 16384 + (uint32_t)(row * 64 + ((chunk ^ ((row >> 1) & 3)) * 16));
                ldm4(bh[p], ad);
                ldm4(bl[p], ad + 8192);
            }
#pragma unroll
            for (int a = 0; a < 4; a++) {
                uint32_t ah[4], al[4];
                int row = rowA_base + a * 16;
                uint32_t ad = base + (uint32_t)(row * 64 + ((chunk ^ ((row >> 1) & 3)) * 16));
                ldm4(ah, ad);
                ldm4(al, ad + 8192);
#pragma unroll
                for (int n = 0; n < 4; n++) {
                    int p = n >> 1, q = n & 1;
                    mma16816(acc[a][n], ah, bh[p][q], bh[p][q + 2]);
                    mma16816(acc[a][n], ah, bl[p][q], bl[p][q + 2]);
                    mma16816(acc[a][n], al, bh[p][q], bh[p][q + 2]);
                }
            }
        }
        int nx = i + 2;
        if (nx < nt) {
            int ns = stage + 2; if (ns >= 3) ns -= 3;
            LOAD_STAGE(ns, nx << 5);
        }
        asm volatile("cp.async.commit_group;");
        if (++stage == 3) stage = 0;
    }
#undef LOAD_STAGE

    const int g = lane >> 2, t = lane & 3;
#pragma unroll
    for (int a = 0; a < 4; a++) {
#pragma unroll
        for (int n = 0; n < 4; n++) {
            int row0 = bm + m0w + a * 16 + g;
            int col  = bn + n0w + n * 8 + 2 * t;
            float v0 = acc[a][n][0], v1 = acc[a][n][1];
            float v2 = acc[a][n][2], v3 = acc[a][n][3];
            if (BIAS) {
                float b0 = bias[col], b1 = bias[col + 1];
                v0 += b0; v1 += b1; v2 += b0; v3 += b1;
            }
            if (RELU) {
                v0 = fmaxf(v0, 0.f); v1 = fmaxf(v1, 0.f);
                v2 = fmaxf(v2, 0.f); v3 = fmaxf(v3, 0.f);
            }
            if (RES) {
                const float2 q0 = *(const float2*)(Res + (size_t)row0 * N + col);
                const float2 q1 = *(const float2*)(Res + (size_t)(row0 + 8) * N + col);
                v0 += q0.x; v1 += q0.y; v2 += q1.x; v3 += q1.y;
            }
            if (SPLITO) {
                __nv_bfloat162 h0, h1, l0, l1;
                split1(v0, h0.x, l0.x); split1(v1, h0.y, l0.y);
                split1(v2, h1.x, l1.x); split1(v3, h1.y, l1.y);
                *(__nv_bfloat162*)(OHi + (size_t)row0 * N + col)       = h0;
                *(__nv_bfloat162*)(OLo + (size_t)row0 * N + col)       = l0;
                *(__nv_bfloat162*)(OHi + (size_t)(row0 + 8) * N + col) = h1;
                *(__nv_bfloat162*)(OLo + (size_t)(row0 + 8) * N + col) = l1;
            } else if (HALFO) {
                __nv_bfloat162 h0, h1;
                h0.x = __float2bfloat16(v0); h0.y = __float2bfloat16(v1);
                h1.x = __float2bfloat16(v2); h1.y = __float2bfloat16(v3);
                *(__nv_bfloat162*)(OHi + (size_t)row0 * N + col)       = h0;
                *(__nv_bfloat162*)(OHi + (size_t)(row0 + 8) * N + col) = h1;
            } else if (!NXTO) {
                float2 o0; o0.x = v0; o0.y = v1;
                float2 o1; o1.x = v2; o1.y = v3;
                *(float2*)(C + (size_t)row0 * N + col)       = o0;
                *(float2*)(C + (size_t)(row0 + 8) * N + col) = o1;
            }
            if (QOUT) {
                int hh = col / 192;
                int cc = col - hh * 192;
                __nv_bfloat162 h0, h1, l0, l1;
                split1(v0, h0.x, l0.x); split1(v1, h0.y, l0.y);
                split1(v2, h1.x, l1.x); split1(v3, h1.y, l1.y);
                int b0_ = row0 & 1, t0_ = row0 >> 1;
                int t1_ = (row0 + 8) >> 1;
                if (cc < 64) {
                    size_t q0o = ((size_t)row0 * 16 + hh) * 64 + cc;
                    size_t q1o = ((size_t)(row0 + 8) * 16 + hh) * 64 + cc;
                    *(__nv_bfloat162*)(OHi + q0o) = h0; *(__nv_bfloat162*)(OLo + q0o) = l0;
                    *(__nv_bfloat162*)(OHi + q1o) = h1; *(__nv_bfloat162*)(OLo + q1o) = l1;
                } else if (cc < 128) {
                    size_t k0o = (((size_t)(b0_ * 16 + hh)) * 4096 + t0_) * 64 + (cc - 64);
                    size_t k1o = (((size_t)(b0_ * 16 + hh)) * 4096 + t1_) * 64 + (cc - 64);
                    *(__nv_bfloat162*)(g_k_hi + k0o) = h0; *(__nv_bfloat162*)(g_k_lo + k0o) = l0;
                    *(__nv_bfloat162*)(g_k_hi + k1o) = h1; *(__nv_bfloat162*)(g_k_lo + k1o) = l1;
                } else {
                    size_t v0o = (((size_t)(b0_ * 16 + hh)) * 4096 + t0_) * 64 + (cc - 128);
                    size_t v1o = (((size_t)(b0_ * 16 + hh)) * 4096 + t1_) * 64 + (cc - 128);
                    *(__nv_bfloat162*)(g_v_hi + v0o) = h0; *(__nv_bfloat162*)(g_v_lo + v0o) = l0;
                    *(__nv_bfloat162*)(g_v_hi + v1o) = h1; *(__nv_bfloat162*)(g_v_lo + v1o) = l1;
                }
                if (NXTO && cc >= 64) {
                    // nxt[s][b*16+h][c] fp32, s=t-3584, c=cc-64 in [0,128)
                    if (t0_ >= 3584) {
                        size_t o = (((size_t)(t0_ - 3584) * 32) + b0_ * 16 + hh) * 128 + (cc - 64);
                        float2 w; w.x = v0; w.y = v1;
                        *(float2*)(C + o) = w;
                    }
                    if (t1_ >= 3584) {
                        size_t o = (((size_t)(t1_ - 3584) * 32) + b0_ * 16 + hh) * 128 + (cc - 64);
                        float2 w; w.x = v2; w.y = v3;
                        *(float2*)(C + o) = w;
                    }
                }
            }
        }
    }
}

// ---------------------------------------------------------------------------
// HMMA sliding-window attention (r11, unchanged — proven)
// ---------------------------------------------------------------------------
#define AT_QH 0
#define AT_QL 8192
#define AT_KH 16384
#define AT_KL 24576
#define AT_VH 32768
#define AT_VL 40960
#define AT_VTH 49152
#define AT_VTL 57344
#define AT_S   65536
#define AT_PH  82944
#define AT_PL  91136
#define AT_CORR 99328
#define AT_LINV 99584
#define ATT_SMEM 99840

__global__ __launch_bounds__(256, 2) void attn_kernel(
    const __nv_bfloat16* __restrict__ Qhi, const __nv_bfloat16* __restrict__ Qlo,
    const __nv_bfloat16* __restrict__ QEb,
    __nv_bfloat16* __restrict__ OHi, __nv_bfloat16* __restrict__ OLo)
{
    extern __shared__ char smem[];
    const uint32_t sbase = smem_u32(smem);
    float* Sf    = (float*)(smem + AT_S);
    float* corrS = (float*)(smem + AT_CORR);
    float* linvS = (float*)(smem + AT_LINV);

    const int s0 = blockIdx.x * 64;
    const int gg = blockIdx.y;
    const int bh = blockIdx.z;
    const int b = bh >> 4, h = bh & 15;
    const int tid = threadIdx.x;
    const int lane = tid & 31, wid = tid >> 5;
    const int tx = tid & 15, ty = tid >> 4;
    const int tbase = gg * 512 + s0;
    const int base_key = tbase - 512;
    const int bh_ = b * 16 + h;

    const int mrow0 = (wid >> 1) * 16;
    const int ncol0 = (wid & 1) * 32;
    const int lg = lane >> 2, lt = lane & 3;

    const int cr0 = tid >> 3, cc0 = tid & 7;
    const int cr1 = (tid + 256) >> 3, cc1 = (tid + 256) & 7;

#define CPT(dstoff, srcp, stride)                                                        \
    do {                                                                                 \
        cp16(sbase + (dstoff) + cr0 * 128 + ((cc0 ^ (cr0 & 7)) * 16),                    \
             (srcp) + (size_t)cr0 * (stride) + cc0 * 8);                                 \
        cp16(sbase + (dstoff) + cr1 * 128 + ((cc1 ^ (cr1 & 7)) * 16),                    \
             (srcp) + (size_t)cr1 * (stride) + cc1 * 8);                                 \
    } while (0)

    {   // preload Q + K/V(0)
        const size_t qoff = (((size_t)tbase * 2 + b) * 16 + h) * 64;
        CPT(AT_QH, Qhi + qoff, 2048);
        CPT(AT_QL, Qlo + qoff, 2048);
        int u0 = base_key; if (u0 < 0) u0 = 0;
        const size_t koff = ((size_t)bh_ * 4096 + u0) * 64;
        CPT(AT_KH, g_k_hi + koff, 64);
        CPT(AT_KL, g_k_lo + koff, 64);
        CPT(AT_VH, g_v_hi + koff, 64);
        CPT(AT_VL, g_v_lo + koff, 64);
        asm volatile("cp.async.commit_group;");
    }

    float O[4][4];
    float mrow[4], lrow[4];
#pragma unroll
    for (int r = 0; r < 4; r++) {
        mrow[r] = -1e30f; lrow[r] = 0.f;
#pragma unroll
        for (int c = 0; c < 4; c++) O[r][c] = 0.f;
    }
    size_t qe_base[4];
#pragma unroll
    for (int r = 0; r < 4; r++) {
        int t = tbase + ty * 4 + r;
        qe_base[r] = ((size_t)(t * 2 + b) * 16 + h) * NJP;
    }

    for (int kt = 0; kt < 9; kt++) {
        asm volatile("cp.async.wait_group 0;");
        __syncthreads();

        {   // transpose V[kk][d] -> VT[d][kk]
            int d0 = (tid & 15) * 4, kk0 = (tid >> 4) * 4;
#pragma unroll
            for (int tile = 0; tile < 2; tile++) {
                uint32_t inb = tile ? AT_VL : AT_VH;
                uint32_t outb = tile ? AT_VTL : AT_VTH;
                uint16_t m[4][4];
#pragma unroll
                for (int i = 0; i < 4; i++) {
                    int row = kk0 + i;
                    uint32_t off = inb + row * 128 + (((d0 >> 3) ^ (row & 7)) << 4) + ((d0 & 7) * 2);
                    uint2 v = *(uint2*)(smem + off);
                    uint16_t* pv = (uint16_t*)&v;
                    m[i][0] = pv[0]; m[i][1] = pv[1]; m[i][2] = pv[2]; m[i][3] = pv[3];
                }
#pragma unroll
                for (int j = 0; j < 4; j++) {
                    int rd = d0 + j;
                    uint32_t o2 = outb + rd * 128 + (((kk0 >> 3) ^ (rd & 7)) << 4) + ((kk0 & 7) * 2);
                    uint16_t o[4] = {m[0][j], m[1][j], m[2][j], m[3][j]};
                    *(uint2*)(smem + o2) = *(uint2*)o;
                }
            }
        }
        __syncthreads();

        // S = Q.K^T via HMMA
        float sacc[4][4];
#pragma unroll
        for (int n = 0; n < 4; n++)
#pragma unroll
            for (int q = 0; q < 4; q++) sacc[n][q] = 0.f;
#pragma unroll
        for (int ks = 0; ks < 4; ks++) {
            int chunk = 2 * ks + (lane >> 4);
            int rq = mrow0 + (lane & 15);
            uint32_t aq = sbase + AT_QH + rq * 128 + ((chunk ^ (rq & 7)) << 4);
            uint32_t qh[4], ql[4];
            ldm4(qh, aq); ldm4(ql, aq + 8192);
            uint32_t khf[2][4], klf[2][4];
#pragma unroll
            for (int p = 0; p < 2; p++) {
                int rk = ncol0 + p * 16 + (lane & 15);
                uint32_t ak = sbase + AT_KH + rk * 128 + ((chunk ^ (rk & 7)) << 4);
                ldm4(khf[p], ak); ldm4(klf[p], ak + 8192);
            }
#pragma unroll
            for (int n = 0; n < 4; n++) {
                int p = n >> 1, q = n & 1;
                mma16816(sacc[n], qh, khf[p][q], khf[p][q + 2]);
                mma16816(sacc[n], qh, klf[p][q], klf[p][q + 2]);
                mma16816(sacc[n], ql, khf[p][q], khf[p][q + 2]);
            }
        }
#pragma unroll
        for (int n = 0; n < 4; n++) {
            int si = mrow0 + lg, ck = ncol0 + n * 8 + lt * 2;
            float2 a0; a0.x = sacc[n][0]; a0.y = sacc[n][1];
            float2 a1; a1.x = sacc[n][2]; a1.y = sacc[n][3];
            *(float2*)&Sf[si * 68 + ck]       = a0;
            *(float2*)&Sf[(si + 8) * 68 + ck] = a1;
        }
        __syncthreads();

        // scalar softmax on smem S
        float acc[4][4];
#pragma unroll
        for (int r = 0; r < 4; r++) {
            float4 sv = *(const float4*)&Sf[(ty * 4 + r) * 68 + tx * 4];
            acc[r][0] = sv.x; acc[r][1] = sv.y; acc[r][2] = sv.z; acc[r][3] = sv.w;
        }
#pragma unroll
        for (int r = 0; r < 4; r++) {
            int si = ty * 4 + r;
#pragma unroll
            for (int c = 0; c < 4; c++) {
                int kk = tx * 4 + c;
                int j = kt * 64 + kk - si;
                int u = base_key + kt * 64 + kk;
                if (j >= 0 && j <= 512 && u >= 0)
                    acc[r][c] = (acc[r][c] + __bfloat162float(QEb[qe_base[r] + j])) * 0.125f;
                else
                    acc[r][c] = -1e30f;
            }
        }
        float corr[4];
#pragma unroll
        for (int r = 0; r < 4; r++) {
            float tm = fmaxf(fmaxf(acc[r][0], acc[r][1]), fmaxf(acc[r][2], acc[r][3]));
#pragma unroll
            for (int o = 1; o < 16; o <<= 1)
                tm = fmaxf(tm, __shfl_xor_sync(0xffffffffu, tm, o));
            float mnew = fmaxf(mrow[r], tm);
            corr[r] = __expf(mrow[r] - mnew);
            float rs = 0.f;
#pragma unroll
            for (int c = 0; c < 4; c++) {
                float p = (acc[r][c] > -5e29f) ? __expf(acc[r][c] - mnew) : 0.f;
                acc[r][c] = p;
                rs += p;
            }
#pragma unroll
            for (int o = 1; o < 16; o <<= 1)
                rs += __shfl_xor_sync(0xffffffffu, rs, o);
            lrow[r] = lrow[r] * corr[r] + rs;
            mrow[r] = mnew;
        }
#pragma unroll
        for (int r = 0; r < 4; r++) {
            int si = ty * 4 + r;
            uint32_t poff = si * 128 + ((((tx >> 1) ^ (si & 7))) << 4) + ((tx & 1) * 8);
            uint16_t hs[4], ls[4];
#pragma unroll
            for (int c = 0; c < 4; c++) {
                __nv_bfloat16 hh_, ll_;
                split1(acc[r][c], hh_, ll_);
                hs[c] = *(uint16_t*)&hh_;
                ls[c] = *(uint16_t*)&ll_;
            }
            *(uint2*)(smem + AT_PH + poff) = *(uint2*)hs;
            *(uint2*)(smem + AT_PL + poff) = *(uint2*)ls;
        }
        if (tx == 0) {
#pragma unroll
            for (int r = 0; r < 4; r++) corrS[ty * 4 + r] = corr[r];
        }
        __syncthreads();

        // prefetch next K/V (overlaps PV)
        if (kt < 8) {
            int u0 = base_key + (kt + 1) * 64; if (u0 < 0) u0 = 0;
            const size_t koff = ((size_t)bh_ * 4096 + u0) * 64;
            CPT(AT_KH, g_k_hi + koff, 64);
            CPT(AT_KL, g_k_lo + koff, 64);
            CPT(AT_VH, g_v_hi + koff, 64);
            CPT(AT_VL, g_v_lo + koff, 64);
        }
        asm volatile("cp.async.commit_group;");

        // O = O*corr + P.V via HMMA
        float cA = corrS[mrow0 + lg], cB = corrS[mrow0 + lg + 8];
#pragma unroll
        for (int n = 0; n < 4; n++) {
            O[n][0] *= cA; O[n][1] *= cA; O[n][2] *= cB; O[n][3] *= cB;
        }
#pragma unroll
        for (int ks = 0; ks < 4; ks++) {
            int chunk = 2 * ks + (lane >> 4);
            int rp = mrow0 + (lane & 15);
            uint32_t ap = sbase + AT_PH + rp * 128 + ((chunk ^ (rp & 7)) << 4);
            uint32_t ph[4], pl[4];
            ldm4(ph, ap); ldm4(pl, ap + 8192);
            uint32_t vhf[2][4], vlf[2][4];
#pragma unroll
            for (int p = 0; p < 2; p++) {
                int rv = ncol0 + p * 16 + (lane & 15);
                uint32_t av = sbase + AT_VTH + rv * 128 + ((chunk ^ (rv & 7)) << 4);
                ldm4(vhf[p], av); ldm4(vlf[p], av + 8192);
            }
#pragma unroll
            for (int n = 0; n < 4; n++) {
                int p = n >> 1, q = n & 1;
                mma16816(O[n], ph, vhf[p][q], vhf[p][q + 2]);
                mma16816(O[n], ph, vlf[p][q], vlf[p][q + 2]);
                mma16816(O[n], pl, vhf[p][q], vhf[p][q + 2]);
            }
        }
    }
#undef CPT

    if (tx == 0) {
#pragma unroll
        for (int r = 0; r < 4; r++) linvS[ty * 4 + r] = 1.f / lrow[r];
    }
    __syncthreads();
    float li0 = linvS[mrow0 + lg], li1 = linvS[mrow0 + lg + 8];
#pragma unroll
    for (int n = 0; n < 4; n++) {
        int si = mrow0 + lg, d = ncol0 + n * 8 + lt * 2;
        int t0 = tbase + si, t1 = t0 + 8;
        size_t o0 = ((size_t)(t0 * 2 + b)) * 1024 + h * 64 + d;
        size_t o1 = ((size_t)(t1 * 2 + b)) * 1024 + h * 64 + d;
        __nv_bfloat162 h0, h1, l0, l1;
        split1(O[n][0] * li0, h0.x, l0.x);
        split1(O[n][1] * li0, h0.y, l0.y);
        split1(O[n][2] * li1, h1.x, l1.x);
        split1(O[n][3] * li1, h1.y, l1.y);
        *(__nv_bfloat162*)(OHi + o0) = h0;
        *(__nv_bfloat162*)(OLo + o0) = l0;
        *(__nv_bfloat162*)(OHi + o1) = h1;
        *(__nv_bfloat162*)(OLo + o1) = l1;
    }
}

// ---------------------------------------------------------------------------
extern "C" void kernel_launch(void* const* d_in, const int* in_sizes, int n_in,
                              void* d_out, int out_size)
{
    const float* x      = (const float*)d_in[0];
    const float* ln1_g  = (const float*)d_in[1];
    const float* ln1_b  = (const float*)d_in[2];
    const float* qkv_w  = (const float*)d_in[3];
    const float* qkv_b  = (const float*)d_in[4];
    const float* pos_emb= (const float*)d_in[5];
    const float* out_w  = (const float*)d_in[6];
    const float* ln2_g  = (const float*)d_in[7];
    const float* ln2_b  = (const float*)d_in[8];
    const float* fc1_w  = (const float*)d_in[9];
    const float* fc1_b  = (const float*)d_in[10];
    const float* fc2_w  = (const float*)d_in[11];
    const float* fc2_b  = (const float*)d_in[12];
    float* out = (float*)d_out;

    float* scratch = 0;
    cudaGetSymbolAddress((void**)&scratch, g_scratch);
    __nv_bfloat16 *Ahi, *Alo, *A2hi, *A2lo, *Whi, *Wlo, *PThi, *PTlo;
    cudaGetSymbolAddress((void**)&Ahi, g_act_hi);
    cudaGetSymbolAddress((void**)&Alo, g_act_lo);
    cudaGetSymbolAddress((void**)&A2hi, g_act2_hi);
    cudaGetSymbolAddress((void**)&A2lo, g_act2_lo);
    cudaGetSymbolAddress((void**)&Whi, g_w_hi);
    cudaGetSymbolAddress((void**)&Wlo, g_w_lo);
    cudaGetSymbolAddress((void**)&PThi, g_pet_hi);
    cudaGetSymbolAddress((void**)&PTlo, g_pet_lo);

    float* OUT1 = scratch + OFF_OUT1;
    __nv_bfloat16* QEb = (__nv_bfloat16*)(scratch + OFF_QE);

    cudaFuncSetAttribute(mma_gemm<true, false, false, false, true, false, true>,   cudaFuncAttributeMaxDynamicSharedMemorySize, MMA_SMEM);
    cudaFuncSetAttribute(mma_gemm<false, false, false, false, false, true, false>, cudaFuncAttributeMaxDynamicSharedMemorySize, MMA_SMEM);
    cudaFuncSetAttribute(mma_gemm<false, false, true, false, false, false, false>, cudaFuncAttributeMaxDynamicSharedMemorySize, MMA_SMEM);
    cudaFuncSetAttribute(mma_gemm<true, true, false, true, false, false, false>,   cudaFuncAttributeMaxDynamicSharedMemorySize, MMA_SMEM);
    cudaFuncSetAttribute(mma_gemm<true, false, true, false, false, false, false>,  cudaFuncAttributeMaxDynamicSharedMemorySize, MMA_SMEM);
    cudaFuncSetAttribute(attn_kernel, cudaFuncAttributeMaxDynamicSharedMemorySize, ATT_SMEM);

    // 0. pe^T split
    pe_split_t_kernel<<<160, 256>>>(pos_emb, PThi, PTlo);
    // 1. LN1 + split
    ln_split_kernel<<<NROWS, 256>>>(x, ln1_g, ln1_b, Ahi, Alo);
    // 2. QKV GEMM: Q/K/V split side-outputs + nxt slice fp32 directly to d_out
    split_kernel<<<(QKV_N * EMB) / 1024, 256>>>(qkv_w, Whi, Wlo);
    mma_gemm<true, false, false, false, true, false, true><<<dim3(QKV_N / 128, NROWS / 128), 256, MMA_SMEM>>>(
        Ahi, Alo, Whi, Wlo, qkv_b, 0, out + 8388608, A2hi, A2lo, NROWS, QKV_N, EMB);
    // 3. QE = Qsplit @ peT^T -> bf16
    mma_gemm<false, false, false, false, false, true, false><<<dim3(NJP / 128, 131072 / 128), 256, MMA_SMEM>>>(
        A2hi, A2lo, PThi, PTlo, 0, 0, 0, QEb, 0, 131072, NJP, 64);
    // 4. HMMA attention -> act split
    attn_kernel<<<dim3(8, 8, 32), 256, ATT_SMEM>>>(A2hi, A2lo, QEb, Ahi, Alo);
    // 5. OUT1 = AV @ out_w^T + x
    split_kernel<<<(EMB * EMB) / 1024, 256>>>(out_w, Whi, Wlo);
    mma_gemm<false, false, true, false, false, false, false><<<dim3(EMB / 128, NROWS / 128), 256, MMA_SMEM>>>(
        Ahi, Alo, Whi, Wlo, 0, x, OUT1, 0, 0, NROWS, EMB, EMB);
    // 6. LN2 + split
    ln_split_kernel<<<NROWS, 256>>>(OUT1, ln2_g, ln2_b, Ahi, Alo);
    // 7. act2 = split(relu(H2 @ fc1_w^T + fc1_b))
    split_kernel<<<(FFN_I * EMB) / 1024, 256>>>(fc1_w, Whi, Wlo);
    mma_gemm<true, true, false, true, false, false, false><<<dim3(FFN_I / 128, NROWS / 128), 256, MMA_SMEM>>>(
        Ahi, Alo, Whi, Wlo, fc1_b, 0, 0, A2hi, A2lo, NROWS, FFN_I, EMB);
    // 8. out = FF1 @ fc2_w^T + fc2_b + OUT1
    split_kernel<<<(EMB * FFN_I) / 1024, 256>>>(fc2_w, Whi, Wlo);
    mma_gemm<true, false, true, false, false, false, false><<<dim3(EMB / 128, NROWS / 128), 256, MMA_SMEM>>>(
        A2hi, A2lo, Whi, Wlo, fc2_b, OUT1, out, 0, 0, NROWS, EMB, FFN_I);
}

// round 13
// speedup vs baseline: 1.4215x; 1.2296x over previous
#include <cuda_runtime.h>
#include <cuda_bf16.h>
#include <cuda_fp16.h>
#include <math.h>
#include <stdint.h>

// ---------------------------------------------------------------------------
// Shapes: x (T=4096, B=2, E=1024); H=16 heads, dk=dv=64; window 512 (513 rel pos)
// QE: bf16 [r = (t*2+b)*16+h][j], row stride 640
// Qsplit: bf16 [(t*2+b)*16+h][64];  Ksplit/Vsplit: bf16 [(b*16+h)][t][64]
// nxt (d_out+8388608): fp32 [s][b*16+h][128] written by QKV GEMM epilogue
// FFN/out-proj path: fp16 (A single, W split hi/lo)
// ---------------------------------------------------------------------------
#define NROWS 8192
#define EMB   1024
#define QKV_N 3072
#define FFN_I 4096
#define NJ    513
#define NJP   640

#define OFF_OUT1   16777216ull
#define OFF_QE     92274688ull
#define SCRATCH_FLOATS 176160768ull

__device__ float g_scratch[SCRATCH_FLOATS];

__device__ __nv_bfloat16 g_act_hi[8388608];     // bf16 LN1-hi / fp16 AV / fp16 H2
__device__ __nv_bfloat16 g_act_lo[8388608];
__device__ __nv_bfloat16 g_act2_hi[33554432];   // bf16 Qsplit-hi early; fp16 FF1 later
__device__ __nv_bfloat16 g_act2_lo[33554432];
__device__ __nv_bfloat16 g_w_hi[4194304];
__device__ __nv_bfloat16 g_w_lo[4194304];
__device__ __nv_bfloat16 g_pet_hi[40960];
__device__ __nv_bfloat16 g_pet_lo[40960];
__device__ __nv_bfloat16 g_k_hi[8388608];
__device__ __nv_bfloat16 g_k_lo[8388608];
__device__ __nv_bfloat16 g_v_hi[8388608];
__device__ __nv_bfloat16 g_v_lo[8388608];

__device__ __forceinline__ uint32_t smem_u32(const void* p) {
    uint32_t a;
    asm("{ .reg .u64 t; cvta.to.shared.u64 t, %1; cvt.u32.u64 %0, t; }" : "=r"(a) : "l"(p));
    return a;
}
__device__ __forceinline__ void split1(float v, __nv_bfloat16& h, __nv_bfloat16& l) {
    h = __float2bfloat16(v);
    l = __float2bfloat16(v - __bfloat162float(h));
}

// ---------------------------------------------------------------------------
__global__ __launch_bounds__(256) void split_kernel(
    const float* __restrict__ X, __nv_bfloat16* __restrict__ Hi,
    __nv_bfloat16* __restrict__ Lo)
{
    int i4 = blockIdx.x * 256 + threadIdx.x;
    float4 v = ((const float4*)X)[i4];
    __nv_bfloat162 hi0, hi1, lo0, lo1;
    split1(v.x, hi0.x, lo0.x);
    split1(v.y, hi0.y, lo0.y);
    split1(v.z, hi1.x, lo1.x);
    split1(v.w, hi1.y, lo1.y);
    ((__nv_bfloat162*)Hi)[i4 * 2]     = hi0;
    ((__nv_bfloat162*)Hi)[i4 * 2 + 1] = hi1;
    ((__nv_bfloat162*)Lo)[i4 * 2]     = lo0;
    ((__nv_bfloat162*)Lo)[i4 * 2 + 1] = lo1;
}

// fp16 weight split: hi = rn(v), lo = rn(v - hi)
__global__ __launch_bounds__(256) void halfsplit_kernel(
    const float* __restrict__ X, __half* __restrict__ Hi,
    __half* __restrict__ Lo)
{
    int i4 = blockIdx.x * 256 + threadIdx.x;
    float4 v = ((const float4*)X)[i4];
    __half h0 = __float2half_rn(v.x), h1 = __float2half_rn(v.y);
    __half h2 = __float2half_rn(v.z), h3 = __float2half_rn(v.w);
    __half l0 = __float2half_rn(v.x - __half2float(h0));
    __half l1 = __float2half_rn(v.y - __half2float(h1));
    __half l2 = __float2half_rn(v.z - __half2float(h2));
    __half l3 = __float2half_rn(v.w - __half2float(h3));
    __half2 H0; H0.x = h0; H0.y = h1;
    __half2 H1; H1.x = h2; H1.y = h3;
    __half2 L0; L0.x = l0; L0.y = l1;
    __half2 L1; L1.x = l2; L1.y = l3;
    ((__half2*)Hi)[i4 * 2]     = H0;
    ((__half2*)Hi)[i4 * 2 + 1] = H1;
    ((__half2*)Lo)[i4 * 2]     = L0;
    ((__half2*)Lo)[i4 * 2 + 1] = L1;
}

__global__ __launch_bounds__(256) void pe_split_t_kernel(
    const float* __restrict__ pe, __nv_bfloat16* __restrict__ Hi,
    __nv_bfloat16* __restrict__ Lo)
{
    int idx = blockIdx.x * 256 + threadIdx.x;
    int k = idx & 63;
    int j = idx >> 6;
    float v = (j < NJ) ? pe[(size_t)k * NJ + j] : 0.f;
    __nv_bfloat16 h, l;
    split1(v, h, l);
    Hi[idx] = h;
    Lo[idx] = l;
}

// LN -> bf16 split (LN1)
__global__ __launch_bounds__(256) void ln_split_kernel(
    const float* __restrict__ X, const float* __restrict__ G,
    const float* __restrict__ Bt, __nv_bfloat16* __restrict__ Hi,
    __nv_bfloat16* __restrict__ Lo)
{
    __shared__ float ssum[8], ssq[8], smv[2];
    int row = blockIdx.x;
    int tid = threadIdx.x;
    const float4* xr = (const float4*)(X + (size_t)row * EMB);
    float4 v = xr[tid];
    float s = v.x + v.y + v.z + v.w;
    float q = v.x*v.x + v.y*v.y + v.z*v.z + v.w*v.w;
#pragma unroll
    for (int o = 16; o > 0; o >>= 1) {
        s += __shfl_xor_sync(0xffffffffu, s, o);
        q += __shfl_xor_sync(0xffffffffu, q, o);
    }
    if ((tid & 31) == 0) { ssum[tid >> 5] = s; ssq[tid >> 5] = q; }
    __syncthreads();
    if (tid == 0) {
        float S = 0.f, Q = 0.f;
#pragma unroll
        for (int i = 0; i < 8; i++) { S += ssum[i]; Q += ssq[i]; }
        float mean = S * (1.f / EMB);
        float var  = Q * (1.f / EMB) - mean * mean;
        smv[0] = mean;
        smv[1] = rsqrtf(var + 1e-5f);
    }
    __syncthreads();
    float mean = smv[0], inv = smv[1];
    float4 g = ((const float4*)G)[tid];
    float4 b = ((const float4*)Bt)[tid];
    float o0 = (v.x - mean) * inv * g.x + b.x;
    float o1 = (v.y - mean) * inv * g.y + b.y;
    float o2 = (v.z - mean) * inv * g.z + b.z;
    float o3 = (v.w - mean) * inv * g.w + b.w;
    __nv_bfloat162 hi0, hi1, lo0, lo1;
    split1(o0, hi0.x, lo0.x);
    split1(o1, hi0.y, lo0.y);
    split1(o2, hi1.x, lo1.x);
    split1(o3, hi1.y, lo1.y);
    size_t i4 = (size_t)row * 256 + tid;
    ((__nv_bfloat162*)Hi)[i4 * 2]     = hi0;
    ((__nv_bfloat162*)Hi)[i4 * 2 + 1] = hi1;
    ((__nv_bfloat162*)Lo)[i4 * 2]     = lo0;
    ((__nv_bfloat162*)Lo)[i4 * 2 + 1] = lo1;
}

// LN -> fp16 single (LN2)
__global__ __launch_bounds__(256) void ln_half_kernel(
    const float* __restrict__ X, const float* __restrict__ G,
    const float* __restrict__ Bt, __half* __restrict__ H)
{
    __shared__ float ssum[8], ssq[8], smv[2];
    int row = blockIdx.x;
    int tid = threadIdx.x;
    const float4* xr = (const float4*)(X + (size_t)row * EMB);
    float4 v = xr[tid];
    float s = v.x + v.y + v.z + v.w;
    float q = v.x*v.x + v.y*v.y + v.z*v.z + v.w*v.w;
#pragma unroll
    for (int o = 16; o > 0; o >>= 1) {
        s += __shfl_xor_sync(0xffffffffu, s, o);
        q += __shfl_xor_sync(0xffffffffu, q, o);
    }
    if ((tid & 31) == 0) { ssum[tid >> 5] = s; ssq[tid >> 5] = q; }
    __syncthreads();
    if (tid == 0) {
        float S = 0.f, Q = 0.f;
#pragma unroll
        for (int i = 0; i < 8; i++) { S += ssum[i]; Q += ssq[i]; }
        float mean = S * (1.f / EMB);
        float var  = Q * (1.f / EMB) - mean * mean;
        smv[0] = mean;
        smv[1] = rsqrtf(var + 1e-5f);
    }
    __syncthreads();
    float mean = smv[0], inv = smv[1];
    float4 g = ((const float4*)G)[tid];
    float4 b = ((const float4*)Bt)[tid];
    __half2 a0 = __floats2half2_rn((v.x - mean) * inv * g.x + b.x,
                                   (v.y - mean) * inv * g.y + b.y);
    __half2 a1 = __floats2half2_rn((v.z - mean) * inv * g.z + b.z,
                                   (v.w - mean) * inv * g.w + b.w);
    size_t i4 = (size_t)row * 256 + tid;
    ((__half2*)H)[i4 * 2]     = a0;
    ((__half2*)H)[i4 * 2 + 1] = a1;
}

// ---------------------------------------------------------------------------
// common MMA helpers
// ---------------------------------------------------------------------------
__device__ __forceinline__ void cp16(uint32_t dst, const void* src) {
    asm volatile("cp.async.cg.shared.global [%0], [%1], 16;" :: "r"(dst), "l"(src));
}
__device__ __forceinline__ void ldm4(uint32_t* r, uint32_t addr) {
    asm volatile("ldmatrix.sync.aligned.m8n8.x4.shared.b16 {%0,%1,%2,%3}, [%4];"
                 : "=r"(r[0]), "=r"(r[1]), "=r"(r[2]), "=r"(r[3]) : "r"(addr));
}
__device__ __forceinline__ void mma16816(float* c, const uint32_t* a,
                                         uint32_t b0, uint32_t b1) {
    asm volatile(
        "mma.sync.aligned.m16n8k16.row.col.f32.bf16.bf16.f32 "
        "{%0,%1,%2,%3}, {%4,%5,%6,%7}, {%8,%9}, {%0,%1,%2,%3};"
        : "+f"(c[0]), "+f"(c[1]), "+f"(c[2]), "+f"(c[3])
        : "r"(a[0]), "r"(a[1]), "r"(a[2]), "r"(a[3]), "r"(b0), "r"(b1));
}
__device__ __forceinline__ void mma16816h(float* c, const uint32_t* a,
                                          uint32_t b0, uint32_t b1) {
    asm volatile(
        "mma.sync.aligned.m16n8k16.row.col.f32.f16.f16.f32 "
        "{%0,%1,%2,%3}, {%4,%5,%6,%7}, {%8,%9}, {%0,%1,%2,%3};"
        : "+f"(c[0]), "+f"(c[1]), "+f"(c[2]), "+f"(c[3])
        : "r"(a[0]), "r"(a[1]), "r"(a[2]), "r"(a[3]), "r"(b0), "r"(b1));
}

// ---------------------------------------------------------------------------
// bf16 split GEMM (proven; used for QKV + QE only)
// ---------------------------------------------------------------------------
#define STAGE_BYTES 32768
#define MMA_SMEM    98304

template<bool BIAS, bool QOUT, bool HALFO, bool NXTO>
__global__ __launch_bounds__(256, 2) void mma_gemm(
    const __nv_bfloat16* __restrict__ Ah, const __nv_bfloat16* __restrict__ Al,
    const __nv_bfloat16* __restrict__ Bh, const __nv_bfloat16* __restrict__ Bl,
    const float* __restrict__ bias,
    float* __restrict__ C, __nv_bfloat16* __restrict__ OHi,
    __nv_bfloat16* __restrict__ OLo, int M, int N, int K)
{
    extern __shared__ char smem[];
    const uint32_t sbase = smem_u32(smem);
    const int tid = threadIdx.x;
    const int wid = tid >> 5, lane = tid & 31;
    const int bm = blockIdx.y * 128, bn = blockIdx.x * 128;
    const int m0w = (wid >> 2) * 64, n0w = (wid & 3) * 32;

    const int r0 = tid >> 2,         c0 = tid & 3;
    const int r1 = (tid + 256) >> 2, c1 = (tid + 256) & 3;
    const uint32_t so0 = (uint32_t)(r0 * 64 + ((c0 ^ ((r0 >> 1) & 3)) * 16));
    const uint32_t so1 = (uint32_t)(r1 * 64 + ((c1 ^ ((r1 >> 1) & 3)) * 16));
    const size_t offA0 = (size_t)(bm + r0) * K + c0 * 8;
    const size_t offA1 = (size_t)(bm + r1) * K + c1 * 8;
    const size_t offB0 = (size_t)(bn + r0) * K + c0 * 8;
    const size_t offB1 = (size_t)(bn + r1) * K + c1 * 8;

    float acc[4][4][4];
#pragma unroll
    for (int a = 0; a < 4; a++)
#pragma unroll
        for (int n = 0; n < 4; n++)
#pragma unroll
            for (int q = 0; q < 4; q++) acc[a][n][q] = 0.f;

    const int nt = K >> 5;
    const int rowA_base = m0w + (lane & 15);
    const int rowB_base = n0w + (lane & 15);
    const int chsel = lane >> 4;

#define LOAD_STAGE(s, k0)                                                     \
    do {                                                                      \
        uint32_t d = sbase + (s) * STAGE_BYTES;                               \
        cp16(d + so0,          Ah + offA0 + (k0));                            \
        cp16(d + so1,          Ah + offA1 + (k0));                            \
        cp16(d + 8192  + so0,  Al + offA0 + (k0));                            \
        cp16(d + 8192  + so1,  Al + offA1 + (k0));                            \
        cp16(d + 16384 + so0,  Bh + offB0 + (k0));                            \
        cp16(d + 16384 + so1,  Bh + offB1 + (k0));                            \
        cp16(d + 24576 + so0,  Bl + offB0 + (k0));                            \
        cp16(d + 24576 + so1,  Bl + offB1 + (k0));                            \
    } while (0)

    LOAD_STAGE(0, 0);
    asm volatile("cp.async.commit_group;");
    if (nt > 1) LOAD_STAGE(1, 32);
    asm volatile("cp.async.commit_group;");

    int stage = 0;
    for (int i = 0; i < nt; i++) {
        asm volatile("cp.async.wait_group 1;");
        __syncthreads();

        uint32_t base = sbase + stage * STAGE_BYTES;
#pragma unroll
        for (int ks = 0; ks < 2; ks++) {
            const int chunk = ks * 2 + chsel;
            uint32_t bh[2][4], bl[2][4];
#pragma unroll
            for (int p = 0; p < 2; p++) {
                int row = rowB_base + p * 16;
                uint32_t ad = base + 16384 + (uint32_t)(row * 64 + ((chunk ^ ((row >> 1) & 3)) * 16));
                ldm4(bh[p], ad);
                ldm4(bl[p], ad + 8192);
            }
#pragma unroll
            for (int a = 0; a < 4; a++) {
                uint32_t ah[4], al[4];
                int row = rowA_base + a * 16;
                uint32_t ad = base + (uint32_t)(row * 64 + ((chunk ^ ((row >> 1) & 3)) * 16));
                ldm4(ah, ad);
                ldm4(al, ad + 8192);
#pragma unroll
                for (int n = 0; n < 4; n++) {
                    int p = n >> 1, q = n & 1;
                    mma16816(acc[a][n], ah, bh[p][q], bh[p][q + 2]);
                    mma16816(acc[a][n], ah, bl[p][q], bl[p][q + 2]);
                    mma16816(acc[a][n], al, bh[p][q], bh[p][q + 2]);
                }
            }
        }
        int nx = i + 2;
        if (nx < nt) {
            int ns = stage + 2; if (ns >= 3) ns -= 3;
            LOAD_STAGE(ns, nx << 5);
        }
        asm volatile("cp.async.commit_group;");
        if (++stage == 3) stage = 0;
    }
#undef LOAD_STAGE

    const int g = lane >> 2, t = lane & 3;
#pragma unroll
    for (int a = 0; a < 4; a++) {
#pragma unroll
        for (int n = 0; n < 4; n++) {
            int row0 = bm + m0w + a * 16 + g;
            int col  = bn + n0w + n * 8 + 2 * t;
            float v0 = acc[a][n][0], v1 = acc[a][n][1];
            float v2 = acc[a][n][2], v3 = acc[a][n][3];
            if (BIAS) {
                float b0 = bias[col], b1 = bias[col + 1];
                v0 += b0; v1 += b1; v2 += b0; v3 += b1;
            }
            if (HALFO) {
                __nv_bfloat162 h0, h1;
                h0.x = __float2bfloat16(v0); h0.y = __float2bfloat16(v1);
                h1.x = __float2bfloat16(v2); h1.y = __float2bfloat16(v3);
                *(__nv_bfloat162*)(OHi + (size_t)row0 * N + col)       = h0;
                *(__nv_bfloat162*)(OHi + (size_t)(row0 + 8) * N + col) = h1;
            }
            if (QOUT) {
                int hh = col / 192;
                int cc = col - hh * 192;
                __nv_bfloat162 h0, h1, l0, l1;
                split1(v0, h0.x, l0.x); split1(v1, h0.y, l0.y);
                split1(v2, h1.x, l1.x); split1(v3, h1.y, l1.y);
                int b0_ = row0 & 1, t0_ = row0 >> 1;
                int t1_ = (row0 + 8) >> 1;
                if (cc < 64) {
                    size_t q0o = ((size_t)row0 * 16 + hh) * 64 + cc;
                    size_t q1o = ((size_t)(row0 + 8) * 16 + hh) * 64 + cc;
                    *(__nv_bfloat162*)(OHi + q0o) = h0; *(__nv_bfloat162*)(OLo + q0o) = l0;
                    *(__nv_bfloat162*)(OHi + q1o) = h1; *(__nv_bfloat162*)(OLo + q1o) = l1;
                } else if (cc < 128) {
                    size_t k0o = (((size_t)(b0_ * 16 + hh)) * 4096 + t0_) * 64 + (cc - 64);
                    size_t k1o = (((size_t)(b0_ * 16 + hh)) * 4096 + t1_) * 64 + (cc - 64);
                    *(__nv_bfloat162*)(g_k_hi + k0o) = h0; *(__nv_bfloat162*)(g_k_lo + k0o) = l0;
                    *(__nv_bfloat162*)(g_k_hi + k1o) = h1; *(__nv_bfloat162*)(g_k_lo + k1o) = l1;
                } else {
                    size_t v0o = (((size_t)(b0_ * 16 + hh)) * 4096 + t0_) * 64 + (cc - 128);
                    size_t v1o = (((size_t)(b0_ * 16 + hh)) * 4096 + t1_) * 64 + (cc - 128);
                    *(__nv_bfloat162*)(g_v_hi + v0o) = h0; *(__nv_bfloat162*)(g_v_lo + v0o) = l0;
                    *(__nv_bfloat162*)(g_v_hi + v1o) = h1; *(__nv_bfloat162*)(g_v_lo + v1o) = l1;
                }
                if (NXTO && cc >= 64) {
                    if (t0_ >= 3584) {
                        size_t o = (((size_t)(t0_ - 3584) * 32) + b0_ * 16 + hh) * 128 + (cc - 64);
                        float2 w; w.x = v0; w.y = v1;
                        *(float2*)(C + o) = w;
                    }
                    if (t1_ >= 3584) {
                        size_t o = (((size_t)(t1_ - 3584) * 32) + b0_ * 16 + hh) * 128 + (cc - 64);
                        float2 w; w.x = v2; w.y = v3;
                        *(float2*)(C + o) = w;
                    }
                }
            }
        }
    }
}

// ---------------------------------------------------------------------------
// fp16 GEMM: C = A(f16) * (Bh+Bl)(f16)^T  — 2 MMAs/tile, A single.
// H16O: write __half output. RES: +Res (fp32). fp32 C otherwise.
// ---------------------------------------------------------------------------
#define H_STAGE 24576
#define H_SMEM  73728

template<bool BIAS, bool RELU, bool RES, bool H16O>
__global__ __launch_bounds__(256, 2) void mma_gemm_h(
    const __half* __restrict__ Ax,
    const __half* __restrict__ Bh_, const __half* __restrict__ Bl_,
    const float* __restrict__ bias, const float* __restrict__ Res,
    float* __restrict__ C, __half* __restrict__ OH, int M, int N, int K)
{
    extern __shared__ char smem[];
    const uint32_t sbase = smem_u32(smem);
    const int tid = threadIdx.x;
    const int wid = tid >> 5, lane = tid & 31;
    const int bm = blockIdx.y * 128, bn = blockIdx.x * 128;
    const int m0w = (wid >> 2) * 64, n0w = (wid & 3) * 32;

    const int r0 = tid >> 2,         c0 = tid & 3;
    const int r1 = (tid + 256) >> 2, c1 = (tid + 256) & 3;
    const uint32_t so0 = (uint32_t)(r0 * 64 + ((c0 ^ ((r0 >> 1) & 3)) * 16));
    const uint32_t so1 = (uint32_t)(r1 * 64 + ((c1 ^ ((r1 >> 1) & 3)) * 16));
    const size_t offA0 = (size_t)(bm + r0) * K + c0 * 8;
    const size_t offA1 = (size_t)(bm + r1) * K + c1 * 8;
    const size_t offB0 = (size_t)(bn + r0) * K + c0 * 8;
    const size_t offB1 = (size_t)(bn + r1) * K + c1 * 8;

    float acc[4][4][4];
#pragma unroll
    for (int a = 0; a < 4; a++)
#pragma unroll
        for (int n = 0; n < 4; n++)
#pragma unroll
            for (int q = 0; q < 4; q++) acc[a][n][q] = 0.f;

    const int nt = K >> 5;
    const int rowA_base = m0w + (lane & 15);
    const int rowB_base = n0w + (lane & 15);
    const int chsel = lane >> 4;

#define LOAD_STAGE_H(s, k0)                                                   \
    do {                                                                      \
        uint32_t d = sbase + (s) * H_STAGE;                                   \
        cp16(d + so0,          Ax  + offA0 + (k0));                           \
        cp16(d + so1,          Ax  + offA1 + (k0));                           \
        cp16(d + 8192  + so0,  Bh_ + offB0 + (k0));                           \
        cp16(d + 8192  + so1,  Bh_ + offB1 + (k0));                           \
        cp16(d + 16384 + so0,  Bl_ + offB0 + (k0));                           \
        cp16(d + 16384 + so1,  Bl_ + offB1 + (k0));                           \
    } while (0)

    LOAD_STAGE_H(0, 0);
    asm volatile("cp.async.commit_group;");
    if (nt > 1) LOAD_STAGE_H(1, 32);
    asm volatile("cp.async.commit_group;");

    int stage = 0;
    for (int i = 0; i < nt; i++) {
        asm volatile("cp.async.wait_group 1;");
        __syncthreads();

        uint32_t base = sbase + stage * H_STAGE;
#pragma unroll
        for (int ks = 0; ks < 2; ks++) {
            const int chunk = ks * 2 + chsel;
            uint32_t bh[2][4], bl[2][4];
#pragma unroll
            for (int p = 0; p < 2; p++) {
                int row = rowB_base + p * 16;
                uint32_t ad = base + 8192 + (uint32_t)(row * 64 + ((chunk ^ ((row >> 1) & 3)) * 16));
                ldm4(bh[p], ad);
                ldm4(bl[p], ad + 8192);
            }
#pragma unroll
            for (int a = 0; a < 4; a++) {
                uint32_t ah[4];
                int row = rowA_base + a * 16;
                uint32_t ad = base + (uint32_t)(row * 64 + ((chunk ^ ((row >> 1) & 3)) * 16));
                ldm4(ah, ad);
#pragma unroll
                for (int n = 0; n < 4; n++) {
                    int p = n >> 1, q = n & 1;
                    mma16816h(acc[a][n], ah, bh[p][q], bh[p][q + 2]);
                    mma16816h(acc[a][n], ah, bl[p][q], bl[p][q + 2]);
                }
            }
        }
        int nx = i + 2;
        if (nx < nt) {
            int ns = stage + 2; if (ns >= 3) ns -= 3;
            LOAD_STAGE_H(ns, nx << 5);
        }
        asm volatile("cp.async.commit_group;");
        if (++stage == 3) stage = 0;
    }
#undef LOAD_STAGE_H

    const int g = lane >> 2, t = lane & 3;
#pragma unroll
    for (int a = 0; a < 4; a++) {
#pragma unroll
        for (int n = 0; n < 4; n++) {
            int row0 = bm + m0w + a * 16 + g;
            int col  = bn + n0w + n * 8 + 2 * t;
            float v0 = acc[a][n][0], v1 = acc[a][n][1];
            float v2 = acc[a][n][2], v3 = acc[a][n][3];
            if (BIAS) {
                float b0 = bias[col], b1 = bias[col + 1];
                v0 += b0; v1 += b1; v2 += b0; v3 += b1;
            }
            if (RELU) {
                v0 = fmaxf(v0, 0.f); v1 = fmaxf(v1, 0.f);
                v2 = fmaxf(v2, 0.f); v3 = fmaxf(v3, 0.f);
            }
            if (RES) {
                const float2 q0 = *(const float2*)(Res + (size_t)row0 * N + col);
                const float2 q1 = *(const float2*)(Res + (size_t)(row0 + 8) * N + col);
                v0 += q0.x; v1 += q0.y; v2 += q1.x; v3 += q1.y;
            }
            if (H16O) {
                __half2 h0 = __floats2half2_rn(v0, v1);
                __half2 h1 = __floats2half2_rn(v2, v3);
                *(__half2*)(OH + (size_t)row0 * N + col)       = h0;
                *(__half2*)(OH + (size_t)(row0 + 8) * N + col) = h1;
            } else {
                float2 o0; o0.x = v0; o0.y = v1;
                float2 o1; o1.x = v2; o1.y = v3;
                *(float2*)(C + (size_t)row0 * N + col)       = o0;
                *(float2*)(C + (size_t)(row0 + 8) * N + col) = o1;
            }
        }
    }
}

// ---------------------------------------------------------------------------
// HMMA sliding-window attention (r11 body; epilogue writes fp16 single)
// ---------------------------------------------------------------------------
#define AT_QH 0
#define AT_QL 8192
#define AT_KH 16384
#define AT_KL 24576
#define AT_VH 32768
#define AT_VL 40960
#define AT_VTH 49152
#define AT_VTL 57344
#define AT_S   65536
#define AT_PH  82944
#define AT_PL  91136
#define AT_CORR 99328
#define AT_LINV 99584
#define ATT_SMEM 99840

__global__ __launch_bounds__(256, 2) void attn_kernel(
    const __nv_bfloat16* __restrict__ Qhi, const __nv_bfloat16* __restrict__ Qlo,
    const __nv_bfloat16* __restrict__ QEb, __half* __restrict__ OH)
{
    extern __shared__ char smem[];
    const uint32_t sbase = smem_u32(smem);
    float* Sf    = (float*)(smem + AT_S);
    float* corrS = (float*)(smem + AT_CORR);
    float* linvS = (float*)(smem + AT_LINV);

    const int s0 = blockIdx.x * 64;
    const int gg = blockIdx.y;
    const int bh = blockIdx.z;
    const int b = bh >> 4, h = bh & 15;
    const int tid = threadIdx.x;
    const int lane = tid & 31, wid = tid >> 5;
    const int tx = tid & 15, ty = tid >> 4;
    const int tbase = gg * 512 + s0;
    const int base_key = tbase - 512;
    const int bh_ = b * 16 + h;

    const int mrow0 = (wid >> 1) * 16;
    const int ncol0 = (wid & 1) * 32;
    const int lg = lane >> 2, lt = lane & 3;

    const int cr0 = tid >> 3, cc0 = tid & 7;
    const int cr1 = (tid + 256) >> 3, cc1 = (tid + 256) & 7;

#define CPT(dstoff, srcp, stride)                                                        \
    do {                                                                                 \
        cp16(sbase + (dstoff) + cr0 * 128 + ((cc0 ^ (cr0 & 7)) * 16),                    \
             (srcp) + (size_t)cr0 * (stride) + cc0 * 8);                                 \
        cp16(sbase + (dstoff) + cr1 * 128 + ((cc1 ^ (cr1 & 7)) * 16),                    \
             (srcp) + (size_t)cr1 * (stride) + cc1 * 8);                                 \
    } while (0)

    {
        const size_t qoff = (((size_t)tbase * 2 + b) * 16 + h) * 64;
        CPT(AT_QH, Qhi + qoff, 2048);
        CPT(AT_QL, Qlo + qoff, 2048);
        int u0 = base_key; if (u0 < 0) u0 = 0;
        const size_t koff = ((size_t)bh_ * 4096 + u0) * 64;
        CPT(AT_KH, g_k_hi + koff, 64);
        CPT(AT_KL, g_k_lo + koff, 64);
        CPT(AT_VH, g_v_hi + koff, 64);
        CPT(AT_VL, g_v_lo + koff, 64);
        asm volatile("cp.async.commit_group;");
    }

    float O[4][4];
    float mrow[4], lrow[4];
#pragma unroll
    for (int r = 0; r < 4; r++) {
        mrow[r] = -1e30f; lrow[r] = 0.f;
#pragma unroll
        for (int c = 0; c < 4; c++) O[r][c] = 0.f;
    }
    size_t qe_base[4];
#pragma unroll
    for (int r = 0; r < 4; r++) {
        int t = tbase + ty * 4 + r;
        qe_base[r] = ((size_t)(t * 2 + b) * 16 + h) * NJP;
    }

    for (int kt = 0; kt < 9; kt++) {
        asm volatile("cp.async.wait_group 0;");
        __syncthreads();

        {
            int d0 = (tid & 15) * 4, kk0 = (tid >> 4) * 4;
#pragma unroll
            for (int tile = 0; tile < 2; tile++) {
                uint32_t inb = tile ? AT_VL : AT_VH;
                uint32_t outb = tile ? AT_VTL : AT_VTH;
                uint16_t m[4][4];
#pragma unroll
                for (int i = 0; i < 4; i++) {
                    int row = kk0 + i;
                    uint32_t off = inb + row * 128 + (((d0 >> 3) ^ (row & 7)) << 4) + ((d0 & 7) * 2);
                    uint2 v = *(uint2*)(smem + off);
                    uint16_t* pv = (uint16_t*)&v;
                    m[i][0] = pv[0]; m[i][1] = pv[1]; m[i][2] = pv[2]; m[i][3] = pv[3];
                }
#pragma unroll
                for (int j = 0; j < 4; j++) {
                    int rd = d0 + j;
                    uint32_t o2 = outb + rd * 128 + (((kk0 >> 3) ^ (rd & 7)) << 4) + ((kk0 & 7) * 2);
                    uint16_t o[4] = {m[0][j], m[1][j], m[2][j], m[3][j]};
                    *(uint2*)(smem + o2) = *(uint2*)o;
                }
            }
        }
        __syncthreads();

        float sacc[4][4];
#pragma unroll
        for (int n = 0; n < 4; n++)
#pragma unroll
            for (int q = 0; q < 4; q++) sacc[n][q] = 0.f;
#pragma unroll
        for (int ks = 0; ks < 4; ks++) {
            int chunk = 2 * ks + (lane >> 4);
            int rq = mrow0 + (lane & 15);
            uint32_t aq = sbase + AT_QH + rq * 128 + ((chunk ^ (rq & 7)) << 4);
            uint32_t qh[4], ql[4];
            ldm4(qh, aq); ldm4(ql, aq + 8192);
            uint32_t khf[2][4], klf[2][4];
#pragma unroll
            for (int p = 0; p < 2; p++) {
                int rk = ncol0 + p * 16 + (lane & 15);
                uint32_t ak = sbase + AT_KH + rk * 128 + ((chunk ^ (rk & 7)) << 4);
                ldm4(khf[p], ak); ldm4(klf[p], ak + 8192);
            }
#pragma unroll
            for (int n = 0; n < 4; n++) {
                int p = n >> 1, q = n & 1;
                mma16816(sacc[n], qh, khf[p][q], khf[p][q + 2]);
                mma16816(sacc[n], qh, klf[p][q], klf[p][q + 2]);
                mma16816(sacc[n], ql, khf[p][q], khf[p][q + 2]);
            }
        }
#pragma unroll
        for (int n = 0; n < 4; n++) {
            int si = mrow0 + lg, ck = ncol0 + n * 8 + lt * 2;
            float2 a0; a0.x = sacc[n][0]; a0.y = sacc[n][1];
            float2 a1; a1.x = sacc[n][2]; a1.y = sacc[n][3];
            *(float2*)&Sf[si * 68 + ck]       = a0;
            *(float2*)&Sf[(si + 8) * 68 + ck] = a1;
        }
        __syncthreads();

        float acc[4][4];
#pragma unroll
        for (int r = 0; r < 4; r++) {
            float4 sv = *(const float4*)&Sf[(ty * 4 + r) * 68 + tx * 4];
            acc[r][0] = sv.x; acc[r][1] = sv.y; acc[r][2] = sv.z; acc[r][3] = sv.w;
        }
#pragma unroll
        for (int r = 0; r < 4; r++) {
            int si = ty * 4 + r;
#pragma unroll
            for (int c = 0; c < 4; c++) {
                int kk = tx * 4 + c;
                int j = kt * 64 + kk - si;
                int u = base_key + kt * 64 + kk;
                if (j >= 0 && j <= 512 && u >= 0)
                    acc[r][c] = (acc[r][c] + __bfloat162float(QEb[qe_base[r] + j])) * 0.125f;
                else
                    acc[r][c] = -1e30f;
            }
        }
        float corr[4];
#pragma unroll
        for (int r = 0; r < 4; r++) {
            float tm = fmaxf(fmaxf(acc[r][0], acc[r][1]), fmaxf(acc[r][2], acc[r][3]));
#pragma unroll
            for (int o = 1; o < 16; o <<= 1)
                tm = fmaxf(tm, __shfl_xor_sync(0xffffffffu, tm, o));
            float mnew = fmaxf(mrow[r], tm);
            corr[r] = __expf(mrow[r] - mnew);
            float rs = 0.f;
#pragma unroll
            for (int c = 0; c < 4; c++) {
                float p = (acc[r][c] > -5e29f) ? __expf(acc[r][c] - mnew) : 0.f;
                acc[r][c] = p;
                rs += p;
            }
#pragma unroll
            for (int o = 1; o < 16; o <<= 1)
                rs += __shfl_xor_sync(0xffffffffu, rs, o);
            lrow[r] = lrow[r] * corr[r] + rs;
            mrow[r] = mnew;
        }
#pragma unroll
        for (int r = 0; r < 4; r++) {
            int si = ty * 4 + r;
            uint32_t poff = si * 128 + ((((tx >> 1) ^ (si & 7))) << 4) + ((tx & 1) * 8);
            uint16_t hs[4], ls[4];
#pragma unroll
            for (int c = 0; c < 4; c++) {
                __nv_bfloat16 hh_, ll_;
                split1(acc[r][c], hh_, ll_);
                hs[c] = *(uint16_t*)&hh_;
                ls[c] = *(uint16_t*)&ll_;
            }
            *(uint2*)(smem + AT_PH + poff) = *(uint2*)hs;
            *(uint2*)(smem + AT_PL + poff) = *(uint2*)ls;
        }
        if (tx == 0) {
#pragma unroll
            for (int r = 0; r < 4; r++) corrS[ty * 4 + r] = corr[r];
        }
        __syncthreads();

        if (kt < 8) {
            int u0 = base_key + (kt + 1) * 64; if (u0 < 0) u0 = 0;
            const size_t koff = ((size_t)bh_ * 4096 + u0) * 64;
            CPT(AT_KH, g_k_hi + koff, 64);
            CPT(AT_KL, g_k_lo + koff, 64);
            CPT(AT_VH, g_v_hi + koff, 64);
            CPT(AT_VL, g_v_lo + koff, 64);
        }
        asm volatile("cp.async.commit_group;");

        float cA = corrS[mrow0 + lg], cB = corrS[mrow0 + lg + 8];
#pragma unroll
        for (int n = 0; n < 4; n++) {
            O[n][0] *= cA; O[n][1] *= cA; O[n][2] *= cB; O[n][3] *= cB;
        }
#pragma unroll
        for (int ks = 0; ks < 4; ks++) {
            int chunk = 2 * ks + (lane >> 4);
            int rp = mrow0 + (lane & 15);
            uint32_t ap = sbase + AT_PH + rp * 128 + ((chunk ^ (rp & 7)) << 4);
            uint32_t ph[4], pl[4];
            ldm4(ph, ap); ldm4(pl, ap + 8192);
            uint32_t vhf[2][4], vlf[2][4];
#pragma unroll
            for (int p = 0; p < 2; p++) {
                int rv = ncol0 + p * 16 + (lane & 15);
                uint32_t av = sbase + AT_VTH + rv * 128 + ((chunk ^ (rv & 7)) << 4);
                ldm4(vhf[p], av); ldm4(vlf[p], av + 8192);
            }
#pragma unroll
            for (int n = 0; n < 4; n++) {
                int p = n >> 1, q = n & 1;
                mma16816(O[n], ph, vhf[p][q], vhf[p][q + 2]);
                mma16816(O[n], ph, vlf[p][q], vlf[p][q + 2]);
                mma16816(O[n], pl, vhf[p][q], vhf[p][q + 2]);
            }
        }
    }
#undef CPT

    if (tx == 0) {
#pragma unroll
        for (int r = 0; r < 4; r++) linvS[ty * 4 + r] = 1.f / lrow[r];
    }
    __syncthreads();
    float li0 = linvS[mrow0 + lg], li1 = linvS[mrow0 + lg + 8];
#pragma unroll
    for (int n = 0; n < 4; n++) {
        int si = mrow0 + lg, d = ncol0 + n * 8 + lt * 2;
        int t0 = tbase + si, t1 = t0 + 8;
        size_t o0 = ((size_t)(t0 * 2 + b)) * 1024 + h * 64 + d;
        size_t o1 = ((size_t)(t1 * 2 + b)) * 1024 + h * 64 + d;
        __half2 h0 = __floats2half2_rn(O[n][0] * li0, O[n][1] * li0);
        __half2 h1 = __floats2half2_rn(O[n][2] * li1, O[n][3] * li1);
        *(__half2*)(OH + o0) = h0;
        *(__half2*)(OH + o1) = h1;
    }
}

// ---------------------------------------------------------------------------
extern "C" void kernel_launch(void* const* d_in, const int* in_sizes, int n_in,
                              void* d_out, int out_size)
{
    const float* x      = (const float*)d_in[0];
    const float* ln1_g  = (const float*)d_in[1];
    const float* ln1_b  = (const float*)d_in[2];
    const float* qkv_w  = (const float*)d_in[3];
    const float* qkv_b  = (const float*)d_in[4];
    const float* pos_emb= (const float*)d_in[5];
    const float* out_w  = (const float*)d_in[6];
    const float* ln2_g  = (const float*)d_in[7];
    const float* ln2_b  = (const float*)d_in[8];
    const float* fc1_w  = (const float*)d_in[9];
    const float* fc1_b  = (const float*)d_in[10];
    const float* fc2_w  = (const float*)d_in[11];
    const float* fc2_b  = (const float*)d_in[12];
    float* out = (float*)d_out;

    float* scratch = 0;
    cudaGetSymbolAddress((void**)&scratch, g_scratch);
    void *pA, *pAl, *pA2, *pA2l, *pW, *pWl, *pPT, *pPTl;
    cudaGetSymbolAddress(&pA, g_act_hi);
    cudaGetSymbolAddress(&pAl, g_act_lo);
    cudaGetSymbolAddress(&pA2, g_act2_hi);
    cudaGetSymbolAddress(&pA2l, g_act2_lo);
    cudaGetSymbolAddress(&pW, g_w_hi);
    cudaGetSymbolAddress(&pWl, g_w_lo);
    cudaGetSymbolAddress(&pPT, g_pet_hi);
    cudaGetSymbolAddress(&pPTl, g_pet_lo);

    __nv_bfloat16* Ahi  = (__nv_bfloat16*)pA;
    __nv_bfloat16* Alo  = (__nv_bfloat16*)pAl;
    __nv_bfloat16* A2hi = (__nv_bfloat16*)pA2;
    __nv_bfloat16* A2lo = (__nv_bfloat16*)pA2l;
    __nv_bfloat16* Whi  = (__nv_bfloat16*)pW;
    __nv_bfloat16* Wlo  = (__nv_bfloat16*)pWl;
    __nv_bfloat16* PThi = (__nv_bfloat16*)pPT;
    __nv_bfloat16* PTlo = (__nv_bfloat16*)pPTl;
    __half* AVh  = (__half*)pA;      // attn out / LN2 out (fp16), reuses act_hi
    __half* FF1h = (__half*)pA2;     // fc1 out fp16
    __half* Whh  = (__half*)pW;      // fp16 weight hi
    __half* Whl  = (__half*)pWl;     // fp16 weight lo

    float* OUT1 = scratch + OFF_OUT1;
    __nv_bfloat16* QEb = (__nv_bfloat16*)(scratch + OFF_QE);

    cudaFuncSetAttribute(mma_gemm<true, true, false, true>,   cudaFuncAttributeMaxDynamicSharedMemorySize, MMA_SMEM);
    cudaFuncSetAttribute(mma_gemm<false, false, true, false>, cudaFuncAttributeMaxDynamicSharedMemorySize, MMA_SMEM);
    cudaFuncSetAttribute(mma_gemm_h<false, false, true, false>, cudaFuncAttributeMaxDynamicSharedMemorySize, H_SMEM);
    cudaFuncSetAttribute(mma_gemm_h<true, true, false, true>,   cudaFuncAttributeMaxDynamicSharedMemorySize, H_SMEM);
    cudaFuncSetAttribute(mma_gemm_h<true, false, true, false>,  cudaFuncAttributeMaxDynamicSharedMemorySize, H_SMEM);
    cudaFuncSetAttribute(attn_kernel, cudaFuncAttributeMaxDynamicSharedMemorySize, ATT_SMEM);

    // 0. pe^T split (bf16)
    pe_split_t_kernel<<<160, 256>>>(pos_emb, PThi, PTlo);
    // 1. LN1 + bf16 split
    ln_split_kernel<<<NROWS, 256>>>(x, ln1_g, ln1_b, Ahi, Alo);
    // 2. QKV GEMM (bf16 3-term): Q/K/V splits + nxt fp32 to d_out
    split_kernel<<<(QKV_N * EMB) / 1024, 256>>>(qkv_w, Whi, Wlo);
    mma_gemm<true, true, false, true><<<dim3(QKV_N / 128, NROWS / 128), 256, MMA_SMEM>>>(
        Ahi, Alo, Whi, Wlo, qkv_b, out + 8388608, A2hi, A2lo, NROWS, QKV_N, EMB);
    // 3. QE = Qsplit @ peT^T -> bf16
    mma_gemm<false, false, true, false><<<dim3(NJP / 128, 131072 / 128), 256, MMA_SMEM>>>(
        A2hi, A2lo, PThi, PTlo, 0, 0, QEb, 0, 131072, NJP, 64);
    // 4. HMMA attention -> AV fp16
    attn_kernel<<<dim3(8, 8, 32), 256, ATT_SMEM>>>(A2hi, A2lo, QEb, AVh);
    // 5. OUT1 = AV @ out_w^T + x  (fp16 GEMM)
    halfsplit_kernel<<<(EMB * EMB) / 1024, 256>>>(out_w, Whh, Whl);
    mma_gemm_h<false, false, true, false><<<dim3(EMB / 128, NROWS / 128), 256, H_SMEM>>>(
        AVh, Whh, Whl, 0, x, OUT1, 0, NROWS, EMB, EMB);
    // 6. LN2 -> fp16
    ln_half_kernel<<<NROWS, 256>>>(OUT1, ln2_g, ln2_b, AVh);
    // 7. FF1 = relu(H2 @ fc1_w^T + fc1_b) -> fp16
    halfsplit_kernel<<<(FFN_I * EMB) / 1024, 256>>>(fc1_w, Whh, Whl);
    mma_gemm_h<true, true, false, true><<<dim3(FFN_I / 128, NROWS / 128), 256, H_SMEM>>>(
        AVh, Whh, Whl, fc1_b, 0, 0, FF1h, NROWS, FFN_I, EMB);
    // 8. out = FF1 @ fc2_w^T + fc2_b + OUT1
    halfsplit_kernel<<<(EMB * FFN_I) / 1024, 256>>>(fc2_w, Whh, Whl);
    mma_gemm_h<true, false, true, false><<<dim3(EMB / 128, NROWS / 128), 256, H_SMEM>>>(
        FF1h, Whh, Whl, fc2_b, OUT1, out, 0, NROWS, EMB, FFN_I);
}

// round 14
// speedup vs baseline: 1.5291x; 1.0757x over previous
#include <cuda_runtime.h>
#include <cuda_bf16.h>
#include <cuda_fp16.h>
#include <math.h>
#include <stdint.h>

// ---------------------------------------------------------------------------
// Shapes: x (T=4096, B=2, E=1024); H=16 heads, dk=dv=64; window 512 (513 rel pos)
// QE: bf16 [r = (t*2+b)*16+h][j], row stride 640
// Qsplit: bf16 [(t*2+b)*16+h][64];  Ksplit/Vsplit: bf16 [(b*16+h)][t][64]
// nxt (d_out+8388608): fp32 [s][b*16+h][128] written by QKV GEMM epilogue
// All GEMMs fp16 A-single x W-split except QE (bf16 3-term, proven)
// ---------------------------------------------------------------------------
#define NROWS 8192
#define EMB   1024
#define QKV_N 3072
#define FFN_I 4096
#define NJ    513
#define NJP   640

#define OFF_OUT1   16777216ull
#define OFF_QE     92274688ull
#define SCRATCH_FLOATS 176160768ull

__device__ float g_scratch[SCRATCH_FLOATS];

__device__ __nv_bfloat16 g_act_hi[8388608];     // fp16 LN1 / AV / H2
__device__ __nv_bfloat16 g_act_lo[8388608];
__device__ __nv_bfloat16 g_act2_hi[33554432];   // bf16 Qsplit-hi early; fp16 FF1 later
__device__ __nv_bfloat16 g_act2_lo[33554432];
__device__ __nv_bfloat16 g_w_hi[4194304];
__device__ __nv_bfloat16 g_w_lo[4194304];
__device__ __nv_bfloat16 g_pet_hi[40960];
__device__ __nv_bfloat16 g_pet_lo[40960];
__device__ __nv_bfloat16 g_k_hi[8388608];
__device__ __nv_bfloat16 g_k_lo[8388608];
__device__ __nv_bfloat16 g_v_hi[8388608];
__device__ __nv_bfloat16 g_v_lo[8388608];

__device__ __forceinline__ uint32_t smem_u32(const void* p) {
    uint32_t a;
    asm("{ .reg .u64 t; cvta.to.shared.u64 t, %1; cvt.u32.u64 %0, t; }" : "=r"(a) : "l"(p));
    return a;
}
__device__ __forceinline__ void split1(float v, __nv_bfloat16& h, __nv_bfloat16& l) {
    h = __float2bfloat16(v);
    l = __float2bfloat16(v - __bfloat162float(h));
}

// ---------------------------------------------------------------------------
// fp16 weight split
__global__ __launch_bounds__(256) void halfsplit_kernel(
    const float* __restrict__ X, __half* __restrict__ Hi,
    __half* __restrict__ Lo)
{
    int i4 = blockIdx.x * 256 + threadIdx.x;
    float4 v = ((const float4*)X)[i4];
    __half h0 = __float2half_rn(v.x), h1 = __float2half_rn(v.y);
    __half h2 = __float2half_rn(v.z), h3 = __float2half_rn(v.w);
    __half l0 = __float2half_rn(v.x - __half2float(h0));
    __half l1 = __float2half_rn(v.y - __half2float(h1));
    __half l2 = __float2half_rn(v.z - __half2float(h2));
    __half l3 = __float2half_rn(v.w - __half2float(h3));
    __half2 H0; H0.x = h0; H0.y = h1;
    __half2 H1; H1.x = h2; H1.y = h3;
    __half2 L0; L0.x = l0; L0.y = l1;
    __half2 L1; L1.x = l2; L1.y = l3;
    ((__half2*)Hi)[i4 * 2]     = H0;
    ((__half2*)Hi)[i4 * 2 + 1] = H1;
    ((__half2*)Lo)[i4 * 2]     = L0;
    ((__half2*)Lo)[i4 * 2 + 1] = L1;
}

__global__ __launch_bounds__(256) void pe_split_t_kernel(
    const float* __restrict__ pe, __nv_bfloat16* __restrict__ Hi,
    __nv_bfloat16* __restrict__ Lo)
{
    int idx = blockIdx.x * 256 + threadIdx.x;
    int k = idx & 63;
    int j = idx >> 6;
    float v = (j < NJ) ? pe[(size_t)k * NJ + j] : 0.f;
    __nv_bfloat16 h, l;
    split1(v, h, l);
    Hi[idx] = h;
    Lo[idx] = l;
}

// LN -> fp16 single
__global__ __launch_bounds__(256) void ln_half_kernel(
    const float* __restrict__ X, const float* __restrict__ G,
    const float* __restrict__ Bt, __half* __restrict__ H)
{
    __shared__ float ssum[8], ssq[8], smv[2];
    int row = blockIdx.x;
    int tid = threadIdx.x;
    const float4* xr = (const float4*)(X + (size_t)row * EMB);
    float4 v = xr[tid];
    float s = v.x + v.y + v.z + v.w;
    float q = v.x*v.x + v.y*v.y + v.z*v.z + v.w*v.w;
#pragma unroll
    for (int o = 16; o > 0; o >>= 1) {
        s += __shfl_xor_sync(0xffffffffu, s, o);
        q += __shfl_xor_sync(0xffffffffu, q, o);
    }
    if ((tid & 31) == 0) { ssum[tid >> 5] = s; ssq[tid >> 5] = q; }
    __syncthreads();
    if (tid == 0) {
        float S = 0.f, Q = 0.f;
#pragma unroll
        for (int i = 0; i < 8; i++) { S += ssum[i]; Q += ssq[i]; }
        float mean = S * (1.f / EMB);
        float var  = Q * (1.f / EMB) - mean * mean;
        smv[0] = mean;
        smv[1] = rsqrtf(var + 1e-5f);
    }
    __syncthreads();
    float mean = smv[0], inv = smv[1];
    float4 g = ((const float4*)G)[tid];
    float4 b = ((const float4*)Bt)[tid];
    __half2 a0 = __floats2half2_rn((v.x - mean) * inv * g.x + b.x,
                                   (v.y - mean) * inv * g.y + b.y);
    __half2 a1 = __floats2half2_rn((v.z - mean) * inv * g.z + b.z,
                                   (v.w - mean) * inv * g.w + b.w);
    size_t i4 = (size_t)row * 256 + tid;
    ((__half2*)H)[i4 * 2]     = a0;
    ((__half2*)H)[i4 * 2 + 1] = a1;
}

// ---------------------------------------------------------------------------
// common MMA helpers
// ---------------------------------------------------------------------------
__device__ __forceinline__ void cp16(uint32_t dst, const void* src) {
    asm volatile("cp.async.cg.shared.global [%0], [%1], 16;" :: "r"(dst), "l"(src));
}
__device__ __forceinline__ void ldm4(uint32_t* r, uint32_t addr) {
    asm volatile("ldmatrix.sync.aligned.m8n8.x4.shared.b16 {%0,%1,%2,%3}, [%4];"
                 : "=r"(r[0]), "=r"(r[1]), "=r"(r[2]), "=r"(r[3]) : "r"(addr));
}
__device__ __forceinline__ void mma16816(float* c, const uint32_t* a,
                                         uint32_t b0, uint32_t b1) {
    asm volatile(
        "mma.sync.aligned.m16n8k16.row.col.f32.bf16.bf16.f32 "
        "{%0,%1,%2,%3}, {%4,%5,%6,%7}, {%8,%9}, {%0,%1,%2,%3};"
        : "+f"(c[0]), "+f"(c[1]), "+f"(c[2]), "+f"(c[3])
        : "r"(a[0]), "r"(a[1]), "r"(a[2]), "r"(a[3]), "r"(b0), "r"(b1));
}
__device__ __forceinline__ void mma16816h(float* c, const uint32_t* a,
                                          uint32_t b0, uint32_t b1) {
    asm volatile(
        "mma.sync.aligned.m16n8k16.row.col.f32.f16.f16.f32 "
        "{%0,%1,%2,%3}, {%4,%5,%6,%7}, {%8,%9}, {%0,%1,%2,%3};"
        : "+f"(c[0]), "+f"(c[1]), "+f"(c[2]), "+f"(c[3])
        : "r"(a[0]), "r"(a[1]), "r"(a[2]), "r"(a[3]), "r"(b0), "r"(b1));
}

// ---------------------------------------------------------------------------
// bf16 split GEMM — QE only (HALFO bf16 out)
// ---------------------------------------------------------------------------
#define STAGE_BYTES 32768
#define MMA_SMEM    98304

__global__ __launch_bounds__(256, 2) void mma_gemm_qe(
    const __nv_bfloat16* __restrict__ Ah, const __nv_bfloat16* __restrict__ Al,
    const __nv_bfloat16* __restrict__ Bh, const __nv_bfloat16* __restrict__ Bl,
    __nv_bfloat16* __restrict__ OHi, int M, int N, int K)
{
    extern __shared__ char smem[];
    const uint32_t sbase = smem_u32(smem);
    const int tid = threadIdx.x;
    const int wid = tid >> 5, lane = tid & 31;
    const int bm = blockIdx.y * 128, bn = blockIdx.x * 128;
    const int m0w = (wid >> 2) * 64, n0w = (wid & 3) * 32;

    const int r0 = tid >> 2,         c0 = tid & 3;
    const int r1 = (tid + 256) >> 2, c1 = (tid + 256) & 3;
    const uint32_t so0 = (uint32_t)(r0 * 64 + ((c0 ^ ((r0 >> 1) & 3)) * 16));
    const uint32_t so1 = (uint32_t)(r1 * 64 + ((c1 ^ ((r1 >> 1) & 3)) * 16));
    const size_t offA0 = (size_t)(bm + r0) * K + c0 * 8;
    const size_t offA1 = (size_t)(bm + r1) * K + c1 * 8;
    const size_t offB0 = (size_t)(bn + r0) * K + c0 * 8;
    const size_t offB1 = (size_t)(bn + r1) * K + c1 * 8;

    float acc[4][4][4];
#pragma unroll
    for (int a = 0; a < 4; a++)
#pragma unroll
        for (int n = 0; n < 4; n++)
#pragma unroll
            for (int q = 0; q < 4; q++) acc[a][n][q] = 0.f;

    const int nt = K >> 5;
    const int rowA_base = m0w + (lane & 15);
    const int rowB_base = n0w + (lane & 15);
    const int chsel = lane >> 4;

#define LOAD_STAGE(s, k0)                                                     \
    do {                                                                      \
        uint32_t d = sbase + (s) * STAGE_BYTES;                               \
        cp16(d + so0,          Ah + offA0 + (k0));                            \
        cp16(d + so1,          Ah + offA1 + (k0));                            \
        cp16(d + 8192  + so0,  Al + offA0 + (k0));                            \
        cp16(d + 8192  + so1,  Al + offA1 + (k0));                            \
        cp16(d + 16384 + so0,  Bh + offB0 + (k0));                            \
        cp16(d + 16384 + so1,  Bh + offB1 + (k0));                            \
        cp16(d + 24576 + so0,  Bl + offB0 + (k0));                            \
        cp16(d + 24576 + so1,  Bl + offB1 + (k0));                            \
    } while (0)

    LOAD_STAGE(0, 0);
    asm volatile("cp.async.commit_group;");
    if (nt > 1) LOAD_STAGE(1, 32);
    asm volatile("cp.async.commit_group;");

    int stage = 0;
    for (int i = 0; i < nt; i++) {
        asm volatile("cp.async.wait_group 1;");
        __syncthreads();

        uint32_t base = sbase + stage * STAGE_BYTES;
#pragma unroll
        for (int ks = 0; ks < 2; ks++) {
            const int chunk = ks * 2 + chsel;
            uint32_t bh[2][4], bl[2][4];
#pragma unroll
            for (int p = 0; p < 2; p++) {
                int row = rowB_base + p * 16;
                uint32_t ad = base + 16384 + (uint32_t)(row * 64 + ((chunk ^ ((row >> 1) & 3)) * 16));
                ldm4(bh[p], ad);
                ldm4(bl[p], ad + 8192);
            }
#pragma unroll
            for (int a = 0; a < 4; a++) {
                uint32_t ah[4], al[4];
                int row = rowA_base + a * 16;
                uint32_t ad = base + (uint32_t)(row * 64 + ((chunk ^ ((row >> 1) & 3)) * 16));
                ldm4(ah, ad);
                ldm4(al, ad + 8192);
#pragma unroll
                for (int n = 0; n < 4; n++) {
                    int p = n >> 1, q = n & 1;
                    mma16816(acc[a][n], ah, bh[p][q], bh[p][q + 2]);
                    mma16816(acc[a][n], ah, bl[p][q], bl[p][q + 2]);
                    mma16816(acc[a][n], al, bh[p][q], bh[p][q + 2]);
                }
            }
        }
        int nx = i + 2;
        if (nx < nt) {
            int ns = stage + 2; if (ns >= 3) ns -= 3;
            LOAD_STAGE(ns, nx << 5);
        }
        asm volatile("cp.async.commit_group;");
        if (++stage == 3) stage = 0;
    }
#undef LOAD_STAGE

    const int g = lane >> 2, t = lane & 3;
#pragma unroll
    for (int a = 0; a < 4; a++) {
#pragma unroll
        for (int n = 0; n < 4; n++) {
            int row0 = bm + m0w + a * 16 + g;
            int col  = bn + n0w + n * 8 + 2 * t;
            __nv_bfloat162 h0, h1;
            h0.x = __float2bfloat16(acc[a][n][0]);
            h0.y = __float2bfloat16(acc[a][n][1]);
            h1.x = __float2bfloat16(acc[a][n][2]);
            h1.y = __float2bfloat16(acc[a][n][3]);
            *(__nv_bfloat162*)(OHi + (size_t)row0 * N + col)       = h0;
            *(__nv_bfloat162*)(OHi + (size_t)(row0 + 8) * N + col) = h1;
        }
    }
}

// ---------------------------------------------------------------------------
// fp16 GEMM: C = A(f16) * (Bh+Bl)(f16)^T — 2 MMAs/tile.
// H16O: fp16 out. RES: +Res fp32. QOUT/NXTO: QKV epilogue (splits + nxt).
// ---------------------------------------------------------------------------
#define H_STAGE 24576
#define H_SMEM  73728

template<bool BIAS, bool RELU, bool RES, bool H16O, bool QOUT, bool NXTO>
__global__ __launch_bounds__(256, 2) void mma_gemm_h(
    const __half* __restrict__ Ax,
    const __half* __restrict__ Bh_, const __half* __restrict__ Bl_,
    const float* __restrict__ bias, const float* __restrict__ Res,
    float* __restrict__ C, __half* __restrict__ OH,
    __nv_bfloat16* __restrict__ QHi, __nv_bfloat16* __restrict__ QLo,
    int M, int N, int K)
{
    extern __shared__ char smem[];
    const uint32_t sbase = smem_u32(smem);
    const int tid = threadIdx.x;
    const int wid = tid >> 5, lane = tid & 31;
    const int bm = blockIdx.y * 128, bn = blockIdx.x * 128;
    const int m0w = (wid >> 2) * 64, n0w = (wid & 3) * 32;

    const int r0 = tid >> 2,         c0 = tid & 3;
    const int r1 = (tid + 256) >> 2, c1 = (tid + 256) & 3;
    const uint32_t so0 = (uint32_t)(r0 * 64 + ((c0 ^ ((r0 >> 1) & 3)) * 16));
    const uint32_t so1 = (uint32_t)(r1 * 64 + ((c1 ^ ((r1 >> 1) & 3)) * 16));
    const size_t offA0 = (size_t)(bm + r0) * K + c0 * 8;
    const size_t offA1 = (size_t)(bm + r1) * K + c1 * 8;
    const size_t offB0 = (size_t)(bn + r0) * K + c0 * 8;
    const size_t offB1 = (size_t)(bn + r1) * K + c1 * 8;

    float acc[4][4][4];
#pragma unroll
    for (int a = 0; a < 4; a++)
#pragma unroll
        for (int n = 0; n < 4; n++)
#pragma unroll
            for (int q = 0; q < 4; q++) acc[a][n][q] = 0.f;

    const int nt = K >> 5;
    const int rowA_base = m0w + (lane & 15);
    const int rowB_base = n0w + (lane & 15);
    const int chsel = lane >> 4;

#define LOAD_STAGE_H(s, k0)                                                   \
    do {                                                                      \
        uint32_t d = sbase + (s) * H_STAGE;                                   \
        cp16(d + so0,          Ax  + offA0 + (k0));                           \
        cp16(d + so1,          Ax  + offA1 + (k0));                           \
        cp16(d + 8192  + so0,  Bh_ + offB0 + (k0));                           \
        cp16(d + 8192  + so1,  Bh_ + offB1 + (k0));                           \
        cp16(d + 16384 + so0,  Bl_ + offB0 + (k0));                           \
        cp16(d + 16384 + so1,  Bl_ + offB1 + (k0));                           \
    } while (0)

    LOAD_STAGE_H(0, 0);
    asm volatile("cp.async.commit_group;");
    if (nt > 1) LOAD_STAGE_H(1, 32);
    asm volatile("cp.async.commit_group;");

    int stage = 0;
    for (int i = 0; i < nt; i++) {
        asm volatile("cp.async.wait_group 1;");
        __syncthreads();

        uint32_t base = sbase + stage * H_STAGE;
#pragma unroll
        for (int ks = 0; ks < 2; ks++) {
            const int chunk = ks * 2 + chsel;
            uint32_t bh[2][4], bl[2][4];
#pragma unroll
            for (int p = 0; p < 2; p++) {
                int row = rowB_base + p * 16;
                uint32_t ad = base + 8192 + (uint32_t)(row * 64 + ((chunk ^ ((row >> 1) & 3)) * 16));
                ldm4(bh[p], ad);
                ldm4(bl[p], ad + 8192);
            }
#pragma unroll
            for (int a = 0; a < 4; a++) {
                uint32_t ah[4];
                int row = rowA_base + a * 16;
                uint32_t ad = base + (uint32_t)(row * 64 + ((chunk ^ ((row >> 1) & 3)) * 16));
                ldm4(ah, ad);
#pragma unroll
                for (int n = 0; n < 4; n++) {
                    int p = n >> 1, q = n & 1;
                    mma16816h(acc[a][n], ah, bh[p][q], bh[p][q + 2]);
                    mma16816h(acc[a][n], ah, bl[p][q], bl[p][q + 2]);
                }
            }
        }
        int nx = i + 2;
        if (nx < nt) {
            int ns = stage + 2; if (ns >= 3) ns -= 3;
            LOAD_STAGE_H(ns, nx << 5);
        }
        asm volatile("cp.async.commit_group;");
        if (++stage == 3) stage = 0;
    }
#undef LOAD_STAGE_H

    const int g = lane >> 2, t = lane & 3;
#pragma unroll
    for (int a = 0; a < 4; a++) {
#pragma unroll
        for (int n = 0; n < 4; n++) {
            int row0 = bm + m0w + a * 16 + g;
            int col  = bn + n0w + n * 8 + 2 * t;
            float v0 = acc[a][n][0], v1 = acc[a][n][1];
            float v2 = acc[a][n][2], v3 = acc[a][n][3];
            if (BIAS) {
                float b0 = bias[col], b1 = bias[col + 1];
                v0 += b0; v1 += b1; v2 += b0; v3 += b1;
            }
            if (RELU) {
                v0 = fmaxf(v0, 0.f); v1 = fmaxf(v1, 0.f);
                v2 = fmaxf(v2, 0.f); v3 = fmaxf(v3, 0.f);
            }
            if (RES) {
                const float2 q0 = *(const float2*)(Res + (size_t)row0 * N + col);
                const float2 q1 = *(const float2*)(Res + (size_t)(row0 + 8) * N + col);
                v0 += q0.x; v1 += q0.y; v2 += q1.x; v3 += q1.y;
            }
            if (H16O) {
                __half2 h0 = __floats2half2_rn(v0, v1);
                __half2 h1 = __floats2half2_rn(v2, v3);
                *(__half2*)(OH + (size_t)row0 * N + col)       = h0;
                *(__half2*)(OH + (size_t)(row0 + 8) * N + col) = h1;
            } else if (!QOUT) {
                float2 o0; o0.x = v0; o0.y = v1;
                float2 o1; o1.x = v2; o1.y = v3;
                *(float2*)(C + (size_t)row0 * N + col)       = o0;
                *(float2*)(C + (size_t)(row0 + 8) * N + col) = o1;
            }
            if (QOUT) {
                int hh = col / 192;
                int cc = col - hh * 192;
                __nv_bfloat162 h0, h1, l0, l1;
                split1(v0, h0.x, l0.x); split1(v1, h0.y, l0.y);
                split1(v2, h1.x, l1.x); split1(v3, h1.y, l1.y);
                int b0_ = row0 & 1, t0_ = row0 >> 1;
                int t1_ = (row0 + 8) >> 1;
                if (cc < 64) {
                    size_t q0o = ((size_t)row0 * 16 + hh) * 64 + cc;
                    size_t q1o = ((size_t)(row0 + 8) * 16 + hh) * 64 + cc;
                    *(__nv_bfloat162*)(QHi + q0o) = h0; *(__nv_bfloat162*)(QLo + q0o) = l0;
                    *(__nv_bfloat162*)(QHi + q1o) = h1; *(__nv_bfloat162*)(QLo + q1o) = l1;
                } else if (cc < 128) {
                    size_t k0o = (((size_t)(b0_ * 16 + hh)) * 4096 + t0_) * 64 + (cc - 64);
                    size_t k1o = (((size_t)(b0_ * 16 + hh)) * 4096 + t1_) * 64 + (cc - 64);
                    *(__nv_bfloat162*)(g_k_hi + k0o) = h0; *(__nv_bfloat162*)(g_k_lo + k0o) = l0;
                    *(__nv_bfloat162*)(g_k_hi + k1o) = h1; *(__nv_bfloat162*)(g_k_lo + k1o) = l1;
                } else {
                    size_t v0o = (((size_t)(b0_ * 16 + hh)) * 4096 + t0_) * 64 + (cc - 128);
                    size_t v1o = (((size_t)(b0_ * 16 + hh)) * 4096 + t1_) * 64 + (cc - 128);
                    *(__nv_bfloat162*)(g_v_hi + v0o) = h0; *(__nv_bfloat162*)(g_v_lo + v0o) = l0;
                    *(__nv_bfloat162*)(g_v_hi + v1o) = h1; *(__nv_bfloat162*)(g_v_lo + v1o) = l1;
                }
                if (NXTO && cc >= 64) {
                    if (t0_ >= 3584) {
                        size_t o = (((size_t)(t0_ - 3584) * 32) + b0_ * 16 + hh) * 128 + (cc - 64);
                        float2 w; w.x = v0; w.y = v1;
                        *(float2*)(C + o) = w;
                    }
                    if (t1_ >= 3584) {
                        size_t o = (((size_t)(t1_ - 3584) * 32) + b0_ * 16 + hh) * 128 + (cc - 64);
                        float2 w; w.x = v2; w.y = v3;
                        *(float2*)(C + o) = w;
                    }
                }
            }
        }
    }
}

// ---------------------------------------------------------------------------
// HMMA sliding-window attention (r11/r13 body, fp16 out)
// ---------------------------------------------------------------------------
#define AT_QH 0
#define AT_QL 8192
#define AT_KH 16384
#define AT_KL 24576
#define AT_VH 32768
#define AT_VL 40960
#define AT_VTH 49152
#define AT_VTL 57344
#define AT_S   65536
#define AT_PH  82944
#define AT_PL  91136
#define AT_CORR 99328
#define AT_LINV 99584
#define ATT_SMEM 99840

__global__ __launch_bounds__(256, 2) void attn_kernel(
    const __nv_bfloat16* __restrict__ Qhi, const __nv_bfloat16* __restrict__ Qlo,
    const __nv_bfloat16* __restrict__ QEb, __half* __restrict__ OH)
{
    extern __shared__ char smem[];
    const uint32_t sbase = smem_u32(smem);
    float* Sf    = (float*)(smem + AT_S);
    float* corrS = (float*)(smem + AT_CORR);
    float* linvS = (float*)(smem + AT_LINV);

    const int s0 = blockIdx.x * 64;
    const int gg = blockIdx.y;
    const int bh = blockIdx.z;
    const int b = bh >> 4, h = bh & 15;
    const int tid = threadIdx.x;
    const int lane = tid & 31, wid = tid >> 5;
    const int tx = tid & 15, ty = tid >> 4;
    const int tbase = gg * 512 + s0;
    const int base_key = tbase - 512;
    const int bh_ = b * 16 + h;

    const int mrow0 = (wid >> 1) * 16;
    const int ncol0 = (wid & 1) * 32;
    const int lg = lane >> 2, lt = lane & 3;

    const int cr0 = tid >> 3, cc0 = tid & 7;
    const int cr1 = (tid + 256) >> 3, cc1 = (tid + 256) & 7;

#define CPT(dstoff, srcp, stride)                                                        \
    do {                                                                                 \
        cp16(sbase + (dstoff) + cr0 * 128 + ((cc0 ^ (cr0 & 7)) * 16),                    \
             (srcp) + (size_t)cr0 * (stride) + cc0 * 8);                                 \
        cp16(sbase + (dstoff) + cr1 * 128 + ((cc1 ^ (cr1 & 7)) * 16),                    \
             (srcp) + (size_t)cr1 * (stride) + cc1 * 8);                                 \
    } while (0)

    {
        const size_t qoff = (((size_t)tbase * 2 + b) * 16 + h) * 64;
        CPT(AT_QH, Qhi + qoff, 2048);
        CPT(AT_QL, Qlo + qoff, 2048);
        int u0 = base_key; if (u0 < 0) u0 = 0;
        const size_t koff = ((size_t)bh_ * 4096 + u0) * 64;
        CPT(AT_KH, g_k_hi + koff, 64);
        CPT(AT_KL, g_k_lo + koff, 64);
        CPT(AT_VH, g_v_hi + koff, 64);
        CPT(AT_VL, g_v_lo + koff, 64);
        asm volatile("cp.async.commit_group;");
    }

    float O[4][4];
    float mrow[4], lrow[4];
#pragma unroll
    for (int r = 0; r < 4; r++) {
        mrow[r] = -1e30f; lrow[r] = 0.f;
#pragma unroll
        for (int c = 0; c < 4; c++) O[r][c] = 0.f;
    }
    size_t qe_base[4];
#pragma unroll
    for (int r = 0; r < 4; r++) {
        int t = tbase + ty * 4 + r;
        qe_base[r] = ((size_t)(t * 2 + b) * 16 + h) * NJP;
    }

    for (int kt = 0; kt < 9; kt++) {
        asm volatile("cp.async.wait_group 0;");
        __syncthreads();

        {
            int d0 = (tid & 15) * 4, kk0 = (tid >> 4) * 4;
#pragma unroll
            for (int tile = 0; tile < 2; tile++) {
                uint32_t inb = tile ? AT_VL : AT_VH;
                uint32_t outb = tile ? AT_VTL : AT_VTH;
                uint16_t m[4][4];
#pragma unroll
                for (int i = 0; i < 4; i++) {
                    int row = kk0 + i;
                    uint32_t off = inb + row * 128 + (((d0 >> 3) ^ (row & 7)) << 4) + ((d0 & 7) * 2);
                    uint2 v = *(uint2*)(smem + off);
                    uint16_t* pv = (uint16_t*)&v;
                    m[i][0] = pv[0]; m[i][1] = pv[1]; m[i][2] = pv[2]; m[i][3] = pv[3];
                }
#pragma unroll
                for (int j = 0; j < 4; j++) {
                    int rd = d0 + j;
                    uint32_t o2 = outb + rd * 128 + (((kk0 >> 3) ^ (rd & 7)) << 4) + ((kk0 & 7) * 2);
                    uint16_t o[4] = {m[0][j], m[1][j], m[2][j], m[3][j]};
                    *(uint2*)(smem + o2) = *(uint2*)o;
                }
            }
        }
        __syncthreads();

        float sacc[4][4];
#pragma unroll
        for (int n = 0; n < 4; n++)
#pragma unroll
            for (int q = 0; q < 4; q++) sacc[n][q] = 0.f;
#pragma unroll
        for (int ks = 0; ks < 4; ks++) {
            int chunk = 2 * ks + (lane >> 4);
            int rq = mrow0 + (lane & 15);
            uint32_t aq = sbase + AT_QH + rq * 128 + ((chunk ^ (rq & 7)) << 4);
            uint32_t qh[4], ql[4];
            ldm4(qh, aq); ldm4(ql, aq + 8192);
            uint32_t khf[2][4], klf[2][4];
#pragma unroll
            for (int p = 0; p < 2; p++) {
                int rk = ncol0 + p * 16 + (lane & 15);
                uint32_t ak = sbase + AT_KH + rk * 128 + ((chunk ^ (rk & 7)) << 4);
                ldm4(khf[p], ak); ldm4(klf[p], ak + 8192);
            }
#pragma unroll
            for (int n = 0; n < 4; n++) {
                int p = n >> 1, q = n & 1;
                mma16816(sacc[n], qh, khf[p][q], khf[p][q + 2]);
                mma16816(sacc[n], qh, klf[p][q], klf[p][q + 2]);
                mma16816(sacc[n], ql, khf[p][q], khf[p][q + 2]);
            }
        }
#pragma unroll
        for (int n = 0; n < 4; n++) {
            int si = mrow0 + lg, ck = ncol0 + n * 8 + lt * 2;
            float2 a0; a0.x = sacc[n][0]; a0.y = sacc[n][1];
            float2 a1; a1.x = sacc[n][2]; a1.y = sacc[n][3];
            *(float2*)&Sf[si * 68 + ck]       = a0;
            *(float2*)&Sf[(si + 8) * 68 + ck] = a1;
        }
        __syncthreads();

        float acc[4][4];
#pragma unroll
        for (int r = 0; r < 4; r++) {
            float4 sv = *(const float4*)&Sf[(ty * 4 + r) * 68 + tx * 4];
            acc[r][0] = sv.x; acc[r][1] = sv.y; acc[r][2] = sv.z; acc[r][3] = sv.w;
        }
#pragma unroll
        for (int r = 0; r < 4; r++) {
            int si = ty * 4 + r;
#pragma unroll
            for (int c = 0; c < 4; c++) {
                int kk = tx * 4 + c;
                int j = kt * 64 + kk - si;
                int u = base_key + kt * 64 + kk;
                if (j >= 0 && j <= 512 && u >= 0)
                    acc[r][c] = (acc[r][c] + __bfloat162float(QEb[qe_base[r] + j])) * 0.125f;
                else
                    acc[r][c] = -1e30f;
            }
        }
        float corr[4];
#pragma unroll
        for (int r = 0; r < 4; r++) {
            float tm = fmaxf(fmaxf(acc[r][0], acc[r][1]), fmaxf(acc[r][2], acc[r][3]));
#pragma unroll
            for (int o = 1; o < 16; o <<= 1)
                tm = fmaxf(tm, __shfl_xor_sync(0xffffffffu, tm, o));
            float mnew = fmaxf(mrow[r], tm);
            corr[r] = __expf(mrow[r] - mnew);
            float rs = 0.f;
#pragma unroll
            for (int c = 0; c < 4; c++) {
                float p = (acc[r][c] > -5e29f) ? __expf(acc[r][c] - mnew) : 0.f;
                acc[r][c] = p;
                rs += p;
            }
#pragma unroll
            for (int o = 1; o < 16; o <<= 1)
                rs += __shfl_xor_sync(0xffffffffu, rs, o);
            lrow[r] = lrow[r] * corr[r] + rs;
            mrow[r] = mnew;
        }
#pragma unroll
        for (int r = 0; r < 4; r++) {
            int si = ty * 4 + r;
            uint32_t poff = si * 128 + ((((tx >> 1) ^ (si & 7))) << 4) + ((tx & 1) * 8);
            uint16_t hs[4], ls[4];
#pragma unroll
            for (int c = 0; c < 4; c++) {
                __nv_bfloat16 hh_, ll_;
                split1(acc[r][c], hh_, ll_);
                hs[c] = *(uint16_t*)&hh_;
                ls[c] = *(uint16_t*)&ll_;
            }
            *(uint2*)(smem + AT_PH + poff) = *(uint2*)hs;
            *(uint2*)(smem + AT_PL + poff) = *(uint2*)ls;
        }
        if (tx == 0) {
#pragma unroll
            for (int r = 0; r < 4; r++) corrS[ty * 4 + r] = corr[r];
        }
        __syncthreads();

        if (kt < 8) {
            int u0 = base_key + (kt + 1) * 64; if (u0 < 0) u0 = 0;
            const size_t koff = ((size_t)bh_ * 4096 + u0) * 64;
            CPT(AT_KH, g_k_hi + koff, 64);
            CPT(AT_KL, g_k_lo + koff, 64);
            CPT(AT_VH, g_v_hi + koff, 64);
            CPT(AT_VL, g_v_lo + koff, 64);
        }
        asm volatile("cp.async.commit_group;");

        float cA = corrS[mrow0 + lg], cB = corrS[mrow0 + lg + 8];
#pragma unroll
        for (int n = 0; n < 4; n++) {
            O[n][0] *= cA; O[n][1] *= cA; O[n][2] *= cB; O[n][3] *= cB;
        }
#pragma unroll
        for (int ks = 0; ks < 4; ks++) {
            int chunk = 2 * ks + (lane >> 4);
            int rp = mrow0 + (lane & 15);
            uint32_t ap = sbase + AT_PH + rp * 128 + ((chunk ^ (rp & 7)) << 4);
            uint32_t ph[4], pl[4];
            ldm4(ph, ap); ldm4(pl, ap + 8192);
            uint32_t vhf[2][4], vlf[2][4];
#pragma unroll
            for (int p = 0; p < 2; p++) {
                int rv = ncol0 + p * 16 + (lane & 15);
                uint32_t av = sbase + AT_VTH + rv * 128 + ((chunk ^ (rv & 7)) << 4);
                ldm4(vhf[p], av); ldm4(vlf[p], av + 8192);
            }
#pragma unroll
            for (int n = 0; n < 4; n++) {
                int p = n >> 1, q = n & 1;
                mma16816(O[n], ph, vhf[p][q], vhf[p][q + 2]);
                mma16816(O[n], ph, vlf[p][q], vlf[p][q + 2]);
                mma16816(O[n], pl, vhf[p][q], vhf[p][q + 2]);
            }
        }
    }
#undef CPT

    if (tx == 0) {
#pragma unroll
        for (int r = 0; r < 4; r++) linvS[ty * 4 + r] = 1.f / lrow[r];
    }
    __syncthreads();
    float li0 = linvS[mrow0 + lg], li1 = linvS[mrow0 + lg + 8];
#pragma unroll
    for (int n = 0; n < 4; n++) {
        int si = mrow0 + lg, d = ncol0 + n * 8 + lt * 2;
        int t0 = tbase + si, t1 = t0 + 8;
        size_t o0 = ((size_t)(t0 * 2 + b)) * 1024 + h * 64 + d;
        size_t o1 = ((size_t)(t1 * 2 + b)) * 1024 + h * 64 + d;
        __half2 h0 = __floats2half2_rn(O[n][0] * li0, O[n][1] * li0);
        __half2 h1 = __floats2half2_rn(O[n][2] * li1, O[n][3] * li1);
        *(__half2*)(OH + o0) = h0;
        *(__half2*)(OH + o1) = h1;
    }
}

// ---------------------------------------------------------------------------
extern "C" void kernel_launch(void* const* d_in, const int* in_sizes, int n_in,
                              void* d_out, int out_size)
{
    const float* x      = (const float*)d_in[0];
    const float* ln1_g  = (const float*)d_in[1];
    const float* ln1_b  = (const float*)d_in[2];
    const float* qkv_w  = (const float*)d_in[3];
    const float* qkv_b  = (const float*)d_in[4];
    const float* pos_emb= (const float*)d_in[5];
    const float* out_w  = (const float*)d_in[6];
    const float* ln2_g  = (const float*)d_in[7];
    const float* ln2_b  = (const float*)d_in[8];
    const float* fc1_w  = (const float*)d_in[9];
    const float* fc1_b  = (const float*)d_in[10];
    const float* fc2_w  = (const float*)d_in[11];
    const float* fc2_b  = (const float*)d_in[12];
    float* out = (float*)d_out;

    float* scratch = 0;
    cudaGetSymbolAddress((void**)&scratch, g_scratch);
    void *pA, *pA2, *pA2l, *pW, *pWl, *pPT, *pPTl;
    cudaGetSymbolAddress(&pA, g_act_hi);
    cudaGetSymbolAddress(&pA2, g_act2_hi);
    cudaGetSymbolAddress(&pA2l, g_act2_lo);
    cudaGetSymbolAddress(&pW, g_w_hi);
    cudaGetSymbolAddress(&pWl, g_w_lo);
    cudaGetSymbolAddress(&pPT, g_pet_hi);
    cudaGetSymbolAddress(&pPTl, g_pet_lo);

    __nv_bfloat16* A2hi = (__nv_bfloat16*)pA2;
    __nv_bfloat16* A2lo = (__nv_bfloat16*)pA2l;
    __nv_bfloat16* PThi = (__nv_bfloat16*)pPT;
    __nv_bfloat16* PTlo = (__nv_bfloat16*)pPTl;
    __half* AVh  = (__half*)pA;      // LN1 out / attn out / LN2 out (fp16)
    __half* FF1h = (__half*)pA2;     // fc1 out fp16 (after QE consumed Qsplit)
    __half* Whh  = (__half*)pW;
    __half* Whl  = (__half*)pWl;

    float* OUT1 = scratch + OFF_OUT1;
    __nv_bfloat16* QEb = (__nv_bfloat16*)(scratch + OFF_QE);

    cudaFuncSetAttribute(mma_gemm_qe, cudaFuncAttributeMaxDynamicSharedMemorySize, MMA_SMEM);
    cudaFuncSetAttribute(mma_gemm_h<true, false, false, false, true, true>,    cudaFuncAttributeMaxDynamicSharedMemorySize, H_SMEM);
    cudaFuncSetAttribute(mma_gemm_h<false, false, true, false, false, false>,  cudaFuncAttributeMaxDynamicSharedMemorySize, H_SMEM);
    cudaFuncSetAttribute(mma_gemm_h<true, true, false, true, false, false>,    cudaFuncAttributeMaxDynamicSharedMemorySize, H_SMEM);
    cudaFuncSetAttribute(mma_gemm_h<true, false, true, false, false, false>,   cudaFuncAttributeMaxDynamicSharedMemorySize, H_SMEM);
    cudaFuncSetAttribute(attn_kernel, cudaFuncAttributeMaxDynamicSharedMemorySize, ATT_SMEM);

    // 0. pe^T split (bf16)
    pe_split_t_kernel<<<160, 256>>>(pos_emb, PThi, PTlo);
    // 1. LN1 -> fp16
    ln_half_kernel<<<NROWS, 256>>>(x, ln1_g, ln1_b, AVh);
    // 2. QKV GEMM (fp16 2-term): Q/K/V bf16 splits + nxt fp32 to d_out
    halfsplit_kernel<<<(QKV_N * EMB) / 1024, 256>>>(qkv_w, Whh, Whl);
    mma_gemm_h<true, false, false, false, true, true><<<dim3(QKV_N / 128, NROWS / 128), 256, H_SMEM>>>(
        AVh, Whh, Whl, qkv_b, 0, out + 8388608, 0, A2hi, A2lo, NROWS, QKV_N, EMB);
    // 3. QE = Qsplit @ peT^T -> bf16  (bf16 3-term)
    mma_gemm_qe<<<dim3(NJP / 128, 131072 / 128), 256, MMA_SMEM>>>(
        A2hi, A2lo, PThi, PTlo, QEb, 131072, NJP, 64);
    // 4. HMMA attention -> AV fp16
    attn_kernel<<<dim3(8, 8, 32), 256, ATT_SMEM>>>(A2hi, A2lo, QEb, AVh);
    // 5. OUT1 = AV @ out_w^T + x
    halfsplit_kernel<<<(EMB * EMB) / 1024, 256>>>(out_w, Whh, Whl);
    mma_gemm_h<false, false, true, false, false, false><<<dim3(EMB / 128, NROWS / 128), 256, H_SMEM>>>(
        AVh, Whh, Whl, 0, x, OUT1, 0, 0, 0, NROWS, EMB, EMB);
    // 6. LN2 -> fp16
    ln_half_kernel<<<NROWS, 256>>>(OUT1, ln2_g, ln2_b, AVh);
    // 7. FF1 = relu(H2 @ fc1_w^T + fc1_b) -> fp16
    halfsplit_kernel<<<(FFN_I * EMB) / 1024, 256>>>(fc1_w, Whh, Whl);
    mma_gemm_h<true, true, false, true, false, false><<<dim3(FFN_I / 128, NROWS / 128), 256, H_SMEM>>>(
        AVh, Whh, Whl, fc1_b, 0, 0, FF1h, 0, 0, NROWS, FFN_I, EMB);
    // 8. out = FF1 @ fc2_w^T + fc2_b + OUT1
    halfsplit_kernel<<<(EMB * FFN_I) / 1024, 256>>>(fc2_w, Whh, Whl);
    mma_gemm_h<true, false, true, false, false, false><<<dim3(EMB / 128, NROWS / 128), 256, H_SMEM>>>(
        FF1h, Whh, Whl, fc2_b, OUT1, out, 0, 0, 0, NROWS, EMB, FFN_I);
}

// round 15
// speedup vs baseline: 1.5935x; 1.0421x over previous
#include <cuda_runtime.h>
#include <cuda_bf16.h>
#include <cuda_fp16.h>
#include <math.h>
#include <stdint.h>

// ---------------------------------------------------------------------------
// Shapes: x (T=4096, B=2, E=1024); H=16 heads, dk=dv=64; window 512 (513 rel pos)
// Q: fp16 [(t*2+b)*16+h][64]; K/V: fp16 hi/lo [(b*16+h)][t][64]
// QE: fp16 [r][j] stride 640; nxt (d_out+8388608): fp32 (QKV GEMM epilogue)
// All GEMMs fp16: A-single x W-split(hi/lo), 2 MMAs/tile
// ---------------------------------------------------------------------------
#define NROWS 8192
#define EMB   1024
#define QKV_N 3072
#define FFN_I 4096
#define NJ    513
#define NJP   640

#define OFF_OUT1   16777216ull
#define OFF_QE     92274688ull
#define SCRATCH_FLOATS 176160768ull

__device__ float g_scratch[SCRATCH_FLOATS];

__device__ __half g_act[8388608];      // fp16 LN1 / AV / H2
__device__ __half g_ff1[33554432];     // fc1 out fp16
__device__ __half g_w_hi[4194304];
__device__ __half g_w_lo[4194304];
__device__ __half g_pet_hi[40960];
__device__ __half g_pet_lo[40960];
__device__ __half g_q[8388608];        // Q fp16 single
__device__ __half g_k_hi[8388608];
__device__ __half g_k_lo[8388608];
__device__ __half g_v_hi[8388608];
__device__ __half g_v_lo[8388608];

__device__ __forceinline__ uint32_t smem_u32(const void* p) {
    uint32_t a;
    asm("{ .reg .u64 t; cvta.to.shared.u64 t, %1; cvt.u32.u64 %0, t; }" : "=r"(a) : "l"(p));
    return a;
}
__device__ __forceinline__ void split1h(float v, __half& h, __half& l) {
    h = __float2half_rn(v);
    l = __float2half_rn(v - __half2float(h));
}

// ---------------------------------------------------------------------------
__global__ __launch_bounds__(256) void halfsplit_kernel(
    const float* __restrict__ X, __half* __restrict__ Hi,
    __half* __restrict__ Lo)
{
    int i4 = blockIdx.x * 256 + threadIdx.x;
    float4 v = ((const float4*)X)[i4];
    __half h0, h1, h2, h3, l0, l1, l2, l3;
    split1h(v.x, h0, l0); split1h(v.y, h1, l1);
    split1h(v.z, h2, l2); split1h(v.w, h3, l3);
    __half2 H0; H0.x = h0; H0.y = h1;
    __half2 H1; H1.x = h2; H1.y = h3;
    __half2 L0; L0.x = l0; L0.y = l1;
    __half2 L1; L1.x = l2; L1.y = l3;
    ((__half2*)Hi)[i4 * 2]     = H0;
    ((__half2*)Hi)[i4 * 2 + 1] = H1;
    ((__half2*)Lo)[i4 * 2]     = L0;
    ((__half2*)Lo)[i4 * 2 + 1] = L1;
}

__global__ __launch_bounds__(256) void pe_halfsplit_t_kernel(
    const float* __restrict__ pe, __half* __restrict__ Hi,
    __half* __restrict__ Lo)
{
    int idx = blockIdx.x * 256 + threadIdx.x;
    int k = idx & 63;
    int j = idx >> 6;
    float v = (j < NJ) ? pe[(size_t)k * NJ + j] : 0.f;
    __half h, l;
    split1h(v, h, l);
    Hi[idx] = h;
    Lo[idx] = l;
}

__global__ __launch_bounds__(256) void ln_half_kernel(
    const float* __restrict__ X, const float* __restrict__ G,
    const float* __restrict__ Bt, __half* __restrict__ H)
{
    __shared__ float ssum[8], ssq[8], smv[2];
    int row = blockIdx.x;
    int tid = threadIdx.x;
    const float4* xr = (const float4*)(X + (size_t)row * EMB);
    float4 v = xr[tid];
    float s = v.x + v.y + v.z + v.w;
    float q = v.x*v.x + v.y*v.y + v.z*v.z + v.w*v.w;
#pragma unroll
    for (int o = 16; o > 0; o >>= 1) {
        s += __shfl_xor_sync(0xffffffffu, s, o);
        q += __shfl_xor_sync(0xffffffffu, q, o);
    }
    if ((tid & 31) == 0) { ssum[tid >> 5] = s; ssq[tid >> 5] = q; }
    __syncthreads();
    if (tid == 0) {
        float S = 0.f, Q = 0.f;
#pragma unroll
        for (int i = 0; i < 8; i++) { S += ssum[i]; Q += ssq[i]; }
        float mean = S * (1.f / EMB);
        float var  = Q * (1.f / EMB) - mean * mean;
        smv[0] = mean;
        smv[1] = rsqrtf(var + 1e-5f);
    }
    __syncthreads();
    float mean = smv[0], inv = smv[1];
    float4 g = ((const float4*)G)[tid];
    float4 b = ((const float4*)Bt)[tid];
    __half2 a0 = __floats2half2_rn((v.x - mean) * inv * g.x + b.x,
                                   (v.y - mean) * inv * g.y + b.y);
    __half2 a1 = __floats2half2_rn((v.z - mean) * inv * g.z + b.z,
                                   (v.w - mean) * inv * g.w + b.w);
    size_t i4 = (size_t)row * 256 + tid;
    ((__half2*)H)[i4 * 2]     = a0;
    ((__half2*)H)[i4 * 2 + 1] = a1;
}

// ---------------------------------------------------------------------------
__device__ __forceinline__ void cp16(uint32_t dst, const void* src) {
    asm volatile("cp.async.cg.shared.global [%0], [%1], 16;" :: "r"(dst), "l"(src));
}
__device__ __forceinline__ void ldm4(uint32_t* r, uint32_t addr) {
    asm volatile("ldmatrix.sync.aligned.m8n8.x4.shared.b16 {%0,%1,%2,%3}, [%4];"
                 : "=r"(r[0]), "=r"(r[1]), "=r"(r[2]), "=r"(r[3]) : "r"(addr));
}
__device__ __forceinline__ void mma16816h(float* c, const uint32_t* a,
                                          uint32_t b0, uint32_t b1) {
    asm volatile(
        "mma.sync.aligned.m16n8k16.row.col.f32.f16.f16.f32 "
        "{%0,%1,%2,%3}, {%4,%5,%6,%7}, {%8,%9}, {%0,%1,%2,%3};"
        : "+f"(c[0]), "+f"(c[1]), "+f"(c[2]), "+f"(c[3])
        : "r"(a[0]), "r"(a[1]), "r"(a[2]), "r"(a[3]), "r"(b0), "r"(b1));
}

// ---------------------------------------------------------------------------
// fp16 GEMM: C = A(f16) * (Bh+Bl)(f16)^T — 2 MMAs/tile.
// H16O: fp16 out. RES: +Res fp32. QOUT/NXTO: QKV epilogue (Q/K/V + nxt).
// ---------------------------------------------------------------------------
#define H_STAGE 24576
#define H_SMEM  73728

template<bool BIAS, bool RELU, bool RES, bool H16O, bool QOUT, bool NXTO>
__global__ __launch_bounds__(256, 2) void mma_gemm_h(
    const __half* __restrict__ Ax,
    const __half* __restrict__ Bh_, const __half* __restrict__ Bl_,
    const float* __restrict__ bias, const float* __restrict__ Res,
    float* __restrict__ C, __half* __restrict__ OH, int M, int N, int K)
{
    extern __shared__ char smem[];
    const uint32_t sbase = smem_u32(smem);
    const int tid = threadIdx.x;
    const int wid = tid >> 5, lane = tid & 31;
    const int bm = blockIdx.y * 128, bn = blockIdx.x * 128;
    const int m0w = (wid >> 2) * 64, n0w = (wid & 3) * 32;

    const int r0 = tid >> 2,         c0 = tid & 3;
    const int r1 = (tid + 256) >> 2, c1 = (tid + 256) & 3;
    const uint32_t so0 = (uint32_t)(r0 * 64 + ((c0 ^ ((r0 >> 1) & 3)) * 16));
    const uint32_t so1 = (uint32_t)(r1 * 64 + ((c1 ^ ((r1 >> 1) & 3)) * 16));
    const size_t offA0 = (size_t)(bm + r0) * K + c0 * 8;
    const size_t offA1 = (size_t)(bm + r1) * K + c1 * 8;
    const size_t offB0 = (size_t)(bn + r0) * K + c0 * 8;
    const size_t offB1 = (size_t)(bn + r1) * K + c1 * 8;

    float acc[4][4][4];
#pragma unroll
    for (int a = 0; a < 4; a++)
#pragma unroll
        for (int n = 0; n < 4; n++)
#pragma unroll
            for (int q = 0; q < 4; q++) acc[a][n][q] = 0.f;

    const int nt = K >> 5;
    const int rowA_base = m0w + (lane & 15);
    const int rowB_base = n0w + (lane & 15);
    const int chsel = lane >> 4;

#define LOAD_STAGE_H(s, k0)                                                   \
    do {                                                                      \
        uint32_t d = sbase + (s) * H_STAGE;                                   \
        cp16(d + so0,          Ax  + offA0 + (k0));                           \
        cp16(d + so1,          Ax  + offA1 + (k0));                           \
        cp16(d + 8192  + so0,  Bh_ + offB0 + (k0));                           \
        cp16(d + 8192  + so1,  Bh_ + offB1 + (k0));                           \
        cp16(d + 16384 + so0,  Bl_ + offB0 + (k0));                           \
        cp16(d + 16384 + so1,  Bl_ + offB1 + (k0));                           \
    } while (0)

    LOAD_STAGE_H(0, 0);
    asm volatile("cp.async.commit_group;");
    if (nt > 1) LOAD_STAGE_H(1, 32);
    asm volatile("cp.async.commit_group;");

    int stage = 0;
    for (int i = 0; i < nt; i++) {
        asm volatile("cp.async.wait_group 1;");
        __syncthreads();

        uint32_t base = sbase + stage * H_STAGE;
#pragma unroll
        for (int ks = 0; ks < 2; ks++) {
            const int chunk = ks * 2 + chsel;
            uint32_t bh[2][4], bl[2][4];
#pragma unroll
            for (int p = 0; p < 2; p++) {
                int row = rowB_base + p * 16;
                uint32_t ad = base + 8192 + (uint32_t)(row * 64 + ((chunk ^ ((row >> 1) & 3)) * 16));
                ldm4(bh[p], ad);
                ldm4(bl[p], ad + 8192);
            }
#pragma unroll
            for (int a = 0; a < 4; a++) {
                uint32_t ah[4];
                int row = rowA_base + a * 16;
                uint32_t ad = base + (uint32_t)(row * 64 + ((chunk ^ ((row >> 1) & 3)) * 16));
                ldm4(ah, ad);
#pragma unroll
                for (int n = 0; n < 4; n++) {
                    int p = n >> 1, q = n & 1;
                    mma16816h(acc[a][n], ah, bh[p][q], bh[p][q + 2]);
                    mma16816h(acc[a][n], ah, bl[p][q], bl[p][q + 2]);
                }
            }
        }
        int nx = i + 2;
        if (nx < nt) {
            int ns = stage + 2; if (ns >= 3) ns -= 3;
            LOAD_STAGE_H(ns, nx << 5);
        }
        asm volatile("cp.async.commit_group;");
        if (++stage == 3) stage = 0;
    }
#undef LOAD_STAGE_H

    const int g = lane >> 2, t = lane & 3;
#pragma unroll
    for (int a = 0; a < 4; a++) {
#pragma unroll
        for (int n = 0; n < 4; n++) {
            int row0 = bm + m0w + a * 16 + g;
            int col  = bn + n0w + n * 8 + 2 * t;
            float v0 = acc[a][n][0], v1 = acc[a][n][1];
            float v2 = acc[a][n][2], v3 = acc[a][n][3];
            if (BIAS) {
                float b0 = bias[col], b1 = bias[col + 1];
                v0 += b0; v1 += b1; v2 += b0; v3 += b1;
            }
            if (RELU) {
                v0 = fmaxf(v0, 0.f); v1 = fmaxf(v1, 0.f);
                v2 = fmaxf(v2, 0.f); v3 = fmaxf(v3, 0.f);
            }
            if (RES) {
                const float2 q0 = *(const float2*)(Res + (size_t)row0 * N + col);
                const float2 q1 = *(const float2*)(Res + (size_t)(row0 + 8) * N + col);
                v0 += q0.x; v1 += q0.y; v2 += q1.x; v3 += q1.y;
            }
            if (H16O) {
                __half2 h0 = __floats2half2_rn(v0, v1);
                __half2 h1 = __floats2half2_rn(v2, v3);
                *(__half2*)(OH + (size_t)row0 * N + col)       = h0;
                *(__half2*)(OH + (size_t)(row0 + 8) * N + col) = h1;
            } else if (!QOUT) {
                float2 o0; o0.x = v0; o0.y = v1;
                float2 o1; o1.x = v2; o1.y = v3;
                *(float2*)(C + (size_t)row0 * N + col)       = o0;
                *(float2*)(C + (size_t)(row0 + 8) * N + col) = o1;
            }
            if (QOUT) {
                int hh = col / 192;
                int cc = col - hh * 192;
                int b0_ = row0 & 1, t0_ = row0 >> 1;
                int t1_ = (row0 + 8) >> 1;
                if (cc < 64) {
                    __half2 q0 = __floats2half2_rn(v0, v1);
                    __half2 q1 = __floats2half2_rn(v2, v3);
                    size_t q0o = ((size_t)row0 * 16 + hh) * 64 + cc;
                    size_t q1o = ((size_t)(row0 + 8) * 16 + hh) * 64 + cc;
                    *(__half2*)(g_q + q0o) = q0;
                    *(__half2*)(g_q + q1o) = q1;
                } else {
                    __half h0x, h0y, h1x, h1y, l0x, l0y, l1x, l1y;
                    split1h(v0, h0x, l0x); split1h(v1, h0y, l0y);
                    split1h(v2, h1x, l1x); split1h(v3, h1y, l1y);
                    __half2 H0; H0.x = h0x; H0.y = h0y;
                    __half2 H1; H1.x = h1x; H1.y = h1y;
                    __half2 L0; L0.x = l0x; L0.y = l0y;
                    __half2 L1; L1.x = l1x; L1.y = l1y;
                    if (cc < 128) {
                        size_t k0o = (((size_t)(b0_ * 16 + hh)) * 4096 + t0_) * 64 + (cc - 64);
                        size_t k1o = (((size_t)(b0_ * 16 + hh)) * 4096 + t1_) * 64 + (cc - 64);
                        *(__half2*)(g_k_hi + k0o) = H0; *(__half2*)(g_k_lo + k0o) = L0;
                        *(__half2*)(g_k_hi + k1o) = H1; *(__half2*)(g_k_lo + k1o) = L1;
                    } else {
                        size_t v0o = (((size_t)(b0_ * 16 + hh)) * 4096 + t0_) * 64 + (cc - 128);
                        size_t v1o = (((size_t)(b0_ * 16 + hh)) * 4096 + t1_) * 64 + (cc - 128);
                        *(__half2*)(g_v_hi + v0o) = H0; *(__half2*)(g_v_lo + v0o) = L0;
                        *(__half2*)(g_v_hi + v1o) = H1; *(__half2*)(g_v_lo + v1o) = L1;
                    }
                    if (NXTO) {
                        if (t0_ >= 3584) {
                            size_t o = (((size_t)(t0_ - 3584) * 32) + b0_ * 16 + hh) * 128 + (cc - 64);
                            float2 w; w.x = v0; w.y = v1;
                            *(float2*)(C + o) = w;
                        }
                        if (t1_ >= 3584) {
                            size_t o = (((size_t)(t1_ - 3584) * 32) + b0_ * 16 + hh) * 128 + (cc - 64);
                            float2 w; w.x = v2; w.y = v3;
                            *(float2*)(C + o) = w;
                        }
                    }
                }
            }
        }
    }
}

// ---------------------------------------------------------------------------
// HMMA sliding-window attention, fp16: Q single, K/V split, P single.
// ---------------------------------------------------------------------------
#define AT_QH  0
#define AT_KH  8192
#define AT_KL  16384
#define AT_VH  24576
#define AT_VL  32768
#define AT_VTH 40960
#define AT_VTL 49152
#define AT_S   57344
#define AT_PH  74752
#define AT_CORR 82944
#define AT_LINV 83200
#define ATT_SMEM 83456

__global__ __launch_bounds__(256, 2) void attn_kernel(
    const __half* __restrict__ Qh, const __half* __restrict__ QEh,
    __half* __restrict__ OH)
{
    extern __shared__ char smem[];
    const uint32_t sbase = smem_u32(smem);
    float* Sf    = (float*)(smem + AT_S);
    float* corrS = (float*)(smem + AT_CORR);
    float* linvS = (float*)(smem + AT_LINV);

    const int s0 = blockIdx.x * 64;
    const int gg = blockIdx.y;
    const int bh = blockIdx.z;
    const int b = bh >> 4, h = bh & 15;
    const int tid = threadIdx.x;
    const int lane = tid & 31, wid = tid >> 5;
    const int tx = tid & 15, ty = tid >> 4;
    const int tbase = gg * 512 + s0;
    const int base_key = tbase - 512;
    const int bh_ = b * 16 + h;

    const int mrow0 = (wid >> 1) * 16;
    const int ncol0 = (wid & 1) * 32;
    const int lg = lane >> 2, lt = lane & 3;

    const int cr0 = tid >> 3, cc0 = tid & 7;
    const int cr1 = (tid + 256) >> 3, cc1 = (tid + 256) & 7;

#define CPT(dstoff, srcp, stride)                                                        \
    do {                                                                                 \
        cp16(sbase + (dstoff) + cr0 * 128 + ((cc0 ^ (cr0 & 7)) * 16),                    \
             (srcp) + (size_t)cr0 * (stride) + cc0 * 8);                                 \
        cp16(sbase + (dstoff) + cr1 * 128 + ((cc1 ^ (cr1 & 7)) * 16),                    \
             (srcp) + (size_t)cr1 * (stride) + cc1 * 8);                                 \
    } while (0)

    {
        const size_t qoff = (((size_t)tbase * 2 + b) * 16 + h) * 64;
        CPT(AT_QH, Qh + qoff, 2048);
        int u0 = base_key; if (u0 < 0) u0 = 0;
        const size_t koff = ((size_t)bh_ * 4096 + u0) * 64;
        CPT(AT_KH, g_k_hi + koff, 64);
        CPT(AT_KL, g_k_lo + koff, 64);
        CPT(AT_VH, g_v_hi + koff, 64);
        CPT(AT_VL, g_v_lo + koff, 64);
        asm volatile("cp.async.commit_group;");
    }

    float O[4][4];
    float mrow[4], lrow[4];
#pragma unroll
    for (int r = 0; r < 4; r++) {
        mrow[r] = -1e30f; lrow[r] = 0.f;
#pragma unroll
        for (int c = 0; c < 4; c++) O[r][c] = 0.f;
    }
    size_t qe_base[4];
#pragma unroll
    for (int r = 0; r < 4; r++) {
        int t = tbase + ty * 4 + r;
        qe_base[r] = ((size_t)(t * 2 + b) * 16 + h) * NJP;
    }

    for (int kt = 0; kt < 9; kt++) {
        asm volatile("cp.async.wait_group 0;");
        __syncthreads();

        {   // transpose V[kk][d] -> VT[d][kk] (hi and lo)
            int d0 = (tid & 15) * 4, kk0 = (tid >> 4) * 4;
#pragma unroll
            for (int tile = 0; tile < 2; tile++) {
                uint32_t inb = tile ? AT_VL : AT_VH;
                uint32_t outb = tile ? AT_VTL : AT_VTH;
                uint16_t m[4][4];
#pragma unroll
                for (int i = 0; i < 4; i++) {
                    int row = kk0 + i;
                    uint32_t off = inb + row * 128 + (((d0 >> 3) ^ (row & 7)) << 4) + ((d0 & 7) * 2);
                    uint2 v = *(uint2*)(smem + off);
                    uint16_t* pv = (uint16_t*)&v;
                    m[i][0] = pv[0]; m[i][1] = pv[1]; m[i][2] = pv[2]; m[i][3] = pv[3];
                }
#pragma unroll
                for (int j = 0; j < 4; j++) {
                    int rd = d0 + j;
                    uint32_t o2 = outb + rd * 128 + (((kk0 >> 3) ^ (rd & 7)) << 4) + ((kk0 & 7) * 2);
                    uint16_t o[4] = {m[0][j], m[1][j], m[2][j], m[3][j]};
                    *(uint2*)(smem + o2) = *(uint2*)o;
                }
            }
        }
        __syncthreads();

        // S = Q.K^T  (Q single, K split: 2 MMAs)
        float sacc[4][4];
#pragma unroll
        for (int n = 0; n < 4; n++)
#pragma unroll
            for (int q = 0; q < 4; q++) sacc[n][q] = 0.f;
#pragma unroll
        for (int ks = 0; ks < 4; ks++) {
            int chunk = 2 * ks + (lane >> 4);
            int rq = mrow0 + (lane & 15);
            uint32_t aq = sbase + AT_QH + rq * 128 + ((chunk ^ (rq & 7)) << 4);
            uint32_t qf[4];
            ldm4(qf, aq);
            uint32_t khf[2][4], klf[2][4];
#pragma unroll
            for (int p = 0; p < 2; p++) {
                int rk = ncol0 + p * 16 + (lane & 15);
                uint32_t ak = sbase + AT_KH + rk * 128 + ((chunk ^ (rk & 7)) << 4);
                ldm4(khf[p], ak); ldm4(klf[p], ak + 8192);
            }
#pragma unroll
            for (int n = 0; n < 4; n++) {
                int p = n >> 1, q = n & 1;
                mma16816h(sacc[n], qf, khf[p][q], khf[p][q + 2]);
                mma16816h(sacc[n], qf, klf[p][q], klf[p][q + 2]);
            }
        }
#pragma unroll
        for (int n = 0; n < 4; n++) {
            int si = mrow0 + lg, ck = ncol0 + n * 8 + lt * 2;
            float2 a0; a0.x = sacc[n][0]; a0.y = sacc[n][1];
            float2 a1; a1.x = sacc[n][2]; a1.y = sacc[n][3];
            *(float2*)&Sf[si * 68 + ck]       = a0;
            *(float2*)&Sf[(si + 8) * 68 + ck] = a1;
        }
        __syncthreads();

        // scalar softmax on smem S
        float acc[4][4];
#pragma unroll
        for (int r = 0; r < 4; r++) {
            float4 sv = *(const float4*)&Sf[(ty * 4 + r) * 68 + tx * 4];
            acc[r][0] = sv.x; acc[r][1] = sv.y; acc[r][2] = sv.z; acc[r][3] = sv.w;
        }
#pragma unroll
        for (int r = 0; r < 4; r++) {
            int si = ty * 4 + r;
#pragma unroll
            for (int c = 0; c < 4; c++) {
                int kk = tx * 4 + c;
                int j = kt * 64 + kk - si;
                int u = base_key + kt * 64 + kk;
                if (j >= 0 && j <= 512 && u >= 0)
                    acc[r][c] = (acc[r][c] + __half2float(QEh[qe_base[r] + j])) * 0.125f;
                else
                    acc[r][c] = -1e30f;
            }
        }
        float corr[4];
#pragma unroll
        for (int r = 0; r < 4; r++) {
            float tm = fmaxf(fmaxf(acc[r][0], acc[r][1]), fmaxf(acc[r][2], acc[r][3]));
#pragma unroll
            for (int o = 1; o < 16; o <<= 1)
                tm = fmaxf(tm, __shfl_xor_sync(0xffffffffu, tm, o));
            float mnew = fmaxf(mrow[r], tm);
            corr[r] = __expf(mrow[r] - mnew);
            float rs = 0.f;
#pragma unroll
            for (int c = 0; c < 4; c++) {
                float p = (acc[r][c] > -5e29f) ? __expf(acc[r][c] - mnew) : 0.f;
                acc[r][c] = p;
                rs += p;
            }
#pragma unroll
            for (int o = 1; o < 16; o <<= 1)
                rs += __shfl_xor_sync(0xffffffffu, rs, o);
            lrow[r] = lrow[r] * corr[r] + rs;
            mrow[r] = mnew;
        }
        // write P fp16 single (swizzled rows) + corr
#pragma unroll
        for (int r = 0; r < 4; r++) {
            int si = ty * 4 + r;
            uint32_t poff = si * 128 + ((((tx >> 1) ^ (si & 7))) << 4) + ((tx & 1) * 8);
            uint16_t hs[4];
#pragma unroll
            for (int c = 0; c < 4; c++) {
                __half ph_ = __float2half_rn(acc[r][c]);
                hs[c] = *(uint16_t*)&ph_;
            }
            *(uint2*)(smem + AT_PH + poff) = *(uint2*)hs;
        }
        if (tx == 0) {
#pragma unroll
            for (int r = 0; r < 4; r++) corrS[ty * 4 + r] = corr[r];
        }
        __syncthreads();

        // prefetch next K/V (overlaps PV)
        if (kt < 8) {
            int u0 = base_key + (kt + 1) * 64; if (u0 < 0) u0 = 0;
            const size_t koff = ((size_t)bh_ * 4096 + u0) * 64;
            CPT(AT_KH, g_k_hi + koff, 64);
            CPT(AT_KL, g_k_lo + koff, 64);
            CPT(AT_VH, g_v_hi + koff, 64);
            CPT(AT_VL, g_v_lo + koff, 64);
        }
        asm volatile("cp.async.commit_group;");

        // O = O*corr + P.V  (P single, V split: 2 MMAs)
        float cA = corrS[mrow0 + lg], cB = corrS[mrow0 + lg + 8];
#pragma unroll
        for (int n = 0; n < 4; n++) {
            O[n][0] *= cA; O[n][1] *= cA; O[n][2] *= cB; O[n][3] *= cB;
        }
#pragma unroll
        for (int ks = 0; ks < 4; ks++) {
            int chunk = 2 * ks + (lane >> 4);
            int rp = mrow0 + (lane & 15);
            uint32_t ap = sbase + AT_PH + rp * 128 + ((chunk ^ (rp & 7)) << 4);
            uint32_t pf[4];
            ldm4(pf, ap);
            uint32_t vhf[2][4], vlf[2][4];
#pragma unroll
            for (int p = 0; p < 2; p++) {
                int rv = ncol0 + p * 16 + (lane & 15);
                uint32_t av = sbase + AT_VTH + rv * 128 + ((chunk ^ (rv & 7)) << 4);
                ldm4(vhf[p], av); ldm4(vlf[p], av + 8192);
            }
#pragma unroll
            for (int n = 0; n < 4; n++) {
                int p = n >> 1, q = n & 1;
                mma16816h(O[n], pf, vhf[p][q], vhf[p][q + 2]);
                mma16816h(O[n], pf, vlf[p][q], vlf[p][q + 2]);
            }
        }
    }
#undef CPT

    if (tx == 0) {
#pragma unroll
        for (int r = 0; r < 4; r++) linvS[ty * 4 + r] = 1.f / lrow[r];
    }
    __syncthreads();
    float li0 = linvS[mrow0 + lg], li1 = linvS[mrow0 + lg + 8];
#pragma unroll
    for (int n = 0; n < 4; n++) {
        int si = mrow0 + lg, d = ncol0 + n * 8 + lt * 2;
        int t0 = tbase + si, t1 = t0 + 8;
        size_t o0 = ((size_t)(t0 * 2 + b)) * 1024 + h * 64 + d;
        size_t o1 = ((size_t)(t1 * 2 + b)) * 1024 + h * 64 + d;
        __half2 h0 = __floats2half2_rn(O[n][0] * li0, O[n][1] * li0);
        __half2 h1 = __floats2half2_rn(O[n][2] * li1, O[n][3] * li1);
        *(__half2*)(OH + o0) = h0;
        *(__half2*)(OH + o1) = h1;
    }
}

// ---------------------------------------------------------------------------
extern "C" void kernel_launch(void* const* d_in, const int* in_sizes, int n_in,
                              void* d_out, int out_size)
{
    const float* x      = (const float*)d_in[0];
    const float* ln1_g  = (const float*)d_in[1];
    const float* ln1_b  = (const float*)d_in[2];
    const float* qkv_w  = (const float*)d_in[3];
    const float* qkv_b  = (const float*)d_in[4];
    const float* pos_emb= (const float*)d_in[5];
    const float* out_w  = (const float*)d_in[6];
    const float* ln2_g  = (const float*)d_in[7];
    const float* ln2_b  = (const float*)d_in[8];
    const float* fc1_w  = (const float*)d_in[9];
    const float* fc1_b  = (const float*)d_in[10];
    const float* fc2_w  = (const float*)d_in[11];
    const float* fc2_b  = (const float*)d_in[12];
    float* out = (float*)d_out;

    float* scratch = 0;
    cudaGetSymbolAddress((void**)&scratch, g_scratch);
    void *pA, *pFF1, *pW, *pWl, *pPT, *pPTl, *pQ;
    cudaGetSymbolAddress(&pA, g_act);
    cudaGetSymbolAddress(&pFF1, g_ff1);
    cudaGetSymbolAddress(&pW, g_w_hi);
    cudaGetSymbolAddress(&pWl, g_w_lo);
    cudaGetSymbolAddress(&pPT, g_pet_hi);
    cudaGetSymbolAddress(&pPTl, g_pet_lo);
    cudaGetSymbolAddress(&pQ, g_q);

    __half* AVh  = (__half*)pA;
    __half* FF1h = (__half*)pFF1;
    __half* Whh  = (__half*)pW;
    __half* Whl  = (__half*)pWl;
    __half* PThh = (__half*)pPT;
    __half* PThl = (__half*)pPTl;
    __half* Qh   = (__half*)pQ;

    float* OUT1 = scratch + OFF_OUT1;
    __half* QEh = (__half*)(scratch + OFF_QE);

    cudaFuncSetAttribute(mma_gemm_h<true, false, false, false, true, true>,    cudaFuncAttributeMaxDynamicSharedMemorySize, H_SMEM);
    cudaFuncSetAttribute(mma_gemm_h<false, false, false, true, false, false>,  cudaFuncAttributeMaxDynamicSharedMemorySize, H_SMEM);
    cudaFuncSetAttribute(mma_gemm_h<false, false, true, false, false, false>,  cudaFuncAttributeMaxDynamicSharedMemorySize, H_SMEM);
    cudaFuncSetAttribute(mma_gemm_h<true, true, false, true, false, false>,    cudaFuncAttributeMaxDynamicSharedMemorySize, H_SMEM);
    cudaFuncSetAttribute(mma_gemm_h<true, false, true, false, false, false>,   cudaFuncAttributeMaxDynamicSharedMemorySize, H_SMEM);
    cudaFuncSetAttribute(attn_kernel, cudaFuncAttributeMaxDynamicSharedMemorySize, ATT_SMEM);

    // 0. pe^T fp16 split
    pe_halfsplit_t_kernel<<<160, 256>>>(pos_emb, PThh, PThl);
    // 1. LN1 -> fp16
    ln_half_kernel<<<NROWS, 256>>>(x, ln1_g, ln1_b, AVh);
    // 2. QKV GEMM: Q fp16 / K,V fp16-split / nxt fp32 -> d_out
    halfsplit_kernel<<<(QKV_N * EMB) / 1024, 256>>>(qkv_w, Whh, Whl);
    mma_gemm_h<true, false, false, false, true, true><<<dim3(QKV_N / 128, NROWS / 128), 256, H_SMEM>>>(
        AVh, Whh, Whl, qkv_b, 0, out + 8388608, 0, NROWS, QKV_N, EMB);
    // 3. QE = Q @ peT^T -> fp16  (M=131072, N=640, K=64)
    mma_gemm_h<false, false, false, true, false, false><<<dim3(NJP / 128, 131072 / 128), 256, H_SMEM>>>(
        Qh, PThh, PThl, 0, 0, 0, QEh, 131072, NJP, 64);
    // 4. HMMA attention -> AV fp16
    attn_kernel<<<dim3(8, 8, 32), 256, ATT_SMEM>>>(Qh, QEh, AVh);
    // 5. OUT1 = AV @ out_w^T + x
    halfsplit_kernel<<<(EMB * EMB) / 1024, 256>>>(out_w, Whh, Whl);
    mma_gemm_h<false, false, true, false, false, false><<<dim3(EMB / 128, NROWS / 128), 256, H_SMEM>>>(
        AVh, Whh, Whl, 0, x, OUT1, 0, NROWS, EMB, EMB);
    // 6. LN2 -> fp16
    ln_half_kernel<<<NROWS, 256>>>(OUT1, ln2_g, ln2_b, AVh);
    // 7. FF1 = relu(H2 @ fc1_w^T + fc1_b) -> fp16
    halfsplit_kernel<<<(FFN_I * EMB) / 1024, 256>>>(fc1_w, Whh, Whl);
    mma_gemm_h<true, true, false, true, false, false><<<dim3(FFN_I / 128, NROWS / 128), 256, H_SMEM>>>(
        AVh, Whh, Whl, fc1_b, 0, 0, FF1h, NROWS, FFN_I, EMB);
    // 8. out = FF1 @ fc2_w^T + fc2_b + OUT1
    halfsplit_kernel<<<(EMB * FFN_I) / 1024, 256>>>(fc2_w, Whh, Whl);
    mma_gemm_h<true, false, true, false, false, false><<<dim3(EMB / 128, NROWS / 128), 256, H_SMEM>>>(
        FF1h, Whh, Whl, fc2_b, OUT1, out, 0, NROWS, EMB, FFN_I);
}

// round 16
// speedup vs baseline: 2.1697x; 1.3617x over previous
#include <cuda_runtime.h>
#include <cuda_bf16.h>
#include <cuda_fp16.h>
#include <math.h>
#include <stdint.h>

// ---------------------------------------------------------------------------
// Shapes: x (T=4096, B=2, E=1024); H=16 heads, dk=dv=64; window 512 (513 rel pos)
// Q: fp16 [(t*2+b)*16+h][64]; K/V: fp16 hi/lo [(b*16+h)][t][64]
// QE: fp16 [r][j] stride 640; nxt (d_out+8388608): fp32 (QKV GEMM epilogue)
// QKV GEMM: A-single x W-split (2 MMAs). out-proj/fc1/fc2/QE: single x single (1 MMA).
// ---------------------------------------------------------------------------
#define NROWS 8192
#define EMB   1024
#define QKV_N 3072
#define FFN_I 4096
#define NJ    513
#define NJP   640

#define OFF_OUT1   16777216ull
#define OFF_QE     92274688ull
#define SCRATCH_FLOATS 176160768ull

__device__ float g_scratch[SCRATCH_FLOATS];

__device__ __half g_act[8388608];      // fp16 LN1 / AV / H2
__device__ __half g_ff1[33554432];     // fc1 out fp16
__device__ __half g_w_hi[4194304];
__device__ __half g_w_lo[4194304];
__device__ __half g_pet[40960];
__device__ __half g_q[8388608];        // Q fp16 single
__device__ __half g_k_hi[8388608];
__device__ __half g_k_lo[8388608];
__device__ __half g_v_hi[8388608];
__device__ __half g_v_lo[8388608];

__device__ __forceinline__ uint32_t smem_u32(const void* p) {
    uint32_t a;
    asm("{ .reg .u64 t; cvta.to.shared.u64 t, %1; cvt.u32.u64 %0, t; }" : "=r"(a) : "l"(p));
    return a;
}
__device__ __forceinline__ void split1h(float v, __half& h, __half& l) {
    h = __float2half_rn(v);
    l = __float2half_rn(v - __half2float(h));
}

// ---------------------------------------------------------------------------
__global__ __launch_bounds__(256) void halfsplit_kernel(
    const float* __restrict__ X, __half* __restrict__ Hi,
    __half* __restrict__ Lo)
{
    int i4 = blockIdx.x * 256 + threadIdx.x;
    float4 v = ((const float4*)X)[i4];
    __half h0, h1, h2, h3, l0, l1, l2, l3;
    split1h(v.x, h0, l0); split1h(v.y, h1, l1);
    split1h(v.z, h2, l2); split1h(v.w, h3, l3);
    __half2 H0; H0.x = h0; H0.y = h1;
    __half2 H1; H1.x = h2; H1.y = h3;
    __half2 L0; L0.x = l0; L0.y = l1;
    __half2 L1; L1.x = l2; L1.y = l3;
    ((__half2*)Hi)[i4 * 2]     = H0;
    ((__half2*)Hi)[i4 * 2 + 1] = H1;
    ((__half2*)Lo)[i4 * 2]     = L0;
    ((__half2*)Lo)[i4 * 2 + 1] = L1;
}

// plain fp32 -> fp16 convert
__global__ __launch_bounds__(256) void halfconv_kernel(
    const float* __restrict__ X, __half* __restrict__ H)
{
    int i4 = blockIdx.x * 256 + threadIdx.x;
    float4 v = ((const float4*)X)[i4];
    __half2 a0 = __floats2half2_rn(v.x, v.y);
    __half2 a1 = __floats2half2_rn(v.z, v.w);
    ((__half2*)H)[i4 * 2]     = a0;
    ((__half2*)H)[i4 * 2 + 1] = a1;
}

__global__ __launch_bounds__(256) void pe_half_t_kernel(
    const float* __restrict__ pe, __half* __restrict__ H)
{
    int idx = blockIdx.x * 256 + threadIdx.x;
    int k = idx & 63;
    int j = idx >> 6;
    float v = (j < NJ) ? pe[(size_t)k * NJ + j] : 0.f;
    H[idx] = __float2half_rn(v);
}

__global__ __launch_bounds__(256) void ln_half_kernel(
    const float* __restrict__ X, const float* __restrict__ G,
    const float* __restrict__ Bt, __half* __restrict__ H)
{
    __shared__ float ssum[8], ssq[8], smv[2];
    int row = blockIdx.x;
    int tid = threadIdx.x;
    const float4* xr = (const float4*)(X + (size_t)row * EMB);
    float4 v = xr[tid];
    float s = v.x + v.y + v.z + v.w;
    float q = v.x*v.x + v.y*v.y + v.z*v.z + v.w*v.w;
#pragma unroll
    for (int o = 16; o > 0; o >>= 1) {
        s += __shfl_xor_sync(0xffffffffu, s, o);
        q += __shfl_xor_sync(0xffffffffu, q, o);
    }
    if ((tid & 31) == 0) { ssum[tid >> 5] = s; ssq[tid >> 5] = q; }
    __syncthreads();
    if (tid == 0) {
        float S = 0.f, Q = 0.f;
#pragma unroll
        for (int i = 0; i < 8; i++) { S += ssum[i]; Q += ssq[i]; }
        float mean = S * (1.f / EMB);
        float var  = Q * (1.f / EMB) - mean * mean;
        smv[0] = mean;
        smv[1] = rsqrtf(var + 1e-5f);
    }
    __syncthreads();
    float mean = smv[0], inv = smv[1];
    float4 g = ((const float4*)G)[tid];
    float4 b = ((const float4*)Bt)[tid];
    __half2 a0 = __floats2half2_rn((v.x - mean) * inv * g.x + b.x,
                                   (v.y - mean) * inv * g.y + b.y);
    __half2 a1 = __floats2half2_rn((v.z - mean) * inv * g.z + b.z,
                                   (v.w - mean) * inv * g.w + b.w);
    size_t i4 = (size_t)row * 256 + tid;
    ((__half2*)H)[i4 * 2]     = a0;
    ((__half2*)H)[i4 * 2 + 1] = a1;
}

// ---------------------------------------------------------------------------
__device__ __forceinline__ void cp16(uint32_t dst, const void* src) {
    asm volatile("cp.async.cg.shared.global [%0], [%1], 16;" :: "r"(dst), "l"(src));
}
__device__ __forceinline__ void ldm4(uint32_t* r, uint32_t addr) {
    asm volatile("ldmatrix.sync.aligned.m8n8.x4.shared.b16 {%0,%1,%2,%3}, [%4];"
                 : "=r"(r[0]), "=r"(r[1]), "=r"(r[2]), "=r"(r[3]) : "r"(addr));
}
__device__ __forceinline__ void mma16816h(float* c, const uint32_t* a,
                                          uint32_t b0, uint32_t b1) {
    asm volatile(
        "mma.sync.aligned.m16n8k16.row.col.f32.f16.f16.f32 "
        "{%0,%1,%2,%3}, {%4,%5,%6,%7}, {%8,%9}, {%0,%1,%2,%3};"
        : "+f"(c[0]), "+f"(c[1]), "+f"(c[2]), "+f"(c[3])
        : "r"(a[0]), "r"(a[1]), "r"(a[2]), "r"(a[3]), "r"(b0), "r"(b1));
}

// ---------------------------------------------------------------------------
// fp16 GEMM: C = A(f16) * (Bh[+Bl])(f16)^T.  BSINGLE: skip Bl (1 MMA/tile).
// H16O: fp16 out. RES: +Res fp32. QOUT/NXTO: QKV epilogue (Q/K/V + nxt).
// ---------------------------------------------------------------------------
#define H_STAGE 24576
#define H_SMEM  73728

template<bool BIAS, bool RELU, bool RES, bool H16O, bool QOUT, bool NXTO, bool BSINGLE>
__global__ __launch_bounds__(256, 2) void mma_gemm_h(
    const __half* __restrict__ Ax,
    const __half* __restrict__ Bh_, const __half* __restrict__ Bl_,
    const float* __restrict__ bias, const float* __restrict__ Res,
    float* __restrict__ C, __half* __restrict__ OH, int M, int N, int K)
{
    extern __shared__ char smem[];
    const uint32_t sbase = smem_u32(smem);
    const int tid = threadIdx.x;
    const int wid = tid >> 5, lane = tid & 31;
    const int bm = blockIdx.y * 128, bn = blockIdx.x * 128;
    const int m0w = (wid >> 2) * 64, n0w = (wid & 3) * 32;

    const int r0 = tid >> 2,         c0 = tid & 3;
    const int r1 = (tid + 256) >> 2, c1 = (tid + 256) & 3;
    const uint32_t so0 = (uint32_t)(r0 * 64 + ((c0 ^ ((r0 >> 1) & 3)) * 16));
    const uint32_t so1 = (uint32_t)(r1 * 64 + ((c1 ^ ((r1 >> 1) & 3)) * 16));
    const size_t offA0 = (size_t)(bm + r0) * K + c0 * 8;
    const size_t offA1 = (size_t)(bm + r1) * K + c1 * 8;
    const size_t offB0 = (size_t)(bn + r0) * K + c0 * 8;
    const size_t offB1 = (size_t)(bn + r1) * K + c1 * 8;

    float acc[4][4][4];
#pragma unroll
    for (int a = 0; a < 4; a++)
#pragma unroll
        for (int n = 0; n < 4; n++)
#pragma unroll
            for (int q = 0; q < 4; q++) acc[a][n][q] = 0.f;

    const int nt = K >> 5;
    const int rowA_base = m0w + (lane & 15);
    const int rowB_base = n0w + (lane & 15);
    const int chsel = lane >> 4;

#define LOAD_STAGE_H(s, k0)                                                   \
    do {                                                                      \
        uint32_t d = sbase + (s) * H_STAGE;                                   \
        cp16(d + so0,          Ax  + offA0 + (k0));                           \
        cp16(d + so1,          Ax  + offA1 + (k0));                           \
        cp16(d + 8192  + so0,  Bh_ + offB0 + (k0));                           \
        cp16(d + 8192  + so1,  Bh_ + offB1 + (k0));                           \
        if (!BSINGLE) {                                                       \
            cp16(d + 16384 + so0,  Bl_ + offB0 + (k0));                       \
            cp16(d + 16384 + so1,  Bl_ + offB1 + (k0));                       \
        }                                                                     \
    } while (0)

    LOAD_STAGE_H(0, 0);
    asm volatile("cp.async.commit_group;");
    if (nt > 1) LOAD_STAGE_H(1, 32);
    asm volatile("cp.async.commit_group;");

    int stage = 0;
    for (int i = 0; i < nt; i++) {
        asm volatile("cp.async.wait_group 1;");
        __syncthreads();

        uint32_t base = sbase + stage * H_STAGE;
#pragma unroll
        for (int ks = 0; ks < 2; ks++) {
            const int chunk = ks * 2 + chsel;
            uint32_t bh[2][4], bl[2][4];
#pragma unroll
            for (int p = 0; p < 2; p++) {
                int row = rowB_base + p * 16;
                uint32_t ad = base + 8192 + (uint32_t)(row * 64 + ((chunk ^ ((row >> 1) & 3)) * 16));
                ldm4(bh[p], ad);
                if (!BSINGLE) ldm4(bl[p], ad + 8192);
            }
#pragma unroll
            for (int a = 0; a < 4; a++) {
                uint32_t ah[4];
                int row = rowA_base + a * 16;
                uint32_t ad = base + (uint32_t)(row * 64 + ((chunk ^ ((row >> 1) & 3)) * 16));
                ldm4(ah, ad);
#pragma unroll
                for (int n = 0; n < 4; n++) {
                    int p = n >> 1, q = n & 1;
                    mma16816h(acc[a][n], ah, bh[p][q], bh[p][q + 2]);
                    if (!BSINGLE) mma16816h(acc[a][n], ah, bl[p][q], bl[p][q + 2]);
                }
            }
        }
        int nx = i + 2;
        if (nx < nt) {
            int ns = stage + 2; if (ns >= 3) ns -= 3;
            LOAD_STAGE_H(ns, nx << 5);
        }
        asm volatile("cp.async.commit_group;");
        if (++stage == 3) stage = 0;
    }
#undef LOAD_STAGE_H

    const int g = lane >> 2, t = lane & 3;
#pragma unroll
    for (int a = 0; a < 4; a++) {
#pragma unroll
        for (int n = 0; n < 4; n++) {
            int row0 = bm + m0w + a * 16 + g;
            int col  = bn + n0w + n * 8 + 2 * t;
            float v0 = acc[a][n][0], v1 = acc[a][n][1];
            float v2 = acc[a][n][2], v3 = acc[a][n][3];
            if (BIAS) {
                float b0 = bias[col], b1 = bias[col + 1];
                v0 += b0; v1 += b1; v2 += b0; v3 += b1;
            }
            if (RELU) {
                v0 = fmaxf(v0, 0.f); v1 = fmaxf(v1, 0.f);
                v2 = fmaxf(v2, 0.f); v3 = fmaxf(v3, 0.f);
            }
            if (RES) {
                const float2 q0 = *(const float2*)(Res + (size_t)row0 * N + col);
                const float2 q1 = *(const float2*)(Res + (size_t)(row0 + 8) * N + col);
                v0 += q0.x; v1 += q0.y; v2 += q1.x; v3 += q1.y;
            }
            if (H16O) {
                __half2 h0 = __floats2half2_rn(v0, v1);
                __half2 h1 = __floats2half2_rn(v2, v3);
                *(__half2*)(OH + (size_t)row0 * N + col)       = h0;
                *(__half2*)(OH + (size_t)(row0 + 8) * N + col) = h1;
            } else if (!QOUT) {
                float2 o0; o0.x = v0; o0.y = v1;
                float2 o1; o1.x = v2; o1.y = v3;
                *(float2*)(C + (size_t)row0 * N + col)       = o0;
                *(float2*)(C + (size_t)(row0 + 8) * N + col) = o1;
            }
            if (QOUT) {
                int hh = col / 192;
                int cc = col - hh * 192;
                int b0_ = row0 & 1, t0_ = row0 >> 1;
                int t1_ = (row0 + 8) >> 1;
                if (cc < 64) {
                    __half2 q0 = __floats2half2_rn(v0, v1);
                    __half2 q1 = __floats2half2_rn(v2, v3);
                    size_t q0o = ((size_t)row0 * 16 + hh) * 64 + cc;
                    size_t q1o = ((size_t)(row0 + 8) * 16 + hh) * 64 + cc;
                    *(__half2*)(g_q + q0o) = q0;
                    *(__half2*)(g_q + q1o) = q1;
                } else {
                    __half h0x, h0y, h1x, h1y, l0x, l0y, l1x, l1y;
                    split1h(v0, h0x, l0x); split1h(v1, h0y, l0y);
                    split1h(v2, h1x, l1x); split1h(v3, h1y, l1y);
                    __half2 H0; H0.x = h0x; H0.y = h0y;
                    __half2 H1; H1.x = h1x; H1.y = h1y;
                    __half2 L0; L0.x = l0x; L0.y = l0y;
                    __half2 L1; L1.x = l1x; L1.y = l1y;
                    if (cc < 128) {
                        size_t k0o = (((size_t)(b0_ * 16 + hh)) * 4096 + t0_) * 64 + (cc - 64);
                        size_t k1o = (((size_t)(b0_ * 16 + hh)) * 4096 + t1_) * 64 + (cc - 64);
                        *(__half2*)(g_k_hi + k0o) = H0; *(__half2*)(g_k_lo + k0o) = L0;
                        *(__half2*)(g_k_hi + k1o) = H1; *(__half2*)(g_k_lo + k1o) = L1;
                    } else {
                        size_t v0o = (((size_t)(b0_ * 16 + hh)) * 4096 + t0_) * 64 + (cc - 128);
                        size_t v1o = (((size_t)(b0_ * 16 + hh)) * 4096 + t1_) * 64 + (cc - 128);
                        *(__half2*)(g_v_hi + v0o) = H0; *(__half2*)(g_v_lo + v0o) = L0;
                        *(__half2*)(g_v_hi + v1o) = H1; *(__half2*)(g_v_lo + v1o) = L1;
                    }
                    if (NXTO) {
                        if (t0_ >= 3584) {
                            size_t o = (((size_t)(t0_ - 3584) * 32) + b0_ * 16 + hh) * 128 + (cc - 64);
                            float2 w; w.x = v0; w.y = v1;
                            *(float2*)(C + o) = w;
                        }
                        if (t1_ >= 3584) {
                            size_t o = (((size_t)(t1_ - 3584) * 32) + b0_ * 16 + hh) * 128 + (cc - 64);
                            float2 w; w.x = v2; w.y = v3;
                            *(float2*)(C + o) = w;
                        }
                    }
                }
            }
        }
    }
}

// ---------------------------------------------------------------------------
// HMMA sliding-window attention, fp16: Q single, K/V split, P single.
// ---------------------------------------------------------------------------
#define AT_QH  0
#define AT_KH  8192
#define AT_KL  16384
#define AT_VH  24576
#define AT_VL  32768
#define AT_VTH 40960
#define AT_VTL 49152
#define AT_S   57344
#define AT_PH  74752
#define AT_CORR 82944
#define AT_LINV 83200
#define ATT_SMEM 83456

__global__ __launch_bounds__(256, 2) void attn_kernel(
    const __half* __restrict__ Qh, const __half* __restrict__ QEh,
    __half* __restrict__ OH)
{
    extern __shared__ char smem[];
    const uint32_t sbase = smem_u32(smem);
    float* Sf    = (float*)(smem + AT_S);
    float* corrS = (float*)(smem + AT_CORR);
    float* linvS = (float*)(smem + AT_LINV);

    const int s0 = blockIdx.x * 64;
    const int gg = blockIdx.y;
    const int bh = blockIdx.z;
    const int b = bh >> 4, h = bh & 15;
    const int tid = threadIdx.x;
    const int lane = tid & 31, wid = tid >> 5;
    const int tx = tid & 15, ty = tid >> 4;
    const int tbase = gg * 512 + s0;
    const int base_key = tbase - 512;
    const int bh_ = b * 16 + h;

    const int mrow0 = (wid >> 1) * 16;
    const int ncol0 = (wid & 1) * 32;
    const int lg = lane >> 2, lt = lane & 3;

    const int cr0 = tid >> 3, cc0 = tid & 7;
    const int cr1 = (tid + 256) >> 3, cc1 = (tid + 256) & 7;

#define CPT(dstoff, srcp, stride)                                                        \
    do {                                                                                 \
        cp16(sbase + (dstoff) + cr0 * 128 + ((cc0 ^ (cr0 & 7)) * 16),                    \
             (srcp) + (size_t)cr0 * (stride) + cc0 * 8);                                 \
        cp16(sbase + (dstoff) + cr1 * 128 + ((cc1 ^ (cr1 & 7)) * 16),                    \
             (srcp) + (size_t)cr1 * (stride) + cc1 * 8);                                 \
    } while (0)

    {
        const size_t qoff = (((size_t)tbase * 2 + b) * 16 + h) * 64;
        CPT(AT_QH, Qh + qoff, 2048);
        int u0 = base_key; if (u0 < 0) u0 = 0;
        const size_t koff = ((size_t)bh_ * 4096 + u0) * 64;
        CPT(AT_KH, g_k_hi + koff, 64);
        CPT(AT_KL, g_k_lo + koff, 64);
        CPT(AT_VH, g_v_hi + koff, 64);
        CPT(AT_VL, g_v_lo + koff, 64);
        asm volatile("cp.async.commit_group;");
    }

    float O[4][4];
    float mrow[4], lrow[4];
#pragma unroll
    for (int r = 0; r < 4; r++) {
        mrow[r] = -1e30f; lrow[r] = 0.f;
#pragma unroll
        for (int c = 0; c < 4; c++) O[r][c] = 0.f;
    }
    size_t qe_base[4];
#pragma unroll
    for (int r = 0; r < 4; r++) {
        int t = tbase + ty * 4 + r;
        qe_base[r] = ((size_t)(t * 2 + b) * 16 + h) * NJP;
    }

    for (int kt = 0; kt < 9; kt++) {
        asm volatile("cp.async.wait_group 0;");
        __syncthreads();

        {   // transpose V[kk][d] -> VT[d][kk] (hi and lo)
            int d0 = (tid & 15) * 4, kk0 = (tid >> 4) * 4;
#pragma unroll
            for (int tile = 0; tile < 2; tile++) {
                uint32_t inb = tile ? AT_VL : AT_VH;
                uint32_t outb = tile ? AT_VTL : AT_VTH;
                uint16_t m[4][4];
#pragma unroll
                for (int i = 0; i < 4; i++) {
                    int row = kk0 + i;
                    uint32_t off = inb + row * 128 + (((d0 >> 3) ^ (row & 7)) << 4) + ((d0 & 7) * 2);
                    uint2 v = *(uint2*)(smem + off);
                    uint16_t* pv = (uint16_t*)&v;
                    m[i][0] = pv[0]; m[i][1] = pv[1]; m[i][2] = pv[2]; m[i][3] = pv[3];
                }
#pragma unroll
                for (int j = 0; j < 4; j++) {
                    int rd = d0 + j;
                    uint32_t o2 = outb + rd * 128 + (((kk0 >> 3) ^ (rd & 7)) << 4) + ((kk0 & 7) * 2);
                    uint16_t o[4] = {m[0][j], m[1][j], m[2][j], m[3][j]};
                    *(uint2*)(smem + o2) = *(uint2*)o;
                }
            }
        }
        __syncthreads();

        // S = Q.K^T  (Q single, K split: 2 MMAs)
        float sacc[4][4];
#pragma unroll
        for (int n = 0; n < 4; n++)
#pragma unroll
            for (int q = 0; q < 4; q++) sacc[n][q] = 0.f;
#pragma unroll
        for (int ks = 0; ks < 4; ks++) {
            int chunk = 2 * ks + (lane >> 4);
            int rq = mrow0 + (lane & 15);
            uint32_t aq = sbase + AT_QH + rq * 128 + ((chunk ^ (rq & 7)) << 4);
            uint32_t qf[4];
            ldm4(qf, aq);
            uint32_t khf[2][4], klf[2][4];
#pragma unroll
            for (int p = 0; p < 2; p++) {
                int rk = ncol0 + p * 16 + (lane & 15);
                uint32_t ak = sbase + AT_KH + rk * 128 + ((chunk ^ (rk & 7)) << 4);
                ldm4(khf[p], ak); ldm4(klf[p], ak + 8192);
            }
#pragma unroll
            for (int n = 0; n < 4; n++) {
                int p = n >> 1, q = n & 1;
                mma16816h(sacc[n], qf, khf[p][q], khf[p][q + 2]);
                mma16816h(sacc[n], qf, klf[p][q], klf[p][q + 2]);
            }
        }
#pragma unroll
        for (int n = 0; n < 4; n++) {
            int si = mrow0 + lg, ck = ncol0 + n * 8 + lt * 2;
            float2 a0; a0.x = sacc[n][0]; a0.y = sacc[n][1];
            float2 a1; a1.x = sacc[n][2]; a1.y = sacc[n][3];
            *(float2*)&Sf[si * 68 + ck]       = a0;
            *(float2*)&Sf[(si + 8) * 68 + ck] = a1;
        }
        __syncthreads();

        // scalar softmax on smem S
        float acc[4][4];
#pragma unroll
        for (int r = 0; r < 4; r++) {
            float4 sv = *(const float4*)&Sf[(ty * 4 + r) * 68 + tx * 4];
            acc[r][0] = sv.x; acc[r][1] = sv.y; acc[r][2] = sv.z; acc[r][3] = sv.w;
        }
#pragma unroll
        for (int r = 0; r < 4; r++) {
            int si = ty * 4 + r;
#pragma unroll
            for (int c = 0; c < 4; c++) {
                int kk = tx * 4 + c;
                int j = kt * 64 + kk - si;
                int u = base_key + kt * 64 + kk;
                if (j >= 0 && j <= 512 && u >= 0)
                    acc[r][c] = (acc[r][c] + __half2float(QEh[qe_base[r] + j])) * 0.125f;
                else
                    acc[r][c] = -1e30f;
            }
        }
        float corr[4];
#pragma unroll
        for (int r = 0; r < 4; r++) {
            float tm = fmaxf(fmaxf(acc[r][0], acc[r][1]), fmaxf(acc[r][2], acc[r][3]));
#pragma unroll
            for (int o = 1; o < 16; o <<= 1)
                tm = fmaxf(tm, __shfl_xor_sync(0xffffffffu, tm, o));
            float mnew = fmaxf(mrow[r], tm);
            corr[r] = __expf(mrow[r] - mnew);
            float rs = 0.f;
#pragma unroll
            for (int c = 0; c < 4; c++) {
                float p = (acc[r][c] > -5e29f) ? __expf(acc[r][c] - mnew) : 0.f;
                acc[r][c] = p;
                rs += p;
            }
#pragma unroll
            for (int o = 1; o < 16; o <<= 1)
                rs += __shfl_xor_sync(0xffffffffu, rs, o);
            lrow[r] = lrow[r] * corr[r] + rs;
            mrow[r] = mnew;
        }
        // write P fp16 single (swizzled rows) + corr
#pragma unroll
        for (int r = 0; r < 4; r++) {
            int si = ty * 4 + r;
            uint32_t poff = si * 128 + ((((tx >> 1) ^ (si & 7))) << 4) + ((tx & 1) * 8);
            uint16_t hs[4];
#pragma unroll
            for (int c = 0; c < 4; c++) {
                __half ph_ = __float2half_rn(acc[r][c]);
                hs[c] = *(uint16_t*)&ph_;
            }
            *(uint2*)(smem + AT_PH + poff) = *(uint2*)hs;
        }
        if (tx == 0) {
#pragma unroll
            for (int r = 0; r < 4; r++) corrS[ty * 4 + r] = corr[r];
        }
        __syncthreads();

        // prefetch next K/V (overlaps PV)
        if (kt < 8) {
            int u0 = base_key + (kt + 1) * 64; if (u0 < 0) u0 = 0;
            const size_t koff = ((size_t)bh_ * 4096 + u0) * 64;
            CPT(AT_KH, g_k_hi + koff, 64);
            CPT(AT_KL, g_k_lo + koff, 64);
            CPT(AT_VH, g_v_hi + koff, 64);
            CPT(AT_VL, g_v_lo + koff, 64);
        }
        asm volatile("cp.async.commit_group;");

        // O = O*corr + P.V  (P single, V split: 2 MMAs)
        float cA = corrS[mrow0 + lg], cB = corrS[mrow0 + lg + 8];
#pragma unroll
        for (int n = 0; n < 4; n++) {
            O[n][0] *= cA; O[n][1] *= cA; O[n][2] *= cB; O[n][3] *= cB;
        }
#pragma unroll
        for (int ks = 0; ks < 4; ks++) {
            int chunk = 2 * ks + (lane >> 4);
            int rp = mrow0 + (lane & 15);
            uint32_t ap = sbase + AT_PH + rp * 128 + ((chunk ^ (rp & 7)) << 4);
            uint32_t pf[4];
            ldm4(pf, ap);
            uint32_t vhf[2][4], vlf[2][4];
#pragma unroll
            for (int p = 0; p < 2; p++) {
                int rv = ncol0 + p * 16 + (lane & 15);
                uint32_t av = sbase + AT_VTH + rv * 128 + ((chunk ^ (rv & 7)) << 4);
                ldm4(vhf[p], av); ldm4(vlf[p], av + 8192);
            }
#pragma unroll
            for (int n = 0; n < 4; n++) {
                int p = n >> 1, q = n & 1;
                mma16816h(O[n], pf, vhf[p][q], vhf[p][q + 2]);
                mma16816h(O[n], pf, vlf[p][q], vlf[p][q + 2]);
            }
        }
    }
#undef CPT

    if (tx == 0) {
#pragma unroll
        for (int r = 0; r < 4; r++) linvS[ty * 4 + r] = 1.f / lrow[r];
    }
    __syncthreads();
    float li0 = linvS[mrow0 + lg], li1 = linvS[mrow0 + lg + 8];
#pragma unroll
    for (int n = 0; n < 4; n++) {
        int si = mrow0 + lg, d = ncol0 + n * 8 + lt * 2;
        int t0 = tbase + si, t1 = t0 + 8;
        size_t o0 = ((size_t)(t0 * 2 + b)) * 1024 + h * 64 + d;
        size_t o1 = ((size_t)(t1 * 2 + b)) * 1024 + h * 64 + d;
        __half2 h0 = __floats2half2_rn(O[n][0] * li0, O[n][1] * li0);
        __half2 h1 = __floats2half2_rn(O[n][2] * li1, O[n][3] * li1);
        *(__half2*)(OH + o0) = h0;
        *(__half2*)(OH + o1) = h1;
    }
}

// ---------------------------------------------------------------------------
extern "C" void kernel_launch(void* const* d_in, const int* in_sizes, int n_in,
                              void* d_out, int out_size)
{
    const float* x      = (const float*)d_in[0];
    const float* ln1_g  = (const float*)d_in[1];
    const float* ln1_b  = (const float*)d_in[2];
    const float* qkv_w  = (const float*)d_in[3];
    const float* qkv_b  = (const float*)d_in[4];
    const float* pos_emb= (const float*)d_in[5];
    const float* out_w  = (const float*)d_in[6];
    const float* ln2_g  = (const float*)d_in[7];
    const float* ln2_b  = (const float*)d_in[8];
    const float* fc1_w  = (const float*)d_in[9];
    const float* fc1_b  = (const float*)d_in[10];
    const float* fc2_w  = (const float*)d_in[11];
    const float* fc2_b  = (const float*)d_in[12];
    float* out = (float*)d_out;

    float* scratch = 0;
    cudaGetSymbolAddress((void**)&scratch, g_scratch);
    void *pA, *pFF1, *pW, *pWl, *pPT, *pQ;
    cudaGetSymbolAddress(&pA, g_act);
    cudaGetSymbolAddress(&pFF1, g_ff1);
    cudaGetSymbolAddress(&pW, g_w_hi);
    cudaGetSymbolAddress(&pWl, g_w_lo);
    cudaGetSymbolAddress(&pPT, g_pet);
    cudaGetSymbolAddress(&pQ, g_q);

    __half* AVh  = (__half*)pA;
    __half* FF1h = (__half*)pFF1;
    __half* Whh  = (__half*)pW;
    __half* Whl  = (__half*)pWl;
    __half* PTh  = (__half*)pPT;
    __half* Qh   = (__half*)pQ;

    float* OUT1 = scratch + OFF_OUT1;
    __half* QEh = (__half*)(scratch + OFF_QE);

    cudaFuncSetAttribute(mma_gemm_h<true, false, false, false, true, true, false>,   cudaFuncAttributeMaxDynamicSharedMemorySize, H_SMEM);
    cudaFuncSetAttribute(mma_gemm_h<false, false, false, true, false, false, true>,  cudaFuncAttributeMaxDynamicSharedMemorySize, H_SMEM);
    cudaFuncSetAttribute(mma_gemm_h<false, false, true, false, false, false, true>,  cudaFuncAttributeMaxDynamicSharedMemorySize, H_SMEM);
    cudaFuncSetAttribute(mma_gemm_h<true, true, false, true, false, false, true>,    cudaFuncAttributeMaxDynamicSharedMemorySize, H_SMEM);
    cudaFuncSetAttribute(mma_gemm_h<true, false, true, false, false, false, true>,   cudaFuncAttributeMaxDynamicSharedMemorySize, H_SMEM);
    cudaFuncSetAttribute(attn_kernel, cudaFuncAttributeMaxDynamicSharedMemorySize, ATT_SMEM);

    // 0. pe^T fp16 (single)
    pe_half_t_kernel<<<160, 256>>>(pos_emb, PTh);
    // 1. LN1 -> fp16
    ln_half_kernel<<<NROWS, 256>>>(x, ln1_g, ln1_b, AVh);
    // 2. QKV GEMM (2-term): Q fp16 / K,V fp16-split / nxt fp32 -> d_out
    halfsplit_kernel<<<(QKV_N * EMB) / 1024, 256>>>(qkv_w, Whh, Whl);
    mma_gemm_h<true, false, false, false, true, true, false><<<dim3(QKV_N / 128, NROWS / 128), 256, H_SMEM>>>(
        AVh, Whh, Whl, qkv_b, 0, out + 8388608, 0, NROWS, QKV_N, EMB);
    // 3. QE = Q @ peT^T -> fp16  (single x single)
    mma_gemm_h<false, false, false, true, false, false, true><<<dim3(NJP / 128, 131072 / 128), 256, H_SMEM>>>(
        Qh, PTh, 0, 0, 0, 0, QEh, 131072, NJP, 64);
    // 4. HMMA attention -> AV fp16
    attn_kernel<<<dim3(8, 8, 32), 256, ATT_SMEM>>>(Qh, QEh, AVh);
    // 5. OUT1 = AV @ out_w^T + x  (single x single)
    halfconv_kernel<<<(EMB * EMB) / 1024, 256>>>(out_w, Whh);
    mma_gemm_h<false, false, true, false, false, false, true><<<dim3(EMB / 128, NROWS / 128), 256, H_SMEM>>>(
        AVh, Whh, 0, 0, x, OUT1, 0, NROWS, EMB, EMB);
    // 6. LN2 -> fp16
    ln_half_kernel<<<NROWS, 256>>>(OUT1, ln2_g, ln2_b, AVh);
    // 7. FF1 = relu(H2 @ fc1_w^T + fc1_b) -> fp16  (single x single)
    halfconv_kernel<<<(FFN_I * EMB) / 1024, 256>>>(fc1_w, Whh);
    mma_gemm_h<true, true, false, true, false, false, true><<<dim3(FFN_I / 128, NROWS / 128), 256, H_SMEM>>>(
        AVh, Whh, 0, fc1_b, 0, 0, FF1h, NROWS, FFN_I, EMB);
    // 8. out = FF1 @ fc2_w^T + fc2_b + OUT1  (single x single)
    halfconv_kernel<<<(EMB * FFN_I) / 1024, 256>>>(fc2_w, Whh);
    mma_gemm_h<true, false, true, false, false, false, true><<<dim3(EMB / 128, NROWS / 128), 256, H_SMEM>>>(
        FF1h, Whh, 0, fc2_b, OUT1, out, 0, NROWS, EMB, FFN_I);
}

// round 17
// speedup vs baseline: 2.6150x; 1.2052x over previous
#include <cuda_runtime.h>
#include <cuda_bf16.h>
#include <cuda_fp16.h>
#include <math.h>
#include <stdint.h>

// ---------------------------------------------------------------------------
// Shapes: x (T=4096, B=2, E=1024); H=16 heads, dk=dv=64; window 512 (513 rel pos)
// Q: fp16 [(t*2+b)*16+h][64]; K/V: fp16 single [(b*16+h)][t][64]
// QE: fp16 [r][j] stride 640; nxt (d_out+8388608): fp32 (QKV GEMM epilogue)
// ALL GEMMs: fp16 single x single (1 MMA/tile)
// ---------------------------------------------------------------------------
#define NROWS 8192
#define EMB   1024
#define QKV_N 3072
#define FFN_I 4096
#define NJ    513
#define NJP   640

#define OFF_OUT1   16777216ull
#define OFF_QE     92274688ull
#define SCRATCH_FLOATS 176160768ull

__device__ float g_scratch[SCRATCH_FLOATS];

__device__ __half g_act[8388608];      // fp16 LN1 / AV / H2
__device__ __half g_ff1[33554432];     // fc1 out fp16
__device__ __half g_w[4194304];        // fp16 weights
__device__ __half g_pet[40960];
__device__ __half g_q[8388608];
__device__ __half g_k[8388608];
__device__ __half g_v[8388608];

__device__ __forceinline__ uint32_t smem_u32(const void* p) {
    uint32_t a;
    asm("{ .reg .u64 t; cvta.to.shared.u64 t, %1; cvt.u32.u64 %0, t; }" : "=r"(a) : "l"(p));
    return a;
}

// ---------------------------------------------------------------------------
// plain fp32 -> fp16 convert
__global__ __launch_bounds__(256) void halfconv_kernel(
    const float* __restrict__ X, __half* __restrict__ H)
{
    int i4 = blockIdx.x * 256 + threadIdx.x;
    float4 v = ((const float4*)X)[i4];
    __half2 a0 = __floats2half2_rn(v.x, v.y);
    __half2 a1 = __floats2half2_rn(v.z, v.w);
    ((__half2*)H)[i4 * 2]     = a0;
    ((__half2*)H)[i4 * 2 + 1] = a1;
}

__global__ __launch_bounds__(256) void pe_half_t_kernel(
    const float* __restrict__ pe, __half* __restrict__ H)
{
    int idx = blockIdx.x * 256 + threadIdx.x;
    int k = idx & 63;
    int j = idx >> 6;
    float v = (j < NJ) ? pe[(size_t)k * NJ + j] : 0.f;
    H[idx] = __float2half_rn(v);
}

__global__ __launch_bounds__(256) void ln_half_kernel(
    const float* __restrict__ X, const float* __restrict__ G,
    const float* __restrict__ Bt, __half* __restrict__ H)
{
    __shared__ float ssum[8], ssq[8], smv[2];
    int row = blockIdx.x;
    int tid = threadIdx.x;
    const float4* xr = (const float4*)(X + (size_t)row * EMB);
    float4 v = xr[tid];
    float s = v.x + v.y + v.z + v.w;
    float q = v.x*v.x + v.y*v.y + v.z*v.z + v.w*v.w;
#pragma unroll
    for (int o = 16; o > 0; o >>= 1) {
        s += __shfl_xor_sync(0xffffffffu, s, o);
        q += __shfl_xor_sync(0xffffffffu, q, o);
    }
    if ((tid & 31) == 0) { ssum[tid >> 5] = s; ssq[tid >> 5] = q; }
    __syncthreads();
    if (tid == 0) {
        float S = 0.f, Q = 0.f;
#pragma unroll
        for (int i = 0; i < 8; i++) { S += ssum[i]; Q += ssq[i]; }
        float mean = S * (1.f / EMB);
        float var  = Q * (1.f / EMB) - mean * mean;
        smv[0] = mean;
        smv[1] = rsqrtf(var + 1e-5f);
    }
    __syncthreads();
    float mean = smv[0], inv = smv[1];
    float4 g = ((const float4*)G)[tid];
    float4 b = ((const float4*)Bt)[tid];
    __half2 a0 = __floats2half2_rn((v.x - mean) * inv * g.x + b.x,
                                   (v.y - mean) * inv * g.y + b.y);
    __half2 a1 = __floats2half2_rn((v.z - mean) * inv * g.z + b.z,
                                   (v.w - mean) * inv * g.w + b.w);
    size_t i4 = (size_t)row * 256 + tid;
    ((__half2*)H)[i4 * 2]     = a0;
    ((__half2*)H)[i4 * 2 + 1] = a1;
}

// ---------------------------------------------------------------------------
__device__ __forceinline__ void cp16(uint32_t dst, const void* src) {
    asm volatile("cp.async.cg.shared.global [%0], [%1], 16;" :: "r"(dst), "l"(src));
}
__device__ __forceinline__ void ldm4(uint32_t* r, uint32_t addr) {
    asm volatile("ldmatrix.sync.aligned.m8n8.x4.shared.b16 {%0,%1,%2,%3}, [%4];"
                 : "=r"(r[0]), "=r"(r[1]), "=r"(r[2]), "=r"(r[3]) : "r"(addr));
}
__device__ __forceinline__ void mma16816h(float* c, const uint32_t* a,
                                          uint32_t b0, uint32_t b1) {
    asm volatile(
        "mma.sync.aligned.m16n8k16.row.col.f32.f16.f16.f32 "
        "{%0,%1,%2,%3}, {%4,%5,%6,%7}, {%8,%9}, {%0,%1,%2,%3};"
        : "+f"(c[0]), "+f"(c[1]), "+f"(c[2]), "+f"(c[3])
        : "r"(a[0]), "r"(a[1]), "r"(a[2]), "r"(a[3]), "r"(b0), "r"(b1));
}

// ---------------------------------------------------------------------------
// fp16 GEMM: C = A(f16) * B(f16)^T — 1 MMA/tile.
// H16O: fp16 out. RES: +Res fp32. QOUT/NXTO: QKV epilogue (Q/K/V + nxt).
// ---------------------------------------------------------------------------
#define H_STAGE 16384
#define H_SMEM  49152

template<bool BIAS, bool RELU, bool RES, bool H16O, bool QOUT, bool NXTO>
__global__ __launch_bounds__(256, 2) void mma_gemm_h(
    const __half* __restrict__ Ax, const __half* __restrict__ Bx,
    const float* __restrict__ bias, const float* __restrict__ Res,
    float* __restrict__ C, __half* __restrict__ OH, int M, int N, int K)
{
    extern __shared__ char smem[];
    const uint32_t sbase = smem_u32(smem);
    const int tid = threadIdx.x;
    const int wid = tid >> 5, lane = tid & 31;
    const int bm = blockIdx.y * 128, bn = blockIdx.x * 128;
    const int m0w = (wid >> 2) * 64, n0w = (wid & 3) * 32;

    const int r0 = tid >> 2,         c0 = tid & 3;
    const int r1 = (tid + 256) >> 2, c1 = (tid + 256) & 3;
    const uint32_t so0 = (uint32_t)(r0 * 64 + ((c0 ^ ((r0 >> 1) & 3)) * 16));
    const uint32_t so1 = (uint32_t)(r1 * 64 + ((c1 ^ ((r1 >> 1) & 3)) * 16));
    const size_t offA0 = (size_t)(bm + r0) * K + c0 * 8;
    const size_t offA1 = (size_t)(bm + r1) * K + c1 * 8;
    const size_t offB0 = (size_t)(bn + r0) * K + c0 * 8;
    const size_t offB1 = (size_t)(bn + r1) * K + c1 * 8;

    float acc[4][4][4];
#pragma unroll
    for (int a = 0; a < 4; a++)
#pragma unroll
        for (int n = 0; n < 4; n++)
#pragma unroll
            for (int q = 0; q < 4; q++) acc[a][n][q] = 0.f;

    const int nt = K >> 5;
    const int rowA_base = m0w + (lane & 15);
    const int rowB_base = n0w + (lane & 15);
    const int chsel = lane >> 4;

#define LOAD_STAGE_H(s, k0)                                                   \
    do {                                                                      \
        uint32_t d = sbase + (s) * H_STAGE;                                   \
        cp16(d + so0,          Ax + offA0 + (k0));                            \
        cp16(d + so1,          Ax + offA1 + (k0));                            \
        cp16(d + 8192  + so0,  Bx + offB0 + (k0));                            \
        cp16(d + 8192  + so1,  Bx + offB1 + (k0));                            \
    } while (0)

    LOAD_STAGE_H(0, 0);
    asm volatile("cp.async.commit_group;");
    if (nt > 1) LOAD_STAGE_H(1, 32);
    asm volatile("cp.async.commit_group;");

    int stage = 0;
    for (int i = 0; i < nt; i++) {
        asm volatile("cp.async.wait_group 1;");
        __syncthreads();

        uint32_t base = sbase + stage * H_STAGE;
#pragma unroll
        for (int ks = 0; ks < 2; ks++) {
            const int chunk = ks * 2 + chsel;
            uint32_t bh[2][4];
#pragma unroll
            for (int p = 0; p < 2; p++) {
                int row = rowB_base + p * 16;
                uint32_t ad = base + 8192 + (uint32_t)(row * 64 + ((chunk ^ ((row >> 1) & 3)) * 16));
                ldm4(bh[p], ad);
            }
#pragma unroll
            for (int a = 0; a < 4; a++) {
                uint32_t ah[4];
                int row = rowA_base + a * 16;
                uint32_t ad = base + (uint32_t)(row * 64 + ((chunk ^ ((row >> 1) & 3)) * 16));
                ldm4(ah, ad);
#pragma unroll
                for (int n = 0; n < 4; n++) {
                    int p = n >> 1, q = n & 1;
                    mma16816h(acc[a][n], ah, bh[p][q], bh[p][q + 2]);
                }
            }
        }
        int nx = i + 2;
        if (nx < nt) {
            int ns = stage + 2; if (ns >= 3) ns -= 3;
            LOAD_STAGE_H(ns, nx << 5);
        }
        asm volatile("cp.async.commit_group;");
        if (++stage == 3) stage = 0;
    }
#undef LOAD_STAGE_H

    const int g = lane >> 2, t = lane & 3;
#pragma unroll
    for (int a = 0; a < 4; a++) {
#pragma unroll
        for (int n = 0; n < 4; n++) {
            int row0 = bm + m0w + a * 16 + g;
            int col  = bn + n0w + n * 8 + 2 * t;
            float v0 = acc[a][n][0], v1 = acc[a][n][1];
            float v2 = acc[a][n][2], v3 = acc[a][n][3];
            if (BIAS) {
                float b0 = bias[col], b1 = bias[col + 1];
                v0 += b0; v1 += b1; v2 += b0; v3 += b1;
            }
            if (RELU) {
                v0 = fmaxf(v0, 0.f); v1 = fmaxf(v1, 0.f);
                v2 = fmaxf(v2, 0.f); v3 = fmaxf(v3, 0.f);
            }
            if (RES) {
                const float2 q0 = *(const float2*)(Res + (size_t)row0 * N + col);
                const float2 q1 = *(const float2*)(Res + (size_t)(row0 + 8) * N + col);
                v0 += q0.x; v1 += q0.y; v2 += q1.x; v3 += q1.y;
            }
            if (H16O) {
                __half2 h0 = __floats2half2_rn(v0, v1);
                __half2 h1 = __floats2half2_rn(v2, v3);
                *(__half2*)(OH + (size_t)row0 * N + col)       = h0;
                *(__half2*)(OH + (size_t)(row0 + 8) * N + col) = h1;
            } else if (!QOUT) {
                float2 o0; o0.x = v0; o0.y = v1;
                float2 o1; o1.x = v2; o1.y = v3;
                *(float2*)(C + (size_t)row0 * N + col)       = o0;
                *(float2*)(C + (size_t)(row0 + 8) * N + col) = o1;
            }
            if (QOUT) {
                int hh = col / 192;
                int cc = col - hh * 192;
                int b0_ = row0 & 1, t0_ = row0 >> 1;
                int t1_ = (row0 + 8) >> 1;
                __half2 h0 = __floats2half2_rn(v0, v1);
                __half2 h1 = __floats2half2_rn(v2, v3);
                if (cc < 64) {
                    size_t q0o = ((size_t)row0 * 16 + hh) * 64 + cc;
                    size_t q1o = ((size_t)(row0 + 8) * 16 + hh) * 64 + cc;
                    *(__half2*)(g_q + q0o) = h0;
                    *(__half2*)(g_q + q1o) = h1;
                } else {
                    if (cc < 128) {
                        size_t k0o = (((size_t)(b0_ * 16 + hh)) * 4096 + t0_) * 64 + (cc - 64);
                        size_t k1o = (((size_t)(b0_ * 16 + hh)) * 4096 + t1_) * 64 + (cc - 64);
                        *(__half2*)(g_k + k0o) = h0;
                        *(__half2*)(g_k + k1o) = h1;
                    } else {
                        size_t v0o = (((size_t)(b0_ * 16 + hh)) * 4096 + t0_) * 64 + (cc - 128);
                        size_t v1o = (((size_t)(b0_ * 16 + hh)) * 4096 + t1_) * 64 + (cc - 128);
                        *(__half2*)(g_v + v0o) = h0;
                        *(__half2*)(g_v + v1o) = h1;
                    }
                    if (NXTO) {
                        if (t0_ >= 3584) {
                            size_t o = (((size_t)(t0_ - 3584) * 32) + b0_ * 16 + hh) * 128 + (cc - 64);
                            float2 w; w.x = v0; w.y = v1;
                            *(float2*)(C + o) = w;
                        }
                        if (t1_ >= 3584) {
                            size_t o = (((size_t)(t1_ - 3584) * 32) + b0_ * 16 + hh) * 128 + (cc - 64);
                            float2 w; w.x = v2; w.y = v3;
                            *(float2*)(C + o) = w;
                        }
                    }
                }
            }
        }
    }
}

// ---------------------------------------------------------------------------
// HMMA sliding-window attention, fp16 single operands throughout.
// ---------------------------------------------------------------------------
#define AT_QH  0
#define AT_KH  8192
#define AT_VH  16384
#define AT_VTH 24576
#define AT_S   32768
#define AT_PH  50176
#define AT_CORR 58368
#define AT_LINV 58624
#define ATT_SMEM 58880

__global__ __launch_bounds__(256, 2) void attn_kernel(
    const __half* __restrict__ Qh, const __half* __restrict__ QEh,
    __half* __restrict__ OH)
{
    extern __shared__ char smem[];
    const uint32_t sbase = smem_u32(smem);
    float* Sf    = (float*)(smem + AT_S);
    float* corrS = (float*)(smem + AT_CORR);
    float* linvS = (float*)(smem + AT_LINV);

    const int s0 = blockIdx.x * 64;
    const int gg = blockIdx.y;
    const int bh = blockIdx.z;
    const int b = bh >> 4, h = bh & 15;
    const int tid = threadIdx.x;
    const int lane = tid & 31, wid = tid >> 5;
    const int tx = tid & 15, ty = tid >> 4;
    const int tbase = gg * 512 + s0;
    const int base_key = tbase - 512;
    const int bh_ = b * 16 + h;

    const int mrow0 = (wid >> 1) * 16;
    const int ncol0 = (wid & 1) * 32;
    const int lg = lane >> 2, lt = lane & 3;

    const int cr0 = tid >> 3, cc0 = tid & 7;
    const int cr1 = (tid + 256) >> 3, cc1 = (tid + 256) & 7;

#define CPT(dstoff, srcp, stride)                                                        \
    do {                                                                                 \
        cp16(sbase + (dstoff) + cr0 * 128 + ((cc0 ^ (cr0 & 7)) * 16),                    \
             (srcp) + (size_t)cr0 * (stride) + cc0 * 8);                                 \
        cp16(sbase + (dstoff) + cr1 * 128 + ((cc1 ^ (cr1 & 7)) * 16),                    \
             (srcp) + (size_t)cr1 * (stride) + cc1 * 8);                                 \
    } while (0)

    {
        const size_t qoff = (((size_t)tbase * 2 + b) * 16 + h) * 64;
        CPT(AT_QH, Qh + qoff, 2048);
        int u0 = base_key; if (u0 < 0) u0 = 0;
        const size_t koff = ((size_t)bh_ * 4096 + u0) * 64;
        CPT(AT_KH, g_k + koff, 64);
        CPT(AT_VH, g_v + koff, 64);
        asm volatile("cp.async.commit_group;");
    }

    float O[4][4];
    float mrow[4], lrow[4];
#pragma unroll
    for (int r = 0; r < 4; r++) {
        mrow[r] = -1e30f; lrow[r] = 0.f;
#pragma unroll
        for (int c = 0; c < 4; c++) O[r][c] = 0.f;
    }
    size_t qe_base[4];
#pragma unroll
    for (int r = 0; r < 4; r++) {
        int t = tbase + ty * 4 + r;
        qe_base[r] = ((size_t)(t * 2 + b) * 16 + h) * NJP;
    }

    for (int kt = 0; kt < 9; kt++) {
        asm volatile("cp.async.wait_group 0;");
        __syncthreads();

        {   // transpose V[kk][d] -> VT[d][kk]
            int d0 = (tid & 15) * 4, kk0 = (tid >> 4) * 4;
            uint16_t m[4][4];
#pragma unroll
            for (int i = 0; i < 4; i++) {
                int row = kk0 + i;
                uint32_t off = AT_VH + row * 128 + (((d0 >> 3) ^ (row & 7)) << 4) + ((d0 & 7) * 2);
                uint2 v = *(uint2*)(smem + off);
                uint16_t* pv = (uint16_t*)&v;
                m[i][0] = pv[0]; m[i][1] = pv[1]; m[i][2] = pv[2]; m[i][3] = pv[3];
            }
#pragma unroll
            for (int j = 0; j < 4; j++) {
                int rd = d0 + j;
                uint32_t o2 = AT_VTH + rd * 128 + (((kk0 >> 3) ^ (rd & 7)) << 4) + ((kk0 & 7) * 2);
                uint16_t o[4] = {m[0][j], m[1][j], m[2][j], m[3][j]};
                *(uint2*)(smem + o2) = *(uint2*)o;
            }
        }
        __syncthreads();

        // S = Q.K^T  (1 MMA per n-tile)
        float sacc[4][4];
#pragma unroll
        for (int n = 0; n < 4; n++)
#pragma unroll
            for (int q = 0; q < 4; q++) sacc[n][q] = 0.f;
#pragma unroll
        for (int ks = 0; ks < 4; ks++) {
            int chunk = 2 * ks + (lane >> 4);
            int rq = mrow0 + (lane & 15);
            uint32_t aq = sbase + AT_QH + rq * 128 + ((chunk ^ (rq & 7)) << 4);
            uint32_t qf[4];
            ldm4(qf, aq);
            uint32_t khf[2][4];
#pragma unroll
            for (int p = 0; p < 2; p++) {
                int rk = ncol0 + p * 16 + (lane & 15);
                uint32_t ak = sbase + AT_KH + rk * 128 + ((chunk ^ (rk & 7)) << 4);
                ldm4(khf[p], ak);
            }
#pragma unroll
            for (int n = 0; n < 4; n++) {
                int p = n >> 1, q = n & 1;
                mma16816h(sacc[n], qf, khf[p][q], khf[p][q + 2]);
            }
        }
#pragma unroll
        for (int n = 0; n < 4; n++) {
            int si = mrow0 + lg, ck = ncol0 + n * 8 + lt * 2;
            float2 a0; a0.x = sacc[n][0]; a0.y = sacc[n][1];
            float2 a1; a1.x = sacc[n][2]; a1.y = sacc[n][3];
            *(float2*)&Sf[si * 68 + ck]       = a0;
            *(float2*)&Sf[(si + 8) * 68 + ck] = a1;
        }
        __syncthreads();

        // scalar softmax on smem S
        float acc[4][4];
#pragma unroll
        for (int r = 0; r < 4; r++) {
            float4 sv = *(const float4*)&Sf[(ty * 4 + r) * 68 + tx * 4];
            acc[r][0] = sv.x; acc[r][1] = sv.y; acc[r][2] = sv.z; acc[r][3] = sv.w;
        }
#pragma unroll
        for (int r = 0; r < 4; r++) {
            int si = ty * 4 + r;
#pragma unroll
            for (int c = 0; c < 4; c++) {
                int kk = tx * 4 + c;
                int j = kt * 64 + kk - si;
                int u = base_key + kt * 64 + kk;
                if (j >= 0 && j <= 512 && u >= 0)
                    acc[r][c] = (acc[r][c] + __half2float(QEh[qe_base[r] + j])) * 0.125f;
                else
                    acc[r][c] = -1e30f;
            }
        }
        float corr[4];
#pragma unroll
        for (int r = 0; r < 4; r++) {
            float tm = fmaxf(fmaxf(acc[r][0], acc[r][1]), fmaxf(acc[r][2], acc[r][3]));
#pragma unroll
            for (int o = 1; o < 16; o <<= 1)
                tm = fmaxf(tm, __shfl_xor_sync(0xffffffffu, tm, o));
            float mnew = fmaxf(mrow[r], tm);
            corr[r] = __expf(mrow[r] - mnew);
            float rs = 0.f;
#pragma unroll
            for (int c = 0; c < 4; c++) {
                float p = (acc[r][c] > -5e29f) ? __expf(acc[r][c] - mnew) : 0.f;
                acc[r][c] = p;
                rs += p;
            }
#pragma unroll
            for (int o = 1; o < 16; o <<= 1)
                rs += __shfl_xor_sync(0xffffffffu, rs, o);
            lrow[r] = lrow[r] * corr[r] + rs;
            mrow[r] = mnew;
        }
        // write P fp16 single (swizzled rows) + corr
#pragma unroll
        for (int r = 0; r < 4; r++) {
            int si = ty * 4 + r;
            uint32_t poff = si * 128 + ((((tx >> 1) ^ (si & 7))) << 4) + ((tx & 1) * 8);
            uint16_t hs[4];
#pragma unroll
            for (int c = 0; c < 4; c++) {
                __half ph_ = __float2half_rn(acc[r][c]);
                hs[c] = *(uint16_t*)&ph_;
            }
            *(uint2*)(smem + AT_PH + poff) = *(uint2*)hs;
        }
        if (tx == 0) {
#pragma unroll
            for (int r = 0; r < 4; r++) corrS[ty * 4 + r] = corr[r];
        }
        __syncthreads();

        // prefetch next K/V (overlaps PV)
        if (kt < 8) {
            int u0 = base_key + (kt + 1) * 64; if (u0 < 0) u0 = 0;
            const size_t koff = ((size_t)bh_ * 4096 + u0) * 64;
            CPT(AT_KH, g_k + koff, 64);
            CPT(AT_VH, g_v + koff, 64);
        }
        asm volatile("cp.async.commit_group;");

        // O = O*corr + P.V  (1 MMA per n-tile)
        float cA = corrS[mrow0 + lg], cB = corrS[mrow0 + lg + 8];
#pragma unroll
        for (int n = 0; n < 4; n++) {
            O[n][0] *= cA; O[n][1] *= cA; O[n][2] *= cB; O[n][3] *= cB;
        }
#pragma unroll
        for (int ks = 0; ks < 4; ks++) {
            int chunk = 2 * ks + (lane >> 4);
            int rp = mrow0 + (lane & 15);
            uint32_t ap = sbase + AT_PH + rp * 128 + ((chunk ^ (rp & 7)) << 4);
            uint32_t pf[4];
            ldm4(pf, ap);
            uint32_t vhf[2][4];
#pragma unroll
            for (int p = 0; p < 2; p++) {
                int rv = ncol0 + p * 16 + (lane & 15);
                uint32_t av = sbase + AT_VTH + rv * 128 + ((chunk ^ (rv & 7)) << 4);
                ldm4(vhf[p], av);
            }
#pragma unroll
            for (int n = 0; n < 4; n++) {
                int p = n >> 1, q = n & 1;
                mma16816h(O[n], pf, vhf[p][q], vhf[p][q + 2]);
            }
        }
    }
#undef CPT

    if (tx == 0) {
#pragma unroll
        for (int r = 0; r < 4; r++) linvS[ty * 4 + r] = 1.f / lrow[r];
    }
    __syncthreads();
    float li0 = linvS[mrow0 + lg], li1 = linvS[mrow0 + lg + 8];
#pragma unroll
    for (int n = 0; n < 4; n++) {
        int si = mrow0 + lg, d = ncol0 + n * 8 + lt * 2;
        int t0 = tbase + si, t1 = t0 + 8;
        size_t o0 = ((size_t)(t0 * 2 + b)) * 1024 + h * 64 + d;
        size_t o1 = ((size_t)(t1 * 2 + b)) * 1024 + h * 64 + d;
        __half2 h0 = __floats2half2_rn(O[n][0] * li0, O[n][1] * li0);
        __half2 h1 = __floats2half2_rn(O[n][2] * li1, O[n][3] * li1);
        *(__half2*)(OH + o0) = h0;
        *(__half2*)(OH + o1) = h1;
    }
}

// ---------------------------------------------------------------------------
extern "C" void kernel_launch(void* const* d_in, const int* in_sizes, int n_in,
                              void* d_out, int out_size)
{
    const float* x      = (const float*)d_in[0];
    const float* ln1_g  = (const float*)d_in[1];
    const float* ln1_b  = (const float*)d_in[2];
    const float* qkv_w  = (const float*)d_in[3];
    const float* qkv_b  = (const float*)d_in[4];
    const float* pos_emb= (const float*)d_in[5];
    const float* out_w  = (const float*)d_in[6];
    const float* ln2_g  = (const float*)d_in[7];
    const float* ln2_b  = (const float*)d_in[8];
    const float* fc1_w  = (const float*)d_in[9];
    const float* fc1_b  = (const float*)d_in[10];
    const float* fc2_w  = (const float*)d_in[11];
    const float* fc2_b  = (const float*)d_in[12];
    float* out = (float*)d_out;

    float* scratch = 0;
    cudaGetSymbolAddress((void**)&scratch, g_scratch);
    void *pA, *pFF1, *pW, *pPT, *pQ;
    cudaGetSymbolAddress(&pA, g_act);
    cudaGetSymbolAddress(&pFF1, g_ff1);
    cudaGetSymbolAddress(&pW, g_w);
    cudaGetSymbolAddress(&pPT, g_pet);
    cudaGetSymbolAddress(&pQ, g_q);

    __half* AVh  = (__half*)pA;
    __half* FF1h = (__half*)pFF1;
    __half* Wh   = (__half*)pW;
    __half* PTh  = (__half*)pPT;
    __half* Qh   = (__half*)pQ;

    float* OUT1 = scratch + OFF_OUT1;
    __half* QEh = (__half*)(scratch + OFF_QE);

    cudaFuncSetAttribute(mma_gemm_h<true, false, false, false, true, true>,   cudaFuncAttributeMaxDynamicSharedMemorySize, H_SMEM);
    cudaFuncSetAttribute(mma_gemm_h<false, false, false, true, false, false>, cudaFuncAttributeMaxDynamicSharedMemorySize, H_SMEM);
    cudaFuncSetAttribute(mma_gemm_h<false, false, true, false, false, false>, cudaFuncAttributeMaxDynamicSharedMemorySize, H_SMEM);
    cudaFuncSetAttribute(mma_gemm_h<true, true, false, true, false, false>,   cudaFuncAttributeMaxDynamicSharedMemorySize, H_SMEM);
    cudaFuncSetAttribute(mma_gemm_h<true, false, true, false, false, false>,  cudaFuncAttributeMaxDynamicSharedMemorySize, H_SMEM);
    cudaFuncSetAttribute(attn_kernel, cudaFuncAttributeMaxDynamicSharedMemorySize, ATT_SMEM);

    // 0. pe^T fp16
    pe_half_t_kernel<<<160, 256>>>(pos_emb, PTh);
    // 1. LN1 -> fp16
    ln_half_kernel<<<NROWS, 256>>>(x, ln1_g, ln1_b, AVh);
    // 2. QKV GEMM: Q/K/V fp16 singles + nxt fp32 -> d_out
    halfconv_kernel<<<(QKV_N * EMB) / 1024, 256>>>(qkv_w, Wh);
    mma_gemm_h<true, false, false, false, true, true><<<dim3(QKV_N / 128, NROWS / 128), 256, H_SMEM>>>(
        AVh, Wh, qkv_b, 0, out + 8388608, 0, NROWS, QKV_N, EMB);
    // 3. QE = Q @ peT^T -> fp16
    mma_gemm_h<false, false, false, true, false, false><<<dim3(NJP / 128, 131072 / 128), 256, H_SMEM>>>(
        Qh, PTh, 0, 0, 0, QEh, 131072, NJP, 64);
    // 4. HMMA attention -> AV fp16
    attn_kernel<<<dim3(8, 8, 32), 256, ATT_SMEM>>>(Qh, QEh, AVh);
    // 5. OUT1 = AV @ out_w^T + x
    halfconv_kernel<<<(EMB * EMB) / 1024, 256>>>(out_w, Wh);
    mma_gemm_h<false, false, true, false, false, false><<<dim3(EMB / 128, NROWS / 128), 256, H_SMEM>>>(
        AVh, Wh, 0, x, OUT1, 0, NROWS, EMB, EMB);
    // 6. LN2 -> fp16
    ln_half_kernel<<<NROWS, 256>>>(OUT1, ln2_g, ln2_b, AVh);
    // 7. FF1 = relu(H2 @ fc1_w^T + fc1_b) -> fp16
    halfconv_kernel<<<(FFN_I * EMB) / 1024, 256>>>(fc1_w, Wh);
    mma_gemm_h<true, true, false, true, false, false><<<dim3(FFN_I / 128, NROWS / 128), 256, H_SMEM>>>(
        AVh, Wh, fc1_b, 0, 0, FF1h, NROWS, FFN_I, EMB);
    // 8. out = FF1 @ fc2_w^T + fc2_b + OUT1
    halfconv_kernel<<<(EMB * FFN_I) / 1024, 256>>>(fc2_w, Wh);
    mma_gemm_h<true, false, true, false, false, false><<<dim3(EMB / 128, NROWS / 128), 256, H_SMEM>>>(
        FF1h, Wh, fc2_b, OUT1, out, 0, NROWS, EMB, FFN_I);
}